// round 8
// baseline (speedup 1.0000x reference)
#include <cuda_runtime.h>

#define Bsz 65536
#define DIN 32
#define HID 128
#define LAT 32
#define NC  8
#define KC  512
#define MID 16

// ---------------- scratch (no allocations allowed) ----------------
static __device__ float  g_v[Bsz * LAT];     // v then v_local
static __device__ float  g_cb[Bsz * LAT];
static __device__ float  g_enc[Bsz * NC];
static __device__ int    g_bidx[Bsz * NC];
static __device__ float  g_dec[Bsz * NC];
static __device__ float  g_zg[Bsz * LAT];
static __device__ float  g_hg[Bsz * HID];
static __device__ float  g_zt[Bsz * LAT];
static __device__ float  g_cbn[NC * KC];
static __device__ double g_vq;

// ---------------- output layout (concatenated tuple, f32) ----------------
#define O_XHAT 0
#define O_VQ   (Bsz * DIN)
#define O_ENC  (O_VQ + 1)
#define O_DEC  (O_ENC + Bsz * NC)
#define O_K    (O_DEC + Bsz * NC)
#define O_ZGEO (O_K + Bsz)
#define O_ZN   (O_ZGEO + Bsz * LAT)
#define O_CBAR (O_ZN + Bsz * LAT)
#define O_TOTAL (O_CBAR + Bsz * LAT)

__device__ __forceinline__ float gelu_ref(float x) {
    float u = __fdiv_rn(x, 1.4142135623730951f);
    float t = erff(u);
    return __fmul_rn(__fmul_rn(0.5f, x), __fadd_rn(1.0f, t));
}

// ---------------- prep ----------------
__global__ void kPrep(const float* __restrict__ cbk) {
    int idx = blockIdx.x * blockDim.x + threadIdx.x;
    if (idx == 0) g_vq = 0.0;
    if (idx < NC * KC) {
        const float* row = cbk + (size_t)idx * LAT;
        float s = 0.f;
        #pragma unroll
        for (int l = 0; l < LAT; l++) s = __fadd_rn(s, __fmul_rn(row[l], row[l]));
        g_cbn[idx] = s;
    }
}

// ---------------- kernel A: x -> features -> v (unchanged) ----------------
__global__ void __launch_bounds__(256) kA(
    const float* __restrict__ x,  const float* __restrict__ w1, const float* __restrict__ b1,
    const float* __restrict__ w2, const float* __restrict__ b2,
    const float* __restrict__ vp, const float* __restrict__ vpb)
{
    extern __shared__ float sm[];
    float* w1n  = sm;
    float* w2n  = w1n + DIN * HID;
    float* vps  = w2n + HID * HID;
    float* b1s  = vps + HID * LAT;
    float* b2s  = b1s + HID;
    float* vpbs = b2s + HID;
    float* h1s  = vpbs + LAT;

    int tid = threadIdx.x;
    for (int i = tid; i < DIN * HID; i += 256) w1n[i] = w1[i];
    for (int i = tid; i < HID * HID; i += 256) w2n[i] = w2[i];
    for (int i = tid; i < HID * LAT; i += 256) vps[i] = vp[i];
    if (tid < HID) { b1s[tid] = b1[tid]; b2s[tid] = b2[tid]; }
    if (tid < LAT) vpbs[tid] = vpb[tid];
    __syncthreads();

    size_t r = (size_t)blockIdx.x * 256 + tid;

    float xr[DIN];
    {
        const float4* xp = (const float4*)(x + r * DIN);
        #pragma unroll
        for (int i = 0; i < 8; i++) {
            float4 t = xp[i];
            xr[4*i] = t.x; xr[4*i+1] = t.y; xr[4*i+2] = t.z; xr[4*i+3] = t.w;
        }
    }

    for (int j = 0; j < HID; j += 4) {
        float a0 = 0.f, a1 = 0.f, a2 = 0.f, a3 = 0.f;
        #pragma unroll
        for (int i = 0; i < DIN; i++) {
            float xi = xr[i];
            float4 w = *(const float4*)(w1n + i * HID + j);
            a0 = fmaf(xi, w.x, a0); a1 = fmaf(xi, w.y, a1);
            a2 = fmaf(xi, w.z, a2); a3 = fmaf(xi, w.w, a3);
        }
        h1s[(j+0) * 256 + tid] = gelu_ref(__fadd_rn(a0, b1s[j+0]));
        h1s[(j+1) * 256 + tid] = gelu_ref(__fadd_rn(a1, b1s[j+1]));
        h1s[(j+2) * 256 + tid] = gelu_ref(__fadd_rn(a2, b1s[j+2]));
        h1s[(j+3) * 256 + tid] = gelu_ref(__fadd_rn(a3, b1s[j+3]));
    }

    float h1[HID];
    #pragma unroll
    for (int i = 0; i < HID; i++) h1[i] = h1s[i * 256 + tid];

    float vv[LAT];
    #pragma unroll
    for (int l = 0; l < LAT; l++) vv[l] = 0.f;
    for (int j = 0; j < HID; j += 4) {
        float a0 = 0.f, a1 = 0.f, a2 = 0.f, a3 = 0.f;
        #pragma unroll
        for (int i = 0; i < HID; i++) {
            float hi = h1[i];
            float4 w = *(const float4*)(w2n + i * HID + j);
            a0 = fmaf(hi, w.x, a0); a1 = fmaf(hi, w.y, a1);
            a2 = fmaf(hi, w.z, a2); a3 = fmaf(hi, w.w, a3);
        }
        float u0 = gelu_ref(__fadd_rn(a0, b2s[j+0]));
        float u1 = gelu_ref(__fadd_rn(a1, b2s[j+1]));
        float u2 = gelu_ref(__fadd_rn(a2, b2s[j+2]));
        float u3 = gelu_ref(__fadd_rn(a3, b2s[j+3]));
        const float4* vr0 = (const float4*)(vps + (j+0) * LAT);
        const float4* vr1 = (const float4*)(vps + (j+1) * LAT);
        const float4* vr2 = (const float4*)(vps + (j+2) * LAT);
        const float4* vr3 = (const float4*)(vps + (j+3) * LAT);
        #pragma unroll
        for (int l4 = 0; l4 < 8; l4++) {
            float4 w = vr0[l4];
            vv[4*l4]   = fmaf(u0, w.x, vv[4*l4]);   vv[4*l4+1] = fmaf(u0, w.y, vv[4*l4+1]);
            vv[4*l4+2] = fmaf(u0, w.z, vv[4*l4+2]); vv[4*l4+3] = fmaf(u0, w.w, vv[4*l4+3]);
        }
        #pragma unroll
        for (int l4 = 0; l4 < 8; l4++) {
            float4 w = vr1[l4];
            vv[4*l4]   = fmaf(u1, w.x, vv[4*l4]);   vv[4*l4+1] = fmaf(u1, w.y, vv[4*l4+1]);
            vv[4*l4+2] = fmaf(u1, w.z, vv[4*l4+2]); vv[4*l4+3] = fmaf(u1, w.w, vv[4*l4+3]);
        }
        #pragma unroll
        for (int l4 = 0; l4 < 8; l4++) {
            float4 w = vr2[l4];
            vv[4*l4]   = fmaf(u2, w.x, vv[4*l4]);   vv[4*l4+1] = fmaf(u2, w.y, vv[4*l4+1]);
            vv[4*l4+2] = fmaf(u2, w.z, vv[4*l4+2]); vv[4*l4+3] = fmaf(u2, w.w, vv[4*l4+3]);
        }
        #pragma unroll
        for (int l4 = 0; l4 < 8; l4++) {
            float4 w = vr3[l4];
            vv[4*l4]   = fmaf(u3, w.x, vv[4*l4]);   vv[4*l4+1] = fmaf(u3, w.y, vv[4*l4+1]);
            vv[4*l4+2] = fmaf(u3, w.z, vv[4*l4+2]); vv[4*l4+3] = fmaf(u3, w.w, vv[4*l4+3]);
        }
    }
    float4* vo = (float4*)(g_v + r * LAT);
    #pragma unroll
    for (int l4 = 0; l4 < 8; l4++) {
        float4 t;
        t.x = __fadd_rn(vv[4*l4],   vpbs[4*l4]);
        t.y = __fadd_rn(vv[4*l4+1], vpbs[4*l4+1]);
        t.z = __fadd_rn(vv[4*l4+2], vpbs[4*l4+2]);
        t.w = __fadd_rn(vv[4*l4+3], vpbs[4*l4+3]);
        vo[l4] = t;
    }
}

// ---------------- kernel V: softmax/K + c_bar/v_local + VQ argmin ----------------
// smem = one codebook chart tile + small tables (~70KB) -> 2 blocks/SM (16 warps)
__global__ void __launch_bounds__(256, 2) kV(
    const float* __restrict__ cc, const float* __restrict__ cbk,
    float* __restrict__ out, int full)
{
    extern __shared__ float sm[];
    float* cbs  = sm;               // KC*LAT = 16384
    float* cbns = cbs + KC * LAT;   // 512
    float* ccs  = cbns + KC;        // 256 [c][l]
    float* cct  = ccs + NC * LAT;   // 256 [l][c]

    int tid = threadIdx.x;
    for (int i = tid; i < NC * LAT; i += 256) {
        float t = cc[i]; ccs[i] = t;
        int c = i / LAT, l = i % LAT;
        cct[l * NC + c] = t;
    }

    size_t r = (size_t)blockIdx.x * 256 + tid;
    float v[LAT];
    {
        const float4* vp4 = (const float4*)(g_v + r * LAT);
        #pragma unroll
        for (int i = 0; i < 8; i++) {
            float4 t = vp4[i];
            v[4*i] = t.x; v[4*i+1] = t.y; v[4*i+2] = t.z; v[4*i+3] = t.w;
        }
    }
    __syncthreads();

    // ---- enc softmax + K: BYTE-IDENTICAL to the passing version ----
    float enc[NC]; int K;
    {
        float sc[NC];
        #pragma unroll
        for (int c = 0; c < NC; c++) sc[c] = 0.f;
        #pragma unroll
        for (int l = 0; l < LAT; l++) {
            float vl = v[l];
            float4 wa = ((const float4*)(cct + l * NC))[0];
            float4 wb = ((const float4*)(cct + l * NC))[1];
            sc[0] = fmaf(vl, wa.x, sc[0]); sc[1] = fmaf(vl, wa.y, sc[1]);
            sc[2] = fmaf(vl, wa.z, sc[2]); sc[3] = fmaf(vl, wa.w, sc[3]);
            sc[4] = fmaf(vl, wb.x, sc[4]); sc[5] = fmaf(vl, wb.y, sc[5]);
            sc[6] = fmaf(vl, wb.z, sc[6]); sc[7] = fmaf(vl, wb.w, sc[7]);
        }
        #pragma unroll
        for (int c = 0; c < NC; c++) sc[c] = __fdiv_rn(sc[c], 5.656854249492381f);
        float m = sc[0];
        #pragma unroll
        for (int c = 1; c < NC; c++) m = fmaxf(m, sc[c]);
        float e[NC];
        #pragma unroll
        for (int c = 0; c < NC; c++)
            e[c] = (float)exp((double)__fsub_rn(sc[c], m));  // correctly-rounded fp32 exp
        float s01 = __fadd_rn(e[0], e[1]);
        float s23 = __fadd_rn(e[2], e[3]);
        float s45 = __fadd_rn(e[4], e[5]);
        float s67 = __fadd_rn(e[6], e[7]);
        float s = __fadd_rn(__fadd_rn(s01, s23), __fadd_rn(s45, s67));
        #pragma unroll
        for (int c = 0; c < NC; c++) enc[c] = __fdiv_rn(e[c], s);
        float bm = e[0]; K = 0;
        #pragma unroll
        for (int c = 1; c < NC; c++) if (e[c] > bm) { bm = e[c]; K = c; }
    }

    // c_bar / v_local (same arithmetic as before)
    float cb[LAT];
    #pragma unroll
    for (int l = 0; l < LAT; l++) cb[l] = 0.f;
    #pragma unroll
    for (int c = 0; c < NC; c++) {
        float e = enc[c];
        #pragma unroll
        for (int l = 0; l < LAT; l++) cb[l] = fmaf(e, ccs[c * LAT + l], cb[l]);
    }
    #pragma unroll
    for (int l = 0; l < LAT; l++) v[l] = __fsub_rn(v[l], cb[l]);   // v_local

    // write row-level outputs now, freeing registers
    {
        float4* vo = (float4*)(g_v + r * LAT);
        float4* co = (float4*)(g_cb + r * LAT);
        #pragma unroll
        for (int l4 = 0; l4 < 8; l4++) {
            float4 tv, tc;
            tv.x = v[4*l4];  tv.y = v[4*l4+1];  tv.z = v[4*l4+2];  tv.w = v[4*l4+3];
            tc.x = cb[4*l4]; tc.y = cb[4*l4+1]; tc.z = cb[4*l4+2]; tc.w = cb[4*l4+3];
            vo[l4] = tv; co[l4] = tc;
        }
        #pragma unroll
        for (int c = 0; c < NC; c++) g_enc[r * NC + c] = enc[c];
        if (full) {
            #pragma unroll
            for (int c = 0; c < NC; c++) out[O_ENC + r * NC + c] = enc[c];
            out[O_K + r] = (float)K;
            #pragma unroll
            for (int l = 0; l < LAT; l++) out[O_CBAR + r * LAT + l] = cb[l];
        }
    }

    float vn = 0.f;
    #pragma unroll
    for (int l = 0; l < LAT; l++) vn = __fadd_rn(vn, __fmul_rn(v[l], v[l]));

    // VQ argmin per chart (identical arithmetic: (vn - 2e) + cbn, strict <)
    #pragma unroll 1
    for (int c = 0; c < NC; c++) {
        __syncthreads();
        const float* src = cbk + (size_t)c * KC * LAT;
        for (int i = tid; i < KC * LAT; i += 256) cbs[i] = src[i];
        for (int i = tid; i < KC; i += 256) cbns[i] = g_cbn[c * KC + i];
        __syncthreads();
        float best = 3.4e38f; int bi = 0;
        for (int k = 0; k < KC; k += 4) {
            float e0 = 0.f, e1 = 0.f, e2 = 0.f, e3 = 0.f;
            const float4* r0 = (const float4*)(cbs + (k+0) * LAT);
            const float4* r1 = (const float4*)(cbs + (k+1) * LAT);
            const float4* r2 = (const float4*)(cbs + (k+2) * LAT);
            const float4* r3 = (const float4*)(cbs + (k+3) * LAT);
            #pragma unroll
            for (int i = 0; i < 8; i++) {
                float4 w0 = r0[i], w1 = r1[i], w2 = r2[i], w3 = r3[i];
                e0 = fmaf(v[4*i], w0.x, e0); e0 = fmaf(v[4*i+1], w0.y, e0);
                e0 = fmaf(v[4*i+2], w0.z, e0); e0 = fmaf(v[4*i+3], w0.w, e0);
                e1 = fmaf(v[4*i], w1.x, e1); e1 = fmaf(v[4*i+1], w1.y, e1);
                e1 = fmaf(v[4*i+2], w1.z, e1); e1 = fmaf(v[4*i+3], w1.w, e1);
                e2 = fmaf(v[4*i], w2.x, e2); e2 = fmaf(v[4*i+1], w2.y, e2);
                e2 = fmaf(v[4*i+2], w2.z, e2); e2 = fmaf(v[4*i+3], w2.w, e2);
                e3 = fmaf(v[4*i], w3.x, e3); e3 = fmaf(v[4*i+1], w3.y, e3);
                e3 = fmaf(v[4*i+2], w3.z, e3); e3 = fmaf(v[4*i+3], w3.w, e3);
            }
            float d0 = __fadd_rn(__fsub_rn(vn, __fmul_rn(2.0f, e0)), cbns[k+0]);
            float d1 = __fadd_rn(__fsub_rn(vn, __fmul_rn(2.0f, e1)), cbns[k+1]);
            float d2 = __fadd_rn(__fsub_rn(vn, __fmul_rn(2.0f, e2)), cbns[k+2]);
            float d3 = __fadd_rn(__fsub_rn(vn, __fmul_rn(2.0f, e3)), cbns[k+3]);
            if (d0 < best) { best = d0; bi = k+0; }
            if (d1 < best) { best = d1; bi = k+1; }
            if (d2 < best) { best = d2; bi = k+2; }
            if (d3 < best) { best = d3; bi = k+3; }
        }
        g_bidx[r * NC + c] = bi;
    }
}

// ---------------- kernel W1: gather + SF MLP + z outputs + dec softmax ----------------
__global__ void __launch_bounds__(256) kW1(
    const float* __restrict__ cbk,
    const float* __restrict__ sfw1, const float* __restrict__ sfb1,
    const float* __restrict__ sfw2, const float* __restrict__ sfb2,
    const float* __restrict__ lrw,  const float* __restrict__ lrb,
    float* __restrict__ out, int full)
{
    extern __shared__ float sm[];
    float* sfw1t = sm;                  // 512 [MID][LAT]
    float* sfw2s = sfw1t + LAT * MID;   // 512 [MID][LAT]
    float* lrws  = sfw2s + MID * LAT;   // 256 [l][c]
    float* sfb1s = lrws + LAT * NC;     // 16
    float* sfb2s = sfb1s + MID;         // 32
    float* lrbs  = sfb2s + LAT;         // 8

    __shared__ float red[256];

    int tid = threadIdx.x;
    for (int i = tid; i < LAT * MID; i += 256) { int l = i / MID, m = i % MID; sfw1t[m * LAT + l] = sfw1[i]; }
    for (int i = tid; i < MID * LAT; i += 256) sfw2s[i] = sfw2[i];
    for (int i = tid; i < LAT * NC; i += 256) lrws[i] = lrw[i];
    if (tid < MID) sfb1s[tid] = sfb1[tid];
    if (tid < LAT) sfb2s[tid] = sfb2[tid];
    if (tid < NC)  lrbs[tid] = lrb[tid];
    __syncthreads();

    size_t r = (size_t)blockIdx.x * 256 + tid;

    float v[LAT], enc[NC];
    {
        const float4* vp4 = (const float4*)(g_v + r * LAT);
        #pragma unroll
        for (int i = 0; i < 8; i++) {
            float4 t = vp4[i];
            v[4*i] = t.x; v[4*i+1] = t.y; v[4*i+2] = t.z; v[4*i+3] = t.w;
        }
        #pragma unroll
        for (int c = 0; c < NC; c++) enc[c] = g_enc[r * NC + c];
    }

    float zqb[LAT], zn[LAT];
    #pragma unroll
    for (int l = 0; l < LAT; l++) { zqb[l] = 0.f; zn[l] = 0.f; }
    float vqa = 0.f;
    #pragma unroll 1
    for (int c = 0; c < NC; c++) {
        int bi = g_bidx[r * NC + c];
        float zq[LAT];
        {
            const float4* z4 = (const float4*)(cbk + ((size_t)c * KC + bi) * LAT);
            #pragma unroll
            for (int i = 0; i < 8; i++) {
                float4 t = z4[i];
                zq[4*i] = t.x; zq[4*i+1] = t.y; zq[4*i+2] = t.z; zq[4*i+3] = t.w;
            }
        }
        float e = enc[c];
        #pragma unroll
        for (int l = 0; l < LAT; l++) zqb[l] = fmaf(e, zq[l], zqb[l]);
        float sq = 0.f;
        #pragma unroll
        for (int l = 0; l < LAT; l++) { float d = __fsub_rn(v[l], zq[l]); zq[l] = d; sq = fmaf(d, d, sq); }
        vqa = fmaf(e, sq, vqa);
        // zq now holds delta
        float mv[MID];
        #pragma unroll
        for (int m = 0; m < MID; m++) {
            float a = 0.f;
            const float4* w4 = (const float4*)(sfw1t + m * LAT);
            #pragma unroll
            for (int i = 0; i < 8; i++) {
                float4 w = w4[i];
                a = fmaf(zq[4*i], w.x, a); a = fmaf(zq[4*i+1], w.y, a);
                a = fmaf(zq[4*i+2], w.z, a); a = fmaf(zq[4*i+3], w.w, a);
            }
            mv[m] = gelu_ref(__fadd_rn(a, sfb1s[m]));
        }
        #pragma unroll
        for (int l4 = 0; l4 < 8; l4++) {
            float4 acc = make_float4(0.f, 0.f, 0.f, 0.f);
            #pragma unroll
            for (int m = 0; m < MID; m++) {
                float4 w = ((const float4*)sfw2s)[m * 8 + l4];
                acc.x = fmaf(mv[m], w.x, acc.x); acc.y = fmaf(mv[m], w.y, acc.y);
                acc.z = fmaf(mv[m], w.z, acc.z); acc.w = fmaf(mv[m], w.w, acc.w);
            }
            float4 b = ((const float4*)sfb2s)[l4];
            zn[4*l4]   = fmaf(e, __fadd_rn(acc.x, b.x), zn[4*l4]);
            zn[4*l4+1] = fmaf(e, __fadd_rn(acc.y, b.y), zn[4*l4+1]);
            zn[4*l4+2] = fmaf(e, __fadd_rn(acc.z, b.z), zn[4*l4+2]);
            zn[4*l4+3] = fmaf(e, __fadd_rn(acc.w, b.w), zn[4*l4+3]);
        }
    }

    // z_geo / zg / z_tex (cb reloaded late to limit register pressure)
    float zg[LAT];
    #pragma unroll
    for (int l = 0; l < LAT; l++) {
        float cbl = g_cb[r * LAT + l];
        float zgeo = __fadd_rn(__fadd_rn(cbl, zqb[l]), zn[l]);
        zg[l] = tanhf(zgeo);
        float ztv = tanhf(__fsub_rn(__fsub_rn(v[l], zqb[l]), zn[l]));
        g_zt[r * LAT + l] = ztv;
        g_zg[r * LAT + l] = zg[l];
        if (full) {
            out[O_ZGEO + r * LAT + l] = zgeo;
            out[O_ZN   + r * LAT + l] = zn[l];
        }
    }

    // dec softmax (identical arithmetic)
    float dec[NC];
    {
        float lg[NC];
        #pragma unroll
        for (int c = 0; c < NC; c++) lg[c] = 0.f;
        #pragma unroll
        for (int l = 0; l < LAT; l++) {
            float zl = zg[l];
            #pragma unroll
            for (int c = 0; c < NC; c++) lg[c] = fmaf(zl, lrws[l * NC + c], lg[c]);
        }
        #pragma unroll
        for (int c = 0; c < NC; c++) lg[c] = __fadd_rn(lg[c], lrbs[c]);
        float m = lg[0];
        #pragma unroll
        for (int c = 1; c < NC; c++) m = fmaxf(m, lg[c]);
        float s = 0.f;
        #pragma unroll
        for (int c = 0; c < NC; c++) { dec[c] = expf(__fsub_rn(lg[c], m)); s = __fadd_rn(s, dec[c]); }
        #pragma unroll
        for (int c = 0; c < NC; c++) dec[c] = __fdiv_rn(dec[c], s);
    }
    #pragma unroll
    for (int c = 0; c < NC; c++) {
        g_dec[r * NC + c] = dec[c];
        if (full) out[O_DEC + r * NC + c] = dec[c];
    }

    // vq partial reduce
    red[tid] = vqa;
    __syncthreads();
    for (int s = 128; s > 0; s >>= 1) {
        if (tid < s) red[tid] += red[tid + s];
        __syncthreads();
    }
    if (tid == 0) atomicAdd(&g_vq, (double)red[0]);
}

// ---------------- kernel W2: h_global (decw via L1 broadcast, high occupancy) ----------------
__global__ void __launch_bounds__(256, 4) kW2(
    const float* __restrict__ decw, const float* __restrict__ decb)
{
    size_t r = (size_t)blockIdx.x * 256 + threadIdx.x;

    float zg[LAT], dec[NC];
    {
        const float4* z4 = (const float4*)(g_zg + r * LAT);
        #pragma unroll
        for (int i = 0; i < 8; i++) {
            float4 t = z4[i];
            zg[4*i] = t.x; zg[4*i+1] = t.y; zg[4*i+2] = t.z; zg[4*i+3] = t.w;
        }
        #pragma unroll
        for (int c = 0; c < NC; c++) dec[c] = g_dec[r * NC + c];
    }

    // h = sum_c dec[c]*(zg . decw[c][h] + decb[c][h]); 2 h-values in flight
    for (int h = 0; h < HID; h += 2) {
        float acc0 = 0.f, acc1 = 0.f;
        #pragma unroll
        for (int c = 0; c < NC; c++) {
            float a0 = 0.f, a1 = 0.f;
            const float4* w0 = (const float4*)(decw + ((size_t)(c * HID + h)) * LAT);
            const float4* w1 = (const float4*)(decw + ((size_t)(c * HID + h + 1)) * LAT);
            #pragma unroll
            for (int i = 0; i < 8; i++) {
                float4 p = __ldg(w0 + i);
                float4 q = __ldg(w1 + i);
                a0 = fmaf(zg[4*i], p.x, a0); a0 = fmaf(zg[4*i+1], p.y, a0);
                a0 = fmaf(zg[4*i+2], p.z, a0); a0 = fmaf(zg[4*i+3], p.w, a0);
                a1 = fmaf(zg[4*i], q.x, a1); a1 = fmaf(zg[4*i+1], q.y, a1);
                a1 = fmaf(zg[4*i+2], q.z, a1); a1 = fmaf(zg[4*i+3], q.w, a1);
            }
            acc0 = __fadd_rn(acc0, __fmul_rn(dec[c], __fadd_rn(a0, __ldg(decb + c * HID + h))));
            acc1 = __fadd_rn(acc1, __fmul_rn(dec[c], __fadd_rn(a1, __ldg(decb + c * HID + h + 1))));
        }
        g_hg[r * HID + h]     = acc0;
        g_hg[r * HID + h + 1] = acc1;
    }
}

// ---------------- kernel C: h_global -> x_hat (unchanged) ----------------
__global__ void __launch_bounds__(256) kC(
    const float* __restrict__ rw1, const float* __restrict__ rb1,
    const float* __restrict__ rw2, const float* __restrict__ rb2,
    const float* __restrict__ skw, const float* __restrict__ skb,
    const float* __restrict__ txw, const float* __restrict__ txb,
    const float* __restrict__ tscale, float* __restrict__ out)
{
    extern __shared__ float sm[];
    float* rw1n = sm;
    float* rw2s = rw1n + HID * HID;
    float* skws = rw2s + HID * DIN;
    float* txws = skws + HID * DIN;
    float* rb1s = txws + LAT * DIN;
    float* rb2s = rb1s + HID;
    float* skbs = rb2s + DIN;
    float* txbs = skbs + DIN;

    int tid = threadIdx.x;
    for (int i = tid; i < HID * HID; i += 256) rw1n[i] = rw1[i];
    for (int i = tid; i < HID * DIN; i += 256) { rw2s[i] = rw2[i]; skws[i] = skw[i]; }
    for (int i = tid; i < LAT * DIN; i += 256) txws[i] = txw[i];
    if (tid < HID) rb1s[tid] = rb1[tid];
    if (tid < DIN) { rb2s[tid] = rb2[tid]; skbs[tid] = skb[tid]; txbs[tid] = txb[tid]; }
    __syncthreads();

    size_t r = (size_t)blockIdx.x * 256 + tid;
    float ts = tscale[0];

    const float* hgp = g_hg + r * HID;

    float hg[HID], g[HID];
    {
        const float4* h4 = (const float4*)hgp;
        #pragma unroll
        for (int i = 0; i < 32; i++) {
            float4 t = h4[i];
            hg[4*i] = t.x; hg[4*i+1] = t.y; hg[4*i+2] = t.z; hg[4*i+3] = t.w;
            g[4*i]   = gelu_ref(t.x); g[4*i+1] = gelu_ref(t.y);
            g[4*i+2] = gelu_ref(t.z); g[4*i+3] = gelu_ref(t.w);
        }
    }

    float o[DIN], sk[DIN];
    #pragma unroll
    for (int l = 0; l < DIN; l++) { o[l] = 0.f; sk[l] = 0.f; }

    for (int j = 0; j < HID; j += 4) {
        float a0 = 0.f, a1 = 0.f, a2 = 0.f, a3 = 0.f;
        #pragma unroll
        for (int i = 0; i < HID; i++) {
            float gi = g[i];
            float4 w = *(const float4*)(rw1n + i * HID + j);
            a0 = fmaf(gi, w.x, a0); a1 = fmaf(gi, w.y, a1);
            a2 = fmaf(gi, w.z, a2); a3 = fmaf(gi, w.w, a3);
        }
        float u0 = gelu_ref(__fadd_rn(a0, rb1s[j+0]));
        float u1 = gelu_ref(__fadd_rn(a1, rb1s[j+1]));
        float u2 = gelu_ref(__fadd_rn(a2, rb1s[j+2]));
        float u3 = gelu_ref(__fadd_rn(a3, rb1s[j+3]));
        const float4* r0 = (const float4*)(rw2s + (j+0) * DIN);
        const float4* r1 = (const float4*)(rw2s + (j+1) * DIN);
        const float4* r2 = (const float4*)(rw2s + (j+2) * DIN);
        const float4* r3 = (const float4*)(rw2s + (j+3) * DIN);
        #pragma unroll
        for (int l4 = 0; l4 < 8; l4++) {
            float4 w = r0[l4];
            o[4*l4]   = fmaf(u0, w.x, o[4*l4]);   o[4*l4+1] = fmaf(u0, w.y, o[4*l4+1]);
            o[4*l4+2] = fmaf(u0, w.z, o[4*l4+2]); o[4*l4+3] = fmaf(u0, w.w, o[4*l4+3]);
        }
        #pragma unroll
        for (int l4 = 0; l4 < 8; l4++) {
            float4 w = r1[l4];
            o[4*l4]   = fmaf(u1, w.x, o[4*l4]);   o[4*l4+1] = fmaf(u1, w.y, o[4*l4+1]);
            o[4*l4+2] = fmaf(u1, w.z, o[4*l4+2]); o[4*l4+3] = fmaf(u1, w.w, o[4*l4+3]);
        }
        #pragma unroll
        for (int l4 = 0; l4 < 8; l4++) {
            float4 w = r2[l4];
            o[4*l4]   = fmaf(u2, w.x, o[4*l4]);   o[4*l4+1] = fmaf(u2, w.y, o[4*l4+1]);
            o[4*l4+2] = fmaf(u2, w.z, o[4*l4+2]); o[4*l4+3] = fmaf(u2, w.w, o[4*l4+3]);
        }
        #pragma unroll
        for (int l4 = 0; l4 < 8; l4++) {
            float4 w = r3[l4];
            o[4*l4]   = fmaf(u3, w.x, o[4*l4]);   o[4*l4+1] = fmaf(u3, w.y, o[4*l4+1]);
            o[4*l4+2] = fmaf(u3, w.z, o[4*l4+2]); o[4*l4+3] = fmaf(u3, w.w, o[4*l4+3]);
        }
        const float4* s0 = (const float4*)(skws + (j+0) * DIN);
        const float4* s1 = (const float4*)(skws + (j+1) * DIN);
        const float4* s2 = (const float4*)(skws + (j+2) * DIN);
        const float4* s3 = (const float4*)(skws + (j+3) * DIN);
        float h0 = hg[j+0], h1v = hg[j+1], h2v = hg[j+2], h3v = hg[j+3];
        #pragma unroll
        for (int l4 = 0; l4 < 8; l4++) {
            float4 w = s0[l4];
            sk[4*l4]   = fmaf(h0, w.x, sk[4*l4]);   sk[4*l4+1] = fmaf(h0, w.y, sk[4*l4+1]);
            sk[4*l4+2] = fmaf(h0, w.z, sk[4*l4+2]); sk[4*l4+3] = fmaf(h0, w.w, sk[4*l4+3]);
        }
        #pragma unroll
        for (int l4 = 0; l4 < 8; l4++) {
            float4 w = s1[l4];
            sk[4*l4]   = fmaf(h1v, w.x, sk[4*l4]);   sk[4*l4+1] = fmaf(h1v, w.y, sk[4*l4+1]);
            sk[4*l4+2] = fmaf(h1v, w.z, sk[4*l4+2]); sk[4*l4+3] = fmaf(h1v, w.w, sk[4*l4+3]);
        }
        #pragma unroll
        for (int l4 = 0; l4 < 8; l4++) {
            float4 w = s2[l4];
            sk[4*l4]   = fmaf(h2v, w.x, sk[4*l4]);   sk[4*l4+1] = fmaf(h2v, w.y, sk[4*l4+1]);
            sk[4*l4+2] = fmaf(h2v, w.z, sk[4*l4+2]); sk[4*l4+3] = fmaf(h2v, w.w, sk[4*l4+3]);
        }
        #pragma unroll
        for (int l4 = 0; l4 < 8; l4++) {
            float4 w = s3[l4];
            sk[4*l4]   = fmaf(h3v, w.x, sk[4*l4]);   sk[4*l4+1] = fmaf(h3v, w.y, sk[4*l4+1]);
            sk[4*l4+2] = fmaf(h3v, w.z, sk[4*l4+2]); sk[4*l4+3] = fmaf(h3v, w.w, sk[4*l4+3]);
        }
    }

    float zt[LAT];
    {
        const float4* z4 = (const float4*)(g_zt + r * LAT);
        #pragma unroll
        for (int i = 0; i < 8; i++) {
            float4 t = z4[i];
            zt[4*i] = t.x; zt[4*i+1] = t.y; zt[4*i+2] = t.z; zt[4*i+3] = t.w;
        }
    }
    float tx[DIN];
    #pragma unroll
    for (int l = 0; l < DIN; l++) tx[l] = 0.f;
    #pragma unroll
    for (int lp = 0; lp < LAT; lp++) {
        float ztl = zt[lp];
        const float4* t4 = (const float4*)(txws + lp * DIN);
        #pragma unroll
        for (int l4 = 0; l4 < 8; l4++) {
            float4 w = t4[l4];
            tx[4*l4]   = fmaf(ztl, w.x, tx[4*l4]);   tx[4*l4+1] = fmaf(ztl, w.y, tx[4*l4+1]);
            tx[4*l4+2] = fmaf(ztl, w.z, tx[4*l4+2]); tx[4*l4+3] = fmaf(ztl, w.w, tx[4*l4+3]);
        }
    }

    float4* xo = (float4*)(out + O_XHAT + r * DIN);
    #pragma unroll
    for (int l4 = 0; l4 < 8; l4++) {
        float4 t;
        #pragma unroll
        for (int q = 0; q < 4; q++) {
            int l = 4*l4 + q;
            float mlp  = __fadd_rn(o[l], rb2s[l]);
            float skp  = __fadd_rn(sk[l], skbs[l]);
            float base = __fadd_rn(mlp, skp);
            float texv = __fmul_rn(ts, __fadd_rn(tx[l], txbs[l]));
            ((float*)&t)[q] = __fadd_rn(base, texv);
        }
        xo[l4] = t;
    }
}

// ---------------- kernel D ----------------
__global__ void kD(float* __restrict__ out, int full) {
    if (full) out[O_VQ] = (float)(1.25 * g_vq / ((double)Bsz * (double)LAT));
}

// ---------------- launch ----------------
extern "C" void kernel_launch(void* const* d_in, const int* in_sizes, int n_in,
                              void* d_out, int out_size) {
    const float* x    = (const float*)d_in[0];
    const float* fw1  = (const float*)d_in[1];
    const float* fb1  = (const float*)d_in[2];
    const float* fw2  = (const float*)d_in[3];
    const float* fb2  = (const float*)d_in[4];
    const float* vpw  = (const float*)d_in[5];
    const float* vpb  = (const float*)d_in[6];
    const float* cc   = (const float*)d_in[7];
    const float* cbk  = (const float*)d_in[8];
    const float* sfw1 = (const float*)d_in[9];
    const float* sfb1 = (const float*)d_in[10];
    const float* sfw2 = (const float*)d_in[11];
    const float* sfb2 = (const float*)d_in[12];
    const float* decw = (const float*)d_in[13];
    const float* decb = (const float*)d_in[14];
    const float* lrw  = (const float*)d_in[15];
    const float* lrb  = (const float*)d_in[16];
    const float* txw  = (const float*)d_in[17];
    const float* txb  = (const float*)d_in[18];
    const float* tsc  = (const float*)d_in[19];
    const float* rw1  = (const float*)d_in[20];
    const float* rb1  = (const float*)d_in[21];
    const float* rw2  = (const float*)d_in[22];
    const float* rb2  = (const float*)d_in[23];
    const float* skw  = (const float*)d_in[24];
    const float* skb  = (const float*)d_in[25];

    float* out = (float*)d_out;
    int full = (out_size >= O_TOTAL) ? 1 : 0;

    const int SMEM_A  = (DIN*HID + HID*HID + HID*LAT + HID + HID + LAT + HID*256) * 4;
    const int SMEM_V  = (KC*LAT + KC + NC*LAT + LAT*NC) * 4;
    const int SMEM_W1 = (LAT*MID + MID*LAT + LAT*NC + MID + LAT + NC) * 4;
    const int SMEM_C  = (HID*HID + HID*DIN + HID*DIN + LAT*DIN + HID + DIN + DIN + DIN) * 4;

    cudaFuncSetAttribute(kA, cudaFuncAttributeMaxDynamicSharedMemorySize, SMEM_A);
    cudaFuncSetAttribute(kV, cudaFuncAttributeMaxDynamicSharedMemorySize, SMEM_V);
    cudaFuncSetAttribute(kW1, cudaFuncAttributeMaxDynamicSharedMemorySize, SMEM_W1);
    cudaFuncSetAttribute(kC, cudaFuncAttributeMaxDynamicSharedMemorySize, SMEM_C);

    kPrep<<<16, 256>>>(cbk);
    kA<<<Bsz / 256, 256, SMEM_A>>>(x, fw1, fb1, fw2, fb2, vpw, vpb);
    kV<<<Bsz / 256, 256, SMEM_V>>>(cc, cbk, out, full);
    kW1<<<Bsz / 256, 256, SMEM_W1>>>(cbk, sfw1, sfb1, sfw2, sfb2, lrw, lrb, out, full);
    kW2<<<Bsz / 256, 256>>>(decw, decb);
    kC<<<Bsz / 256, 256, SMEM_C>>>(rw1, rb1, rw2, rb2, skw, skb, txw, txb, tsc, out);
    kD<<<1, 1>>>(out, full);
}

// round 9
// speedup vs baseline: 1.3093x; 1.3093x over previous
#include <cuda_runtime.h>

#define Bsz 65536
#define DIN 32
#define HID 128
#define LAT 32
#define NC  8
#define KC  512
#define MID 16

// ---------------- scratch (no allocations allowed) ----------------
static __device__ float  g_v[Bsz * LAT];     // v then v_local
static __device__ float  g_cb[Bsz * LAT];
static __device__ float  g_enc[Bsz * NC];
static __device__ int    g_bidx[Bsz * NC];
static __device__ float  g_hg[Bsz * HID];
static __device__ float  g_zt[Bsz * LAT];
static __device__ float  g_cbn[NC * KC];
static __device__ double g_vq;

// ---------------- output layout (concatenated tuple, f32) ----------------
#define O_XHAT 0
#define O_VQ   (Bsz * DIN)
#define O_ENC  (O_VQ + 1)
#define O_DEC  (O_ENC + Bsz * NC)
#define O_K    (O_DEC + Bsz * NC)
#define O_ZGEO (O_K + Bsz)
#define O_ZN   (O_ZGEO + Bsz * LAT)
#define O_CBAR (O_ZN + Bsz * LAT)
#define O_TOTAL (O_CBAR + Bsz * LAT)

__device__ __forceinline__ float gelu_ref(float x) {
    float u = __fdiv_rn(x, 1.4142135623730951f);
    float t = erff(u);
    return __fmul_rn(__fmul_rn(0.5f, x), __fadd_rn(1.0f, t));
}

// ---------------- prep ----------------
__global__ void kPrep(const float* __restrict__ cbk) {
    int idx = blockIdx.x * blockDim.x + threadIdx.x;
    if (idx == 0) g_vq = 0.0;
    if (idx < NC * KC) {
        const float* row = cbk + (size_t)idx * LAT;
        float s = 0.f;
        #pragma unroll
        for (int l = 0; l < LAT; l++) s = __fadd_rn(s, __fmul_rn(row[l], row[l]));
        g_cbn[idx] = s;
    }
}

// ---------------- kernel A: x -> features -> v (unchanged) ----------------
__global__ void __launch_bounds__(256) kA(
    const float* __restrict__ x,  const float* __restrict__ w1, const float* __restrict__ b1,
    const float* __restrict__ w2, const float* __restrict__ b2,
    const float* __restrict__ vp, const float* __restrict__ vpb)
{
    extern __shared__ float sm[];
    float* w1n  = sm;
    float* w2n  = w1n + DIN * HID;
    float* vps  = w2n + HID * HID;
    float* b1s  = vps + HID * LAT;
    float* b2s  = b1s + HID;
    float* vpbs = b2s + HID;
    float* h1s  = vpbs + LAT;

    int tid = threadIdx.x;
    for (int i = tid; i < DIN * HID; i += 256) w1n[i] = w1[i];
    for (int i = tid; i < HID * HID; i += 256) w2n[i] = w2[i];
    for (int i = tid; i < HID * LAT; i += 256) vps[i] = vp[i];
    if (tid < HID) { b1s[tid] = b1[tid]; b2s[tid] = b2[tid]; }
    if (tid < LAT) vpbs[tid] = vpb[tid];
    __syncthreads();

    size_t r = (size_t)blockIdx.x * 256 + tid;

    float xr[DIN];
    {
        const float4* xp = (const float4*)(x + r * DIN);
        #pragma unroll
        for (int i = 0; i < 8; i++) {
            float4 t = xp[i];
            xr[4*i] = t.x; xr[4*i+1] = t.y; xr[4*i+2] = t.z; xr[4*i+3] = t.w;
        }
    }

    for (int j = 0; j < HID; j += 4) {
        float a0 = 0.f, a1 = 0.f, a2 = 0.f, a3 = 0.f;
        #pragma unroll
        for (int i = 0; i < DIN; i++) {
            float xi = xr[i];
            float4 w = *(const float4*)(w1n + i * HID + j);
            a0 = fmaf(xi, w.x, a0); a1 = fmaf(xi, w.y, a1);
            a2 = fmaf(xi, w.z, a2); a3 = fmaf(xi, w.w, a3);
        }
        h1s[(j+0) * 256 + tid] = gelu_ref(__fadd_rn(a0, b1s[j+0]));
        h1s[(j+1) * 256 + tid] = gelu_ref(__fadd_rn(a1, b1s[j+1]));
        h1s[(j+2) * 256 + tid] = gelu_ref(__fadd_rn(a2, b1s[j+2]));
        h1s[(j+3) * 256 + tid] = gelu_ref(__fadd_rn(a3, b1s[j+3]));
    }

    float h1[HID];
    #pragma unroll
    for (int i = 0; i < HID; i++) h1[i] = h1s[i * 256 + tid];

    float vv[LAT];
    #pragma unroll
    for (int l = 0; l < LAT; l++) vv[l] = 0.f;
    for (int j = 0; j < HID; j += 4) {
        float a0 = 0.f, a1 = 0.f, a2 = 0.f, a3 = 0.f;
        #pragma unroll
        for (int i = 0; i < HID; i++) {
            float hi = h1[i];
            float4 w = *(const float4*)(w2n + i * HID + j);
            a0 = fmaf(hi, w.x, a0); a1 = fmaf(hi, w.y, a1);
            a2 = fmaf(hi, w.z, a2); a3 = fmaf(hi, w.w, a3);
        }
        float u0 = gelu_ref(__fadd_rn(a0, b2s[j+0]));
        float u1 = gelu_ref(__fadd_rn(a1, b2s[j+1]));
        float u2 = gelu_ref(__fadd_rn(a2, b2s[j+2]));
        float u3 = gelu_ref(__fadd_rn(a3, b2s[j+3]));
        const float4* vr0 = (const float4*)(vps + (j+0) * LAT);
        const float4* vr1 = (const float4*)(vps + (j+1) * LAT);
        const float4* vr2 = (const float4*)(vps + (j+2) * LAT);
        const float4* vr3 = (const float4*)(vps + (j+3) * LAT);
        #pragma unroll
        for (int l4 = 0; l4 < 8; l4++) {
            float4 w = vr0[l4];
            vv[4*l4]   = fmaf(u0, w.x, vv[4*l4]);   vv[4*l4+1] = fmaf(u0, w.y, vv[4*l4+1]);
            vv[4*l4+2] = fmaf(u0, w.z, vv[4*l4+2]); vv[4*l4+3] = fmaf(u0, w.w, vv[4*l4+3]);
        }
        #pragma unroll
        for (int l4 = 0; l4 < 8; l4++) {
            float4 w = vr1[l4];
            vv[4*l4]   = fmaf(u1, w.x, vv[4*l4]);   vv[4*l4+1] = fmaf(u1, w.y, vv[4*l4+1]);
            vv[4*l4+2] = fmaf(u1, w.z, vv[4*l4+2]); vv[4*l4+3] = fmaf(u1, w.w, vv[4*l4+3]);
        }
        #pragma unroll
        for (int l4 = 0; l4 < 8; l4++) {
            float4 w = vr2[l4];
            vv[4*l4]   = fmaf(u2, w.x, vv[4*l4]);   vv[4*l4+1] = fmaf(u2, w.y, vv[4*l4+1]);
            vv[4*l4+2] = fmaf(u2, w.z, vv[4*l4+2]); vv[4*l4+3] = fmaf(u2, w.w, vv[4*l4+3]);
        }
        #pragma unroll
        for (int l4 = 0; l4 < 8; l4++) {
            float4 w = vr3[l4];
            vv[4*l4]   = fmaf(u3, w.x, vv[4*l4]);   vv[4*l4+1] = fmaf(u3, w.y, vv[4*l4+1]);
            vv[4*l4+2] = fmaf(u3, w.z, vv[4*l4+2]); vv[4*l4+3] = fmaf(u3, w.w, vv[4*l4+3]);
        }
    }
    float4* vo = (float4*)(g_v + r * LAT);
    #pragma unroll
    for (int l4 = 0; l4 < 8; l4++) {
        float4 t;
        t.x = __fadd_rn(vv[4*l4],   vpbs[4*l4]);
        t.y = __fadd_rn(vv[4*l4+1], vpbs[4*l4+1]);
        t.z = __fadd_rn(vv[4*l4+2], vpbs[4*l4+2]);
        t.w = __fadd_rn(vv[4*l4+3], vpbs[4*l4+3]);
        vo[l4] = t;
    }
}

// ---------------- kernel V: softmax/K + c_bar/v_local + VQ argmin ----------------
// smem = one codebook chart tile + small tables (~70KB) -> 2 blocks/SM
__global__ void __launch_bounds__(256, 2) kV(
    const float* __restrict__ cc, const float* __restrict__ cbk,
    float* __restrict__ out, int full)
{
    extern __shared__ float sm[];
    float* cbs  = sm;               // KC*LAT
    float* cbns = cbs + KC * LAT;   // KC
    float* ccs  = cbns + KC;        // [c][l]
    float* cct  = ccs + NC * LAT;   // [l][c]

    int tid = threadIdx.x;
    for (int i = tid; i < NC * LAT; i += 256) {
        float t = cc[i]; ccs[i] = t;
        int c = i / LAT, l = i % LAT;
        cct[l * NC + c] = t;
    }

    size_t r = (size_t)blockIdx.x * 256 + tid;
    float v[LAT];
    {
        const float4* vp4 = (const float4*)(g_v + r * LAT);
        #pragma unroll
        for (int i = 0; i < 8; i++) {
            float4 t = vp4[i];
            v[4*i] = t.x; v[4*i+1] = t.y; v[4*i+2] = t.z; v[4*i+3] = t.w;
        }
    }
    __syncthreads();

    // ---- enc softmax + K: BYTE-IDENTICAL to the passing version ----
    float enc[NC]; int K;
    {
        float sc[NC];
        #pragma unroll
        for (int c = 0; c < NC; c++) sc[c] = 0.f;
        #pragma unroll
        for (int l = 0; l < LAT; l++) {
            float vl = v[l];
            float4 wa = ((const float4*)(cct + l * NC))[0];
            float4 wb = ((const float4*)(cct + l * NC))[1];
            sc[0] = fmaf(vl, wa.x, sc[0]); sc[1] = fmaf(vl, wa.y, sc[1]);
            sc[2] = fmaf(vl, wa.z, sc[2]); sc[3] = fmaf(vl, wa.w, sc[3]);
            sc[4] = fmaf(vl, wb.x, sc[4]); sc[5] = fmaf(vl, wb.y, sc[5]);
            sc[6] = fmaf(vl, wb.z, sc[6]); sc[7] = fmaf(vl, wb.w, sc[7]);
        }
        #pragma unroll
        for (int c = 0; c < NC; c++) sc[c] = __fdiv_rn(sc[c], 5.656854249492381f);
        float m = sc[0];
        #pragma unroll
        for (int c = 1; c < NC; c++) m = fmaxf(m, sc[c]);
        float e[NC];
        #pragma unroll
        for (int c = 0; c < NC; c++)
            e[c] = (float)exp((double)__fsub_rn(sc[c], m));  // correctly-rounded fp32 exp
        float s01 = __fadd_rn(e[0], e[1]);
        float s23 = __fadd_rn(e[2], e[3]);
        float s45 = __fadd_rn(e[4], e[5]);
        float s67 = __fadd_rn(e[6], e[7]);
        float s = __fadd_rn(__fadd_rn(s01, s23), __fadd_rn(s45, s67));
        #pragma unroll
        for (int c = 0; c < NC; c++) enc[c] = __fdiv_rn(e[c], s);
        float bm = e[0]; K = 0;
        #pragma unroll
        for (int c = 1; c < NC; c++) if (e[c] > bm) { bm = e[c]; K = c; }
    }

    // c_bar / v_local
    float cb[LAT];
    #pragma unroll
    for (int l = 0; l < LAT; l++) cb[l] = 0.f;
    #pragma unroll
    for (int c = 0; c < NC; c++) {
        float e = enc[c];
        #pragma unroll
        for (int l = 0; l < LAT; l++) cb[l] = fmaf(e, ccs[c * LAT + l], cb[l]);
    }
    #pragma unroll
    for (int l = 0; l < LAT; l++) v[l] = __fsub_rn(v[l], cb[l]);   // v_local

    {
        float4* vo = (float4*)(g_v + r * LAT);
        float4* co = (float4*)(g_cb + r * LAT);
        #pragma unroll
        for (int l4 = 0; l4 < 8; l4++) {
            float4 tv, tc;
            tv.x = v[4*l4];  tv.y = v[4*l4+1];  tv.z = v[4*l4+2];  tv.w = v[4*l4+3];
            tc.x = cb[4*l4]; tc.y = cb[4*l4+1]; tc.z = cb[4*l4+2]; tc.w = cb[4*l4+3];
            vo[l4] = tv; co[l4] = tc;
        }
        #pragma unroll
        for (int c = 0; c < NC; c++) g_enc[r * NC + c] = enc[c];
        if (full) {
            #pragma unroll
            for (int c = 0; c < NC; c++) out[O_ENC + r * NC + c] = enc[c];
            out[O_K + r] = (float)K;
            #pragma unroll
            for (int l = 0; l < LAT; l++) out[O_CBAR + r * LAT + l] = cb[l];
        }
    }

    float vn = 0.f;
    #pragma unroll
    for (int l = 0; l < LAT; l++) vn = __fadd_rn(vn, __fmul_rn(v[l], v[l]));

    // VQ argmin per chart (identical arithmetic)
    #pragma unroll 1
    for (int c = 0; c < NC; c++) {
        __syncthreads();
        const float* src = cbk + (size_t)c * KC * LAT;
        for (int i = tid; i < KC * LAT; i += 256) cbs[i] = src[i];
        for (int i = tid; i < KC; i += 256) cbns[i] = g_cbn[c * KC + i];
        __syncthreads();
        float best = 3.4e38f; int bi = 0;
        for (int k = 0; k < KC; k += 4) {
            float e0 = 0.f, e1 = 0.f, e2 = 0.f, e3 = 0.f;
            const float4* r0 = (const float4*)(cbs + (k+0) * LAT);
            const float4* r1 = (const float4*)(cbs + (k+1) * LAT);
            const float4* r2 = (const float4*)(cbs + (k+2) * LAT);
            const float4* r3 = (const float4*)(cbs + (k+3) * LAT);
            #pragma unroll
            for (int i = 0; i < 8; i++) {
                float4 w0 = r0[i], w1 = r1[i], w2 = r2[i], w3 = r3[i];
                e0 = fmaf(v[4*i], w0.x, e0); e0 = fmaf(v[4*i+1], w0.y, e0);
                e0 = fmaf(v[4*i+2], w0.z, e0); e0 = fmaf(v[4*i+3], w0.w, e0);
                e1 = fmaf(v[4*i], w1.x, e1); e1 = fmaf(v[4*i+1], w1.y, e1);
                e1 = fmaf(v[4*i+2], w1.z, e1); e1 = fmaf(v[4*i+3], w1.w, e1);
                e2 = fmaf(v[4*i], w2.x, e2); e2 = fmaf(v[4*i+1], w2.y, e2);
                e2 = fmaf(v[4*i+2], w2.z, e2); e2 = fmaf(v[4*i+3], w2.w, e2);
                e3 = fmaf(v[4*i], w3.x, e3); e3 = fmaf(v[4*i+1], w3.y, e3);
                e3 = fmaf(v[4*i+2], w3.z, e3); e3 = fmaf(v[4*i+3], w3.w, e3);
            }
            float d0 = __fadd_rn(__fsub_rn(vn, __fmul_rn(2.0f, e0)), cbns[k+0]);
            float d1 = __fadd_rn(__fsub_rn(vn, __fmul_rn(2.0f, e1)), cbns[k+1]);
            float d2 = __fadd_rn(__fsub_rn(vn, __fmul_rn(2.0f, e2)), cbns[k+2]);
            float d3 = __fadd_rn(__fsub_rn(vn, __fmul_rn(2.0f, e3)), cbns[k+3]);
            if (d0 < best) { best = d0; bi = k+0; }
            if (d1 < best) { best = d1; bi = k+1; }
            if (d2 < best) { best = d2; bi = k+2; }
            if (d3 < best) { best = d3; bi = k+3; }
        }
        g_bidx[r * NC + c] = bi;
    }
}

// ---------------- kernel W: gather + SF MLP + z outputs + dec softmax + h_global ----------------
// Monolithic (round-7 kB structure minus dist search) -> big kernel, ptxas allots
// full registers, no spill. dec_w in smem (137 KB), 1 block/SM.
__global__ void __launch_bounds__(256) kW(
    const float* __restrict__ cbk,
    const float* __restrict__ sfw1, const float* __restrict__ sfb1,
    const float* __restrict__ sfw2, const float* __restrict__ sfb2,
    const float* __restrict__ decw, const float* __restrict__ decb,
    const float* __restrict__ lrw,  const float* __restrict__ lrb,
    float* __restrict__ out, int full)
{
    extern __shared__ float sm[];
    float* decws = sm;                       // 32768 f
    float* decbs = decws + NC * HID * LAT;   // 1024 f
    float* sfw1t = decbs + NC * HID;         // 512 [MID][LAT]
    float* sfw2s = sfw1t + LAT * MID;        // 512 [MID][LAT]
    float* lrws  = sfw2s + MID * LAT;        // 256 [l][c]
    float* sfb1s = lrws + LAT * NC;          // 16
    float* sfb2s = sfb1s + MID;              // 32
    float* lrbs  = sfb2s + LAT;              // 8

    __shared__ float red[256];

    int tid = threadIdx.x;
    for (int i = tid; i < NC * HID * LAT; i += 256) decws[i] = decw[i];
    for (int i = tid; i < NC * HID; i += 256) decbs[i] = decb[i];
    for (int i = tid; i < LAT * MID; i += 256) { int l = i / MID, m = i % MID; sfw1t[m * LAT + l] = sfw1[i]; }
    for (int i = tid; i < MID * LAT; i += 256) sfw2s[i] = sfw2[i];
    for (int i = tid; i < LAT * NC; i += 256) lrws[i] = lrw[i];
    if (tid < MID) sfb1s[tid] = sfb1[tid];
    if (tid < LAT) sfb2s[tid] = sfb2[tid];
    if (tid < NC)  lrbs[tid] = lrb[tid];
    __syncthreads();

    size_t r = (size_t)blockIdx.x * 256 + tid;

    float v[LAT], enc[NC];
    {
        const float4* vp4 = (const float4*)(g_v + r * LAT);
        #pragma unroll
        for (int i = 0; i < 8; i++) {
            float4 t = vp4[i];
            v[4*i] = t.x; v[4*i+1] = t.y; v[4*i+2] = t.z; v[4*i+3] = t.w;
        }
        #pragma unroll
        for (int c = 0; c < NC; c++) enc[c] = g_enc[r * NC + c];
    }

    float zqb[LAT], zn[LAT];
    #pragma unroll
    for (int l = 0; l < LAT; l++) { zqb[l] = 0.f; zn[l] = 0.f; }
    float vqa = 0.f;
    #pragma unroll
    for (int c = 0; c < NC; c++) {
        int bi = g_bidx[r * NC + c];
        float zq[LAT];
        {
            const float4* z4 = (const float4*)(cbk + ((size_t)c * KC + bi) * LAT);
            #pragma unroll
            for (int i = 0; i < 8; i++) {
                float4 t = z4[i];
                zq[4*i] = t.x; zq[4*i+1] = t.y; zq[4*i+2] = t.z; zq[4*i+3] = t.w;
            }
        }
        float e = enc[c];
        #pragma unroll
        for (int l = 0; l < LAT; l++) zqb[l] = fmaf(e, zq[l], zqb[l]);
        float sq = 0.f;
        #pragma unroll
        for (int l = 0; l < LAT; l++) { float d = __fsub_rn(v[l], zq[l]); zq[l] = d; sq = fmaf(d, d, sq); }
        vqa = fmaf(e, sq, vqa);
        // zq now holds delta
        float mv[MID];
        #pragma unroll
        for (int m = 0; m < MID; m++) {
            float a = 0.f;
            const float4* w4 = (const float4*)(sfw1t + m * LAT);
            #pragma unroll
            for (int i = 0; i < 8; i++) {
                float4 w = w4[i];
                a = fmaf(zq[4*i], w.x, a); a = fmaf(zq[4*i+1], w.y, a);
                a = fmaf(zq[4*i+2], w.z, a); a = fmaf(zq[4*i+3], w.w, a);
            }
            mv[m] = gelu_ref(__fadd_rn(a, sfb1s[m]));
        }
        #pragma unroll
        for (int l4 = 0; l4 < 8; l4++) {
            float4 acc = make_float4(0.f, 0.f, 0.f, 0.f);
            #pragma unroll
            for (int m = 0; m < MID; m++) {
                float4 w = ((const float4*)sfw2s)[m * 8 + l4];
                acc.x = fmaf(mv[m], w.x, acc.x); acc.y = fmaf(mv[m], w.y, acc.y);
                acc.z = fmaf(mv[m], w.z, acc.z); acc.w = fmaf(mv[m], w.w, acc.w);
            }
            float4 b = ((const float4*)sfb2s)[l4];
            zn[4*l4]   = fmaf(e, __fadd_rn(acc.x, b.x), zn[4*l4]);
            zn[4*l4+1] = fmaf(e, __fadd_rn(acc.y, b.y), zn[4*l4+1]);
            zn[4*l4+2] = fmaf(e, __fadd_rn(acc.z, b.z), zn[4*l4+2]);
            zn[4*l4+3] = fmaf(e, __fadd_rn(acc.w, b.w), zn[4*l4+3]);
        }
    }

    // z_geo / zg / z_tex
    float zg[LAT];
    #pragma unroll
    for (int l = 0; l < LAT; l++) {
        float cbl = g_cb[r * LAT + l];
        float zgeo = __fadd_rn(__fadd_rn(cbl, zqb[l]), zn[l]);
        zg[l] = tanhf(zgeo);
        float ztv = tanhf(__fsub_rn(__fsub_rn(v[l], zqb[l]), zn[l]));
        g_zt[r * LAT + l] = ztv;
        if (full) {
            out[O_ZGEO + r * LAT + l] = zgeo;
            out[O_ZN   + r * LAT + l] = zn[l];
        }
    }

    // dec softmax (identical arithmetic)
    float dec[NC];
    {
        float lg[NC];
        #pragma unroll
        for (int c = 0; c < NC; c++) lg[c] = 0.f;
        #pragma unroll
        for (int l = 0; l < LAT; l++) {
            float zl = zg[l];
            #pragma unroll
            for (int c = 0; c < NC; c++) lg[c] = fmaf(zl, lrws[l * NC + c], lg[c]);
        }
        #pragma unroll
        for (int c = 0; c < NC; c++) lg[c] = __fadd_rn(lg[c], lrbs[c]);
        float m = lg[0];
        #pragma unroll
        for (int c = 1; c < NC; c++) m = fmaxf(m, lg[c]);
        float s = 0.f;
        #pragma unroll
        for (int c = 0; c < NC; c++) { dec[c] = expf(__fsub_rn(lg[c], m)); s = __fadd_rn(s, dec[c]); }
        #pragma unroll
        for (int c = 0; c < NC; c++) dec[c] = __fdiv_rn(dec[c], s);
    }
    if (full) {
        #pragma unroll
        for (int c = 0; c < NC; c++) out[O_DEC + r * NC + c] = dec[c];
    }

    // h_global: per (c,h): seq-fma dot over l, +decb after; weighted sum over c
    for (int h = 0; h < HID; h++) {
        float acc = 0.f;
        #pragma unroll
        for (int c = 0; c < NC; c++) {
            float a = 0.f;
            const float4* w4 = (const float4*)(decws + (c * HID + h) * LAT);
            #pragma unroll
            for (int i = 0; i < 8; i++) {
                float4 w = w4[i];
                a = fmaf(zg[4*i], w.x, a); a = fmaf(zg[4*i+1], w.y, a);
                a = fmaf(zg[4*i+2], w.z, a); a = fmaf(zg[4*i+3], w.w, a);
            }
            acc = __fadd_rn(acc, __fmul_rn(dec[c], __fadd_rn(a, decbs[c * HID + h])));
        }
        g_hg[r * HID + h] = acc;
    }

    // vq partial reduce
    red[tid] = vqa;
    __syncthreads();
    for (int s = 128; s > 0; s >>= 1) {
        if (tid < s) red[tid] += red[tid + s];
        __syncthreads();
    }
    if (tid == 0) atomicAdd(&g_vq, (double)red[0]);
}

// ---------------- kernel C: h_global -> x_hat (unchanged) ----------------
__global__ void __launch_bounds__(256) kC(
    const float* __restrict__ rw1, const float* __restrict__ rb1,
    const float* __restrict__ rw2, const float* __restrict__ rb2,
    const float* __restrict__ skw, const float* __restrict__ skb,
    const float* __restrict__ txw, const float* __restrict__ txb,
    const float* __restrict__ tscale, float* __restrict__ out)
{
    extern __shared__ float sm[];
    float* rw1n = sm;
    float* rw2s = rw1n + HID * HID;
    float* skws = rw2s + HID * DIN;
    float* txws = skws + HID * DIN;
    float* rb1s = txws + LAT * DIN;
    float* rb2s = rb1s + HID;
    float* skbs = rb2s + DIN;
    float* txbs = skbs + DIN;

    int tid = threadIdx.x;
    for (int i = tid; i < HID * HID; i += 256) rw1n[i] = rw1[i];
    for (int i = tid; i < HID * DIN; i += 256) { rw2s[i] = rw2[i]; skws[i] = skw[i]; }
    for (int i = tid; i < LAT * DIN; i += 256) txws[i] = txw[i];
    if (tid < HID) rb1s[tid] = rb1[tid];
    if (tid < DIN) { rb2s[tid] = rb2[tid]; skbs[tid] = skb[tid]; txbs[tid] = txb[tid]; }
    __syncthreads();

    size_t r = (size_t)blockIdx.x * 256 + tid;
    float ts = tscale[0];

    const float* hgp = g_hg + r * HID;

    float hg[HID], g[HID];
    {
        const float4* h4 = (const float4*)hgp;
        #pragma unroll
        for (int i = 0; i < 32; i++) {
            float4 t = h4[i];
            hg[4*i] = t.x; hg[4*i+1] = t.y; hg[4*i+2] = t.z; hg[4*i+3] = t.w;
            g[4*i]   = gelu_ref(t.x); g[4*i+1] = gelu_ref(t.y);
            g[4*i+2] = gelu_ref(t.z); g[4*i+3] = gelu_ref(t.w);
        }
    }

    float o[DIN], sk[DIN];
    #pragma unroll
    for (int l = 0; l < DIN; l++) { o[l] = 0.f; sk[l] = 0.f; }

    for (int j = 0; j < HID; j += 4) {
        float a0 = 0.f, a1 = 0.f, a2 = 0.f, a3 = 0.f;
        #pragma unroll
        for (int i = 0; i < HID; i++) {
            float gi = g[i];
            float4 w = *(const float4*)(rw1n + i * HID + j);
            a0 = fmaf(gi, w.x, a0); a1 = fmaf(gi, w.y, a1);
            a2 = fmaf(gi, w.z, a2); a3 = fmaf(gi, w.w, a3);
        }
        float u0 = gelu_ref(__fadd_rn(a0, rb1s[j+0]));
        float u1 = gelu_ref(__fadd_rn(a1, rb1s[j+1]));
        float u2 = gelu_ref(__fadd_rn(a2, rb1s[j+2]));
        float u3 = gelu_ref(__fadd_rn(a3, rb1s[j+3]));
        const float4* r0 = (const float4*)(rw2s + (j+0) * DIN);
        const float4* r1 = (const float4*)(rw2s + (j+1) * DIN);
        const float4* r2 = (const float4*)(rw2s + (j+2) * DIN);
        const float4* r3 = (const float4*)(rw2s + (j+3) * DIN);
        #pragma unroll
        for (int l4 = 0; l4 < 8; l4++) {
            float4 w = r0[l4];
            o[4*l4]   = fmaf(u0, w.x, o[4*l4]);   o[4*l4+1] = fmaf(u0, w.y, o[4*l4+1]);
            o[4*l4+2] = fmaf(u0, w.z, o[4*l4+2]); o[4*l4+3] = fmaf(u0, w.w, o[4*l4+3]);
        }
        #pragma unroll
        for (int l4 = 0; l4 < 8; l4++) {
            float4 w = r1[l4];
            o[4*l4]   = fmaf(u1, w.x, o[4*l4]);   o[4*l4+1] = fmaf(u1, w.y, o[4*l4+1]);
            o[4*l4+2] = fmaf(u1, w.z, o[4*l4+2]); o[4*l4+3] = fmaf(u1, w.w, o[4*l4+3]);
        }
        #pragma unroll
        for (int l4 = 0; l4 < 8; l4++) {
            float4 w = r2[l4];
            o[4*l4]   = fmaf(u2, w.x, o[4*l4]);   o[4*l4+1] = fmaf(u2, w.y, o[4*l4+1]);
            o[4*l4+2] = fmaf(u2, w.z, o[4*l4+2]); o[4*l4+3] = fmaf(u2, w.w, o[4*l4+3]);
        }
        #pragma unroll
        for (int l4 = 0; l4 < 8; l4++) {
            float4 w = r3[l4];
            o[4*l4]   = fmaf(u3, w.x, o[4*l4]);   o[4*l4+1] = fmaf(u3, w.y, o[4*l4+1]);
            o[4*l4+2] = fmaf(u3, w.z, o[4*l4+2]); o[4*l4+3] = fmaf(u3, w.w, o[4*l4+3]);
        }
        const float4* s0 = (const float4*)(skws + (j+0) * DIN);
        const float4* s1 = (const float4*)(skws + (j+1) * DIN);
        const float4* s2 = (const float4*)(skws + (j+2) * DIN);
        const float4* s3 = (const float4*)(skws + (j+3) * DIN);
        float h0 = hg[j+0], h1v = hg[j+1], h2v = hg[j+2], h3v = hg[j+3];
        #pragma unroll
        for (int l4 = 0; l4 < 8; l4++) {
            float4 w = s0[l4];
            sk[4*l4]   = fmaf(h0, w.x, sk[4*l4]);   sk[4*l4+1] = fmaf(h0, w.y, sk[4*l4+1]);
            sk[4*l4+2] = fmaf(h0, w.z, sk[4*l4+2]); sk[4*l4+3] = fmaf(h0, w.w, sk[4*l4+3]);
        }
        #pragma unroll
        for (int l4 = 0; l4 < 8; l4++) {
            float4 w = s1[l4];
            sk[4*l4]   = fmaf(h1v, w.x, sk[4*l4]);   sk[4*l4+1] = fmaf(h1v, w.y, sk[4*l4+1]);
            sk[4*l4+2] = fmaf(h1v, w.z, sk[4*l4+2]); sk[4*l4+3] = fmaf(h1v, w.w, sk[4*l4+3]);
        }
        #pragma unroll
        for (int l4 = 0; l4 < 8; l4++) {
            float4 w = s2[l4];
            sk[4*l4]   = fmaf(h2v, w.x, sk[4*l4]);   sk[4*l4+1] = fmaf(h2v, w.y, sk[4*l4+1]);
            sk[4*l4+2] = fmaf(h2v, w.z, sk[4*l4+2]); sk[4*l4+3] = fmaf(h2v, w.w, sk[4*l4+3]);
        }
        #pragma unroll
        for (int l4 = 0; l4 < 8; l4++) {
            float4 w = s3[l4];
            sk[4*l4]   = fmaf(h3v, w.x, sk[4*l4]);   sk[4*l4+1] = fmaf(h3v, w.y, sk[4*l4+1]);
            sk[4*l4+2] = fmaf(h3v, w.z, sk[4*l4+2]); sk[4*l4+3] = fmaf(h3v, w.w, sk[4*l4+3]);
        }
    }

    float zt[LAT];
    {
        const float4* z4 = (const float4*)(g_zt + r * LAT);
        #pragma unroll
        for (int i = 0; i < 8; i++) {
            float4 t = z4[i];
            zt[4*i] = t.x; zt[4*i+1] = t.y; zt[4*i+2] = t.z; zt[4*i+3] = t.w;
        }
    }
    float tx[DIN];
    #pragma unroll
    for (int l = 0; l < DIN; l++) tx[l] = 0.f;
    #pragma unroll
    for (int lp = 0; lp < LAT; lp++) {
        float ztl = zt[lp];
        const float4* t4 = (const float4*)(txws + lp * DIN);
        #pragma unroll
        for (int l4 = 0; l4 < 8; l4++) {
            float4 w = t4[l4];
            tx[4*l4]   = fmaf(ztl, w.x, tx[4*l4]);   tx[4*l4+1] = fmaf(ztl, w.y, tx[4*l4+1]);
            tx[4*l4+2] = fmaf(ztl, w.z, tx[4*l4+2]); tx[4*l4+3] = fmaf(ztl, w.w, tx[4*l4+3]);
        }
    }

    float4* xo = (float4*)(out + O_XHAT + r * DIN);
    #pragma unroll
    for (int l4 = 0; l4 < 8; l4++) {
        float4 t;
        #pragma unroll
        for (int q = 0; q < 4; q++) {
            int l = 4*l4 + q;
            float mlp  = __fadd_rn(o[l], rb2s[l]);
            float skp  = __fadd_rn(sk[l], skbs[l]);
            float base = __fadd_rn(mlp, skp);
            float texv = __fmul_rn(ts, __fadd_rn(tx[l], txbs[l]));
            ((float*)&t)[q] = __fadd_rn(base, texv);
        }
        xo[l4] = t;
    }
}

// ---------------- kernel D ----------------
__global__ void kD(float* __restrict__ out, int full) {
    if (full) out[O_VQ] = (float)(1.25 * g_vq / ((double)Bsz * (double)LAT));
}

// ---------------- launch ----------------
extern "C" void kernel_launch(void* const* d_in, const int* in_sizes, int n_in,
                              void* d_out, int out_size) {
    const float* x    = (const float*)d_in[0];
    const float* fw1  = (const float*)d_in[1];
    const float* fb1  = (const float*)d_in[2];
    const float* fw2  = (const float*)d_in[3];
    const float* fb2  = (const float*)d_in[4];
    const float* vpw  = (const float*)d_in[5];
    const float* vpb  = (const float*)d_in[6];
    const float* cc   = (const float*)d_in[7];
    const float* cbk  = (const float*)d_in[8];
    const float* sfw1 = (const float*)d_in[9];
    const float* sfb1 = (const float*)d_in[10];
    const float* sfw2 = (const float*)d_in[11];
    const float* sfb2 = (const float*)d_in[12];
    const float* decw = (const float*)d_in[13];
    const float* decb = (const float*)d_in[14];
    const float* lrw  = (const float*)d_in[15];
    const float* lrb  = (const float*)d_in[16];
    const float* txw  = (const float*)d_in[17];
    const float* txb  = (const float*)d_in[18];
    const float* tsc  = (const float*)d_in[19];
    const float* rw1  = (const float*)d_in[20];
    const float* rb1  = (const float*)d_in[21];
    const float* rw2  = (const float*)d_in[22];
    const float* rb2  = (const float*)d_in[23];
    const float* skw  = (const float*)d_in[24];
    const float* skb  = (const float*)d_in[25];

    float* out = (float*)d_out;
    int full = (out_size >= O_TOTAL) ? 1 : 0;

    const int SMEM_A = (DIN*HID + HID*HID + HID*LAT + HID + HID + LAT + HID*256) * 4;
    const int SMEM_V = (KC*LAT + KC + NC*LAT + LAT*NC) * 4;
    const int SMEM_W = (NC*HID*LAT + NC*HID + LAT*MID + MID*LAT + LAT*NC + MID + LAT + NC) * 4;
    const int SMEM_C = (HID*HID + HID*DIN + HID*DIN + LAT*DIN + HID + DIN + DIN + DIN) * 4;

    cudaFuncSetAttribute(kA, cudaFuncAttributeMaxDynamicSharedMemorySize, SMEM_A);
    cudaFuncSetAttribute(kV, cudaFuncAttributeMaxDynamicSharedMemorySize, SMEM_V);
    cudaFuncSetAttribute(kW, cudaFuncAttributeMaxDynamicSharedMemorySize, SMEM_W);
    cudaFuncSetAttribute(kC, cudaFuncAttributeMaxDynamicSharedMemorySize, SMEM_C);

    kPrep<<<16, 256>>>(cbk);
    kA<<<Bsz / 256, 256, SMEM_A>>>(x, fw1, fb1, fw2, fb2, vpw, vpb);
    kV<<<Bsz / 256, 256, SMEM_V>>>(cc, cbk, out, full);
    kW<<<Bsz / 256, 256, SMEM_W>>>(cbk, sfw1, sfb1, sfw2, sfb2, decw, decb, lrw, lrb, out, full);
    kC<<<Bsz / 256, 256, SMEM_C>>>(rw1, rb1, rw2, rb2, skw, skb, txw, txb, tsc, out);
    kD<<<1, 1>>>(out, full);
}

// round 10
// speedup vs baseline: 1.3330x; 1.0181x over previous
#include <cuda_runtime.h>

#define Bsz 65536
#define DIN 32
#define HID 128
#define LAT 32
#define NC  8
#define KC  512
#define MID 16

// ---------------- scratch (no allocations allowed) ----------------
static __device__ float  g_v[Bsz * LAT];     // v then v_local
static __device__ float  g_cb[Bsz * LAT];
static __device__ float  g_enc[Bsz * NC];
static __device__ int    g_bidx[Bsz * NC];
static __device__ float  g_hg[Bsz * HID];
static __device__ float  g_zt[Bsz * LAT];
static __device__ float  g_cbn[NC * KC];
static __device__ double g_vq;

// ---------------- output layout (concatenated tuple, f32) ----------------
#define O_XHAT 0
#define O_VQ   (Bsz * DIN)
#define O_ENC  (O_VQ + 1)
#define O_DEC  (O_ENC + Bsz * NC)
#define O_K    (O_DEC + Bsz * NC)
#define O_ZGEO (O_K + Bsz)
#define O_ZN   (O_ZGEO + Bsz * LAT)
#define O_CBAR (O_ZN + Bsz * LAT)
#define O_TOTAL (O_CBAR + Bsz * LAT)

__device__ __forceinline__ float gelu_ref(float x) {
    float u = __fdiv_rn(x, 1.4142135623730951f);
    float t = erff(u);
    return __fmul_rn(__fmul_rn(0.5f, x), __fadd_rn(1.0f, t));
}

// ---------------- prep ----------------
__global__ void kPrep(const float* __restrict__ cbk) {
    int idx = blockIdx.x * blockDim.x + threadIdx.x;
    if (idx == 0) g_vq = 0.0;
    if (idx < NC * KC) {
        const float* row = cbk + (size_t)idx * LAT;
        float s = 0.f;
        #pragma unroll
        for (int l = 0; l < LAT; l++) s = __fadd_rn(s, __fmul_rn(row[l], row[l]));
        g_cbn[idx] = s;
    }
}

// ---------------- kernel A: x -> features -> v (unchanged) ----------------
__global__ void __launch_bounds__(256) kA(
    const float* __restrict__ x,  const float* __restrict__ w1, const float* __restrict__ b1,
    const float* __restrict__ w2, const float* __restrict__ b2,
    const float* __restrict__ vp, const float* __restrict__ vpb)
{
    extern __shared__ float sm[];
    float* w1n  = sm;
    float* w2n  = w1n + DIN * HID;
    float* vps  = w2n + HID * HID;
    float* b1s  = vps + HID * LAT;
    float* b2s  = b1s + HID;
    float* vpbs = b2s + HID;
    float* h1s  = vpbs + LAT;

    int tid = threadIdx.x;
    for (int i = tid; i < DIN * HID; i += 256) w1n[i] = w1[i];
    for (int i = tid; i < HID * HID; i += 256) w2n[i] = w2[i];
    for (int i = tid; i < HID * LAT; i += 256) vps[i] = vp[i];
    if (tid < HID) { b1s[tid] = b1[tid]; b2s[tid] = b2[tid]; }
    if (tid < LAT) vpbs[tid] = vpb[tid];
    __syncthreads();

    size_t r = (size_t)blockIdx.x * 256 + tid;

    float xr[DIN];
    {
        const float4* xp = (const float4*)(x + r * DIN);
        #pragma unroll
        for (int i = 0; i < 8; i++) {
            float4 t = xp[i];
            xr[4*i] = t.x; xr[4*i+1] = t.y; xr[4*i+2] = t.z; xr[4*i+3] = t.w;
        }
    }

    for (int j = 0; j < HID; j += 4) {
        float a0 = 0.f, a1 = 0.f, a2 = 0.f, a3 = 0.f;
        #pragma unroll
        for (int i = 0; i < DIN; i++) {
            float xi = xr[i];
            float4 w = *(const float4*)(w1n + i * HID + j);
            a0 = fmaf(xi, w.x, a0); a1 = fmaf(xi, w.y, a1);
            a2 = fmaf(xi, w.z, a2); a3 = fmaf(xi, w.w, a3);
        }
        h1s[(j+0) * 256 + tid] = gelu_ref(__fadd_rn(a0, b1s[j+0]));
        h1s[(j+1) * 256 + tid] = gelu_ref(__fadd_rn(a1, b1s[j+1]));
        h1s[(j+2) * 256 + tid] = gelu_ref(__fadd_rn(a2, b1s[j+2]));
        h1s[(j+3) * 256 + tid] = gelu_ref(__fadd_rn(a3, b1s[j+3]));
    }

    float h1[HID];
    #pragma unroll
    for (int i = 0; i < HID; i++) h1[i] = h1s[i * 256 + tid];

    float vv[LAT];
    #pragma unroll
    for (int l = 0; l < LAT; l++) vv[l] = 0.f;
    for (int j = 0; j < HID; j += 4) {
        float a0 = 0.f, a1 = 0.f, a2 = 0.f, a3 = 0.f;
        #pragma unroll
        for (int i = 0; i < HID; i++) {
            float hi = h1[i];
            float4 w = *(const float4*)(w2n + i * HID + j);
            a0 = fmaf(hi, w.x, a0); a1 = fmaf(hi, w.y, a1);
            a2 = fmaf(hi, w.z, a2); a3 = fmaf(hi, w.w, a3);
        }
        float u0 = gelu_ref(__fadd_rn(a0, b2s[j+0]));
        float u1 = gelu_ref(__fadd_rn(a1, b2s[j+1]));
        float u2 = gelu_ref(__fadd_rn(a2, b2s[j+2]));
        float u3 = gelu_ref(__fadd_rn(a3, b2s[j+3]));
        const float4* vr0 = (const float4*)(vps + (j+0) * LAT);
        const float4* vr1 = (const float4*)(vps + (j+1) * LAT);
        const float4* vr2 = (const float4*)(vps + (j+2) * LAT);
        const float4* vr3 = (const float4*)(vps + (j+3) * LAT);
        #pragma unroll
        for (int l4 = 0; l4 < 8; l4++) {
            float4 w = vr0[l4];
            vv[4*l4]   = fmaf(u0, w.x, vv[4*l4]);   vv[4*l4+1] = fmaf(u0, w.y, vv[4*l4+1]);
            vv[4*l4+2] = fmaf(u0, w.z, vv[4*l4+2]); vv[4*l4+3] = fmaf(u0, w.w, vv[4*l4+3]);
        }
        #pragma unroll
        for (int l4 = 0; l4 < 8; l4++) {
            float4 w = vr1[l4];
            vv[4*l4]   = fmaf(u1, w.x, vv[4*l4]);   vv[4*l4+1] = fmaf(u1, w.y, vv[4*l4+1]);
            vv[4*l4+2] = fmaf(u1, w.z, vv[4*l4+2]); vv[4*l4+3] = fmaf(u1, w.w, vv[4*l4+3]);
        }
        #pragma unroll
        for (int l4 = 0; l4 < 8; l4++) {
            float4 w = vr2[l4];
            vv[4*l4]   = fmaf(u2, w.x, vv[4*l4]);   vv[4*l4+1] = fmaf(u2, w.y, vv[4*l4+1]);
            vv[4*l4+2] = fmaf(u2, w.z, vv[4*l4+2]); vv[4*l4+3] = fmaf(u2, w.w, vv[4*l4+3]);
        }
        #pragma unroll
        for (int l4 = 0; l4 < 8; l4++) {
            float4 w = vr3[l4];
            vv[4*l4]   = fmaf(u3, w.x, vv[4*l4]);   vv[4*l4+1] = fmaf(u3, w.y, vv[4*l4+1]);
            vv[4*l4+2] = fmaf(u3, w.z, vv[4*l4+2]); vv[4*l4+3] = fmaf(u3, w.w, vv[4*l4+3]);
        }
    }
    float4* vo = (float4*)(g_v + r * LAT);
    #pragma unroll
    for (int l4 = 0; l4 < 8; l4++) {
        float4 t;
        t.x = __fadd_rn(vv[4*l4],   vpbs[4*l4]);
        t.y = __fadd_rn(vv[4*l4+1], vpbs[4*l4+1]);
        t.z = __fadd_rn(vv[4*l4+2], vpbs[4*l4+2]);
        t.w = __fadd_rn(vv[4*l4+3], vpbs[4*l4+3]);
        vo[l4] = t;
    }
}

// ---------------- kernel V: softmax/K + c_bar/v_local + VQ argmin ----------------
__global__ void __launch_bounds__(256, 2) kV(
    const float* __restrict__ cc, const float* __restrict__ cbk,
    float* __restrict__ out, int full)
{
    extern __shared__ float sm[];
    float* cbs  = sm;               // KC*LAT
    float* cbns = cbs + KC * LAT;   // KC
    float* ccs  = cbns + KC;        // [c][l]
    float* cct  = ccs + NC * LAT;   // [l][c]

    int tid = threadIdx.x;
    for (int i = tid; i < NC * LAT; i += 256) {
        float t = cc[i]; ccs[i] = t;
        int c = i / LAT, l = i % LAT;
        cct[l * NC + c] = t;
    }

    size_t r = (size_t)blockIdx.x * 256 + tid;
    float v[LAT];
    {
        const float4* vp4 = (const float4*)(g_v + r * LAT);
        #pragma unroll
        for (int i = 0; i < 8; i++) {
            float4 t = vp4[i];
            v[4*i] = t.x; v[4*i+1] = t.y; v[4*i+2] = t.z; v[4*i+3] = t.w;
        }
    }
    __syncthreads();

    // ---- enc softmax + K: BYTE-IDENTICAL to the passing version ----
    float enc[NC]; int K;
    {
        float sc[NC];
        #pragma unroll
        for (int c = 0; c < NC; c++) sc[c] = 0.f;
        #pragma unroll
        for (int l = 0; l < LAT; l++) {
            float vl = v[l];
            float4 wa = ((const float4*)(cct + l * NC))[0];
            float4 wb = ((const float4*)(cct + l * NC))[1];
            sc[0] = fmaf(vl, wa.x, sc[0]); sc[1] = fmaf(vl, wa.y, sc[1]);
            sc[2] = fmaf(vl, wa.z, sc[2]); sc[3] = fmaf(vl, wa.w, sc[3]);
            sc[4] = fmaf(vl, wb.x, sc[4]); sc[5] = fmaf(vl, wb.y, sc[5]);
            sc[6] = fmaf(vl, wb.z, sc[6]); sc[7] = fmaf(vl, wb.w, sc[7]);
        }
        #pragma unroll
        for (int c = 0; c < NC; c++) sc[c] = __fdiv_rn(sc[c], 5.656854249492381f);
        float m = sc[0];
        #pragma unroll
        for (int c = 1; c < NC; c++) m = fmaxf(m, sc[c]);
        float e[NC];
        #pragma unroll
        for (int c = 0; c < NC; c++)
            e[c] = (float)exp((double)__fsub_rn(sc[c], m));  // correctly-rounded fp32 exp
        float s01 = __fadd_rn(e[0], e[1]);
        float s23 = __fadd_rn(e[2], e[3]);
        float s45 = __fadd_rn(e[4], e[5]);
        float s67 = __fadd_rn(e[6], e[7]);
        float s = __fadd_rn(__fadd_rn(s01, s23), __fadd_rn(s45, s67));
        #pragma unroll
        for (int c = 0; c < NC; c++) enc[c] = __fdiv_rn(e[c], s);
        float bm = e[0]; K = 0;
        #pragma unroll
        for (int c = 1; c < NC; c++) if (e[c] > bm) { bm = e[c]; K = c; }
    }

    // c_bar / v_local
    float cb[LAT];
    #pragma unroll
    for (int l = 0; l < LAT; l++) cb[l] = 0.f;
    #pragma unroll
    for (int c = 0; c < NC; c++) {
        float e = enc[c];
        #pragma unroll
        for (int l = 0; l < LAT; l++) cb[l] = fmaf(e, ccs[c * LAT + l], cb[l]);
    }
    #pragma unroll
    for (int l = 0; l < LAT; l++) v[l] = __fsub_rn(v[l], cb[l]);   // v_local

    {
        float4* vo = (float4*)(g_v + r * LAT);
        float4* co = (float4*)(g_cb + r * LAT);
        #pragma unroll
        for (int l4 = 0; l4 < 8; l4++) {
            float4 tv, tc;
            tv.x = v[4*l4];  tv.y = v[4*l4+1];  tv.z = v[4*l4+2];  tv.w = v[4*l4+3];
            tc.x = cb[4*l4]; tc.y = cb[4*l4+1]; tc.z = cb[4*l4+2]; tc.w = cb[4*l4+3];
            vo[l4] = tv; co[l4] = tc;
        }
        #pragma unroll
        for (int c = 0; c < NC; c++) g_enc[r * NC + c] = enc[c];
        if (full) {
            #pragma unroll
            for (int c = 0; c < NC; c++) out[O_ENC + r * NC + c] = enc[c];
            out[O_K + r] = (float)K;
            #pragma unroll
            for (int l = 0; l < LAT; l++) out[O_CBAR + r * LAT + l] = cb[l];
        }
    }

    float vn = 0.f;
    #pragma unroll
    for (int l = 0; l < LAT; l++) vn = __fadd_rn(vn, __fmul_rn(v[l], v[l]));

    // VQ argmin per chart (identical arithmetic)
    #pragma unroll 1
    for (int c = 0; c < NC; c++) {
        __syncthreads();
        const float* src = cbk + (size_t)c * KC * LAT;
        for (int i = tid; i < KC * LAT; i += 256) cbs[i] = src[i];
        for (int i = tid; i < KC; i += 256) cbns[i] = g_cbn[c * KC + i];
        __syncthreads();
        float best = 3.4e38f; int bi = 0;
        for (int k = 0; k < KC; k += 4) {
            float e0 = 0.f, e1 = 0.f, e2 = 0.f, e3 = 0.f;
            const float4* r0 = (const float4*)(cbs + (k+0) * LAT);
            const float4* r1 = (const float4*)(cbs + (k+1) * LAT);
            const float4* r2 = (const float4*)(cbs + (k+2) * LAT);
            const float4* r3 = (const float4*)(cbs + (k+3) * LAT);
            #pragma unroll
            for (int i = 0; i < 8; i++) {
                float4 w0 = r0[i], w1 = r1[i], w2 = r2[i], w3 = r3[i];
                e0 = fmaf(v[4*i], w0.x, e0); e0 = fmaf(v[4*i+1], w0.y, e0);
                e0 = fmaf(v[4*i+2], w0.z, e0); e0 = fmaf(v[4*i+3], w0.w, e0);
                e1 = fmaf(v[4*i], w1.x, e1); e1 = fmaf(v[4*i+1], w1.y, e1);
                e1 = fmaf(v[4*i+2], w1.z, e1); e1 = fmaf(v[4*i+3], w1.w, e1);
                e2 = fmaf(v[4*i], w2.x, e2); e2 = fmaf(v[4*i+1], w2.y, e2);
                e2 = fmaf(v[4*i+2], w2.z, e2); e2 = fmaf(v[4*i+3], w2.w, e2);
                e3 = fmaf(v[4*i], w3.x, e3); e3 = fmaf(v[4*i+1], w3.y, e3);
                e3 = fmaf(v[4*i+2], w3.z, e3); e3 = fmaf(v[4*i+3], w3.w, e3);
            }
            float d0 = __fadd_rn(__fsub_rn(vn, __fmul_rn(2.0f, e0)), cbns[k+0]);
            float d1 = __fadd_rn(__fsub_rn(vn, __fmul_rn(2.0f, e1)), cbns[k+1]);
            float d2 = __fadd_rn(__fsub_rn(vn, __fmul_rn(2.0f, e2)), cbns[k+2]);
            float d3 = __fadd_rn(__fsub_rn(vn, __fmul_rn(2.0f, e3)), cbns[k+3]);
            if (d0 < best) { best = d0; bi = k+0; }
            if (d1 < best) { best = d1; bi = k+1; }
            if (d2 < best) { best = d2; bi = k+2; }
            if (d3 < best) { best = d3; bi = k+3; }
        }
        g_bidx[r * NC + c] = bi;
    }
}

// ---------------- kernel W: gather + SF MLP + z outputs + dec softmax + h_global ----------------
// __launch_bounds__(256, 1): smem (137 KB) already forces 1 block/SM; declare it so
// ptxas grants the full 255-register budget and stops spilling the ~170-float live set.
__global__ void __launch_bounds__(256, 1) kW(
    const float* __restrict__ cbk,
    const float* __restrict__ sfw1, const float* __restrict__ sfb1,
    const float* __restrict__ sfw2, const float* __restrict__ sfb2,
    const float* __restrict__ decw, const float* __restrict__ decb,
    const float* __restrict__ lrw,  const float* __restrict__ lrb,
    float* __restrict__ out, int full)
{
    extern __shared__ float sm[];
    float* decws = sm;                       // 32768 f
    float* decbs = decws + NC * HID * LAT;   // 1024 f
    float* sfw1t = decbs + NC * HID;         // 512 [MID][LAT]
    float* sfw2s = sfw1t + LAT * MID;        // 512 [MID][LAT]
    float* lrws  = sfw2s + MID * LAT;        // 256 [l][c]
    float* sfb1s = lrws + LAT * NC;          // 16
    float* sfb2s = sfb1s + MID;              // 32
    float* lrbs  = sfb2s + LAT;              // 8

    __shared__ float red[256];

    int tid = threadIdx.x;
    for (int i = tid; i < NC * HID * LAT; i += 256) decws[i] = decw[i];
    for (int i = tid; i < NC * HID; i += 256) decbs[i] = decb[i];
    for (int i = tid; i < LAT * MID; i += 256) { int l = i / MID, m = i % MID; sfw1t[m * LAT + l] = sfw1[i]; }
    for (int i = tid; i < MID * LAT; i += 256) sfw2s[i] = sfw2[i];
    for (int i = tid; i < LAT * NC; i += 256) lrws[i] = lrw[i];
    if (tid < MID) sfb1s[tid] = sfb1[tid];
    if (tid < LAT) sfb2s[tid] = sfb2[tid];
    if (tid < NC)  lrbs[tid] = lrb[tid];
    __syncthreads();

    size_t r = (size_t)blockIdx.x * 256 + tid;

    float v[LAT], enc[NC];
    {
        const float4* vp4 = (const float4*)(g_v + r * LAT);
        #pragma unroll
        for (int i = 0; i < 8; i++) {
            float4 t = vp4[i];
            v[4*i] = t.x; v[4*i+1] = t.y; v[4*i+2] = t.z; v[4*i+3] = t.w;
        }
        #pragma unroll
        for (int c = 0; c < NC; c++) enc[c] = g_enc[r * NC + c];
    }

    float zqb[LAT], zn[LAT];
    #pragma unroll
    for (int l = 0; l < LAT; l++) { zqb[l] = 0.f; zn[l] = 0.f; }
    float vqa = 0.f;
    #pragma unroll
    for (int c = 0; c < NC; c++) {
        int bi = g_bidx[r * NC + c];
        float zq[LAT];
        {
            const float4* z4 = (const float4*)(cbk + ((size_t)c * KC + bi) * LAT);
            #pragma unroll
            for (int i = 0; i < 8; i++) {
                float4 t = z4[i];
                zq[4*i] = t.x; zq[4*i+1] = t.y; zq[4*i+2] = t.z; zq[4*i+3] = t.w;
            }
        }
        float e = enc[c];
        #pragma unroll
        for (int l = 0; l < LAT; l++) zqb[l] = fmaf(e, zq[l], zqb[l]);
        float sq = 0.f;
        #pragma unroll
        for (int l = 0; l < LAT; l++) { float d = __fsub_rn(v[l], zq[l]); zq[l] = d; sq = fmaf(d, d, sq); }
        vqa = fmaf(e, sq, vqa);
        // zq now holds delta
        float mv[MID];
        #pragma unroll
        for (int m = 0; m < MID; m++) {
            float a = 0.f;
            const float4* w4 = (const float4*)(sfw1t + m * LAT);
            #pragma unroll
            for (int i = 0; i < 8; i++) {
                float4 w = w4[i];
                a = fmaf(zq[4*i], w.x, a); a = fmaf(zq[4*i+1], w.y, a);
                a = fmaf(zq[4*i+2], w.z, a); a = fmaf(zq[4*i+3], w.w, a);
            }
            mv[m] = gelu_ref(__fadd_rn(a, sfb1s[m]));
        }
        #pragma unroll
        for (int l4 = 0; l4 < 8; l4++) {
            float4 acc = make_float4(0.f, 0.f, 0.f, 0.f);
            #pragma unroll
            for (int m = 0; m < MID; m++) {
                float4 w = ((const float4*)sfw2s)[m * 8 + l4];
                acc.x = fmaf(mv[m], w.x, acc.x); acc.y = fmaf(mv[m], w.y, acc.y);
                acc.z = fmaf(mv[m], w.z, acc.z); acc.w = fmaf(mv[m], w.w, acc.w);
            }
            float4 b = ((const float4*)sfb2s)[l4];
            zn[4*l4]   = fmaf(e, __fadd_rn(acc.x, b.x), zn[4*l4]);
            zn[4*l4+1] = fmaf(e, __fadd_rn(acc.y, b.y), zn[4*l4+1]);
            zn[4*l4+2] = fmaf(e, __fadd_rn(acc.z, b.z), zn[4*l4+2]);
            zn[4*l4+3] = fmaf(e, __fadd_rn(acc.w, b.w), zn[4*l4+3]);
        }
    }

    // z_geo / zg / z_tex
    float zg[LAT];
    #pragma unroll
    for (int l = 0; l < LAT; l++) {
        float cbl = g_cb[r * LAT + l];
        float zgeo = __fadd_rn(__fadd_rn(cbl, zqb[l]), zn[l]);
        zg[l] = tanhf(zgeo);
        float ztv = tanhf(__fsub_rn(__fsub_rn(v[l], zqb[l]), zn[l]));
        g_zt[r * LAT + l] = ztv;
        if (full) {
            out[O_ZGEO + r * LAT + l] = zgeo;
            out[O_ZN   + r * LAT + l] = zn[l];
        }
    }

    // dec softmax (identical arithmetic)
    float dec[NC];
    {
        float lg[NC];
        #pragma unroll
        for (int c = 0; c < NC; c++) lg[c] = 0.f;
        #pragma unroll
        for (int l = 0; l < LAT; l++) {
            float zl = zg[l];
            #pragma unroll
            for (int c = 0; c < NC; c++) lg[c] = fmaf(zl, lrws[l * NC + c], lg[c]);
        }
        #pragma unroll
        for (int c = 0; c < NC; c++) lg[c] = __fadd_rn(lg[c], lrbs[c]);
        float m = lg[0];
        #pragma unroll
        for (int c = 1; c < NC; c++) m = fmaxf(m, lg[c]);
        float s = 0.f;
        #pragma unroll
        for (int c = 0; c < NC; c++) { dec[c] = expf(__fsub_rn(lg[c], m)); s = __fadd_rn(s, dec[c]); }
        #pragma unroll
        for (int c = 0; c < NC; c++) dec[c] = __fdiv_rn(dec[c], s);
    }
    if (full) {
        #pragma unroll
        for (int c = 0; c < NC; c++) out[O_DEC + r * NC + c] = dec[c];
    }

    // h_global: per (c,h): seq-fma dot over l, +decb after; weighted sum over c
    for (int h = 0; h < HID; h++) {
        float acc = 0.f;
        #pragma unroll
        for (int c = 0; c < NC; c++) {
            float a = 0.f;
            const float4* w4 = (const float4*)(decws + (c * HID + h) * LAT);
            #pragma unroll
            for (int i = 0; i < 8; i++) {
                float4 w = w4[i];
                a = fmaf(zg[4*i], w.x, a); a = fmaf(zg[4*i+1], w.y, a);
                a = fmaf(zg[4*i+2], w.z, a); a = fmaf(zg[4*i+3], w.w, a);
            }
            acc = __fadd_rn(acc, __fmul_rn(dec[c], __fadd_rn(a, decbs[c * HID + h])));
        }
        g_hg[r * HID + h] = acc;
    }

    // vq partial reduce
    red[tid] = vqa;
    __syncthreads();
    for (int s = 128; s > 0; s >>= 1) {
        if (tid < s) red[tid] += red[tid + s];
        __syncthreads();
    }
    if (tid == 0) atomicAdd(&g_vq, (double)red[0]);
}

// ---------------- kernel C: h_global -> x_hat (unchanged) ----------------
__global__ void __launch_bounds__(256) kC(
    const float* __restrict__ rw1, const float* __restrict__ rb1,
    const float* __restrict__ rw2, const float* __restrict__ rb2,
    const float* __restrict__ skw, const float* __restrict__ skb,
    const float* __restrict__ txw, const float* __restrict__ txb,
    const float* __restrict__ tscale, float* __restrict__ out)
{
    extern __shared__ float sm[];
    float* rw1n = sm;
    float* rw2s = rw1n + HID * HID;
    float* skws = rw2s + HID * DIN;
    float* txws = skws + HID * DIN;
    float* rb1s = txws + LAT * DIN;
    float* rb2s = rb1s + HID;
    float* skbs = rb2s + DIN;
    float* txbs = skbs + DIN;

    int tid = threadIdx.x;
    for (int i = tid; i < HID * HID; i += 256) rw1n[i] = rw1[i];
    for (int i = tid; i < HID * DIN; i += 256) { rw2s[i] = rw2[i]; skws[i] = skw[i]; }
    for (int i = tid; i < LAT * DIN; i += 256) txws[i] = txw[i];
    if (tid < HID) rb1s[tid] = rb1[tid];
    if (tid < DIN) { rb2s[tid] = rb2[tid]; skbs[tid] = skb[tid]; txbs[tid] = txb[tid]; }
    __syncthreads();

    size_t r = (size_t)blockIdx.x * 256 + tid;
    float ts = tscale[0];

    const float* hgp = g_hg + r * HID;

    float hg[HID], g[HID];
    {
        const float4* h4 = (const float4*)hgp;
        #pragma unroll
        for (int i = 0; i < 32; i++) {
            float4 t = h4[i];
            hg[4*i] = t.x; hg[4*i+1] = t.y; hg[4*i+2] = t.z; hg[4*i+3] = t.w;
            g[4*i]   = gelu_ref(t.x); g[4*i+1] = gelu_ref(t.y);
            g[4*i+2] = gelu_ref(t.z); g[4*i+3] = gelu_ref(t.w);
        }
    }

    float o[DIN], sk[DIN];
    #pragma unroll
    for (int l = 0; l < DIN; l++) { o[l] = 0.f; sk[l] = 0.f; }

    for (int j = 0; j < HID; j += 4) {
        float a0 = 0.f, a1 = 0.f, a2 = 0.f, a3 = 0.f;
        #pragma unroll
        for (int i = 0; i < HID; i++) {
            float gi = g[i];
            float4 w = *(const float4*)(rw1n + i * HID + j);
            a0 = fmaf(gi, w.x, a0); a1 = fmaf(gi, w.y, a1);
            a2 = fmaf(gi, w.z, a2); a3 = fmaf(gi, w.w, a3);
        }
        float u0 = gelu_ref(__fadd_rn(a0, rb1s[j+0]));
        float u1 = gelu_ref(__fadd_rn(a1, rb1s[j+1]));
        float u2 = gelu_ref(__fadd_rn(a2, rb1s[j+2]));
        float u3 = gelu_ref(__fadd_rn(a3, rb1s[j+3]));
        const float4* r0 = (const float4*)(rw2s + (j+0) * DIN);
        const float4* r1 = (const float4*)(rw2s + (j+1) * DIN);
        const float4* r2 = (const float4*)(rw2s + (j+2) * DIN);
        const float4* r3 = (const float4*)(rw2s + (j+3) * DIN);
        #pragma unroll
        for (int l4 = 0; l4 < 8; l4++) {
            float4 w = r0[l4];
            o[4*l4]   = fmaf(u0, w.x, o[4*l4]);   o[4*l4+1] = fmaf(u0, w.y, o[4*l4+1]);
            o[4*l4+2] = fmaf(u0, w.z, o[4*l4+2]); o[4*l4+3] = fmaf(u0, w.w, o[4*l4+3]);
        }
        #pragma unroll
        for (int l4 = 0; l4 < 8; l4++) {
            float4 w = r1[l4];
            o[4*l4]   = fmaf(u1, w.x, o[4*l4]);   o[4*l4+1] = fmaf(u1, w.y, o[4*l4+1]);
            o[4*l4+2] = fmaf(u1, w.z, o[4*l4+2]); o[4*l4+3] = fmaf(u1, w.w, o[4*l4+3]);
        }
        #pragma unroll
        for (int l4 = 0; l4 < 8; l4++) {
            float4 w = r2[l4];
            o[4*l4]   = fmaf(u2, w.x, o[4*l4]);   o[4*l4+1] = fmaf(u2, w.y, o[4*l4+1]);
            o[4*l4+2] = fmaf(u2, w.z, o[4*l4+2]); o[4*l4+3] = fmaf(u2, w.w, o[4*l4+3]);
        }
        #pragma unroll
        for (int l4 = 0; l4 < 8; l4++) {
            float4 w = r3[l4];
            o[4*l4]   = fmaf(u3, w.x, o[4*l4]);   o[4*l4+1] = fmaf(u3, w.y, o[4*l4+1]);
            o[4*l4+2] = fmaf(u3, w.z, o[4*l4+2]); o[4*l4+3] = fmaf(u3, w.w, o[4*l4+3]);
        }
        const float4* s0 = (const float4*)(skws + (j+0) * DIN);
        const float4* s1 = (const float4*)(skws + (j+1) * DIN);
        const float4* s2 = (const float4*)(skws + (j+2) * DIN);
        const float4* s3 = (const float4*)(skws + (j+3) * DIN);
        float h0 = hg[j+0], h1v = hg[j+1], h2v = hg[j+2], h3v = hg[j+3];
        #pragma unroll
        for (int l4 = 0; l4 < 8; l4++) {
            float4 w = s0[l4];
            sk[4*l4]   = fmaf(h0, w.x, sk[4*l4]);   sk[4*l4+1] = fmaf(h0, w.y, sk[4*l4+1]);
            sk[4*l4+2] = fmaf(h0, w.z, sk[4*l4+2]); sk[4*l4+3] = fmaf(h0, w.w, sk[4*l4+3]);
        }
        #pragma unroll
        for (int l4 = 0; l4 < 8; l4++) {
            float4 w = s1[l4];
            sk[4*l4]   = fmaf(h1v, w.x, sk[4*l4]);   sk[4*l4+1] = fmaf(h1v, w.y, sk[4*l4+1]);
            sk[4*l4+2] = fmaf(h1v, w.z, sk[4*l4+2]); sk[4*l4+3] = fmaf(h1v, w.w, sk[4*l4+3]);
        }
        #pragma unroll
        for (int l4 = 0; l4 < 8; l4++) {
            float4 w = s2[l4];
            sk[4*l4]   = fmaf(h2v, w.x, sk[4*l4]);   sk[4*l4+1] = fmaf(h2v, w.y, sk[4*l4+1]);
            sk[4*l4+2] = fmaf(h2v, w.z, sk[4*l4+2]); sk[4*l4+3] = fmaf(h2v, w.w, sk[4*l4+3]);
        }
        #pragma unroll
        for (int l4 = 0; l4 < 8; l4++) {
            float4 w = s3[l4];
            sk[4*l4]   = fmaf(h3v, w.x, sk[4*l4]);   sk[4*l4+1] = fmaf(h3v, w.y, sk[4*l4+1]);
            sk[4*l4+2] = fmaf(h3v, w.z, sk[4*l4+2]); sk[4*l4+3] = fmaf(h3v, w.w, sk[4*l4+3]);
        }
    }

    float zt[LAT];
    {
        const float4* z4 = (const float4*)(g_zt + r * LAT);
        #pragma unroll
        for (int i = 0; i < 8; i++) {
            float4 t = z4[i];
            zt[4*i] = t.x; zt[4*i+1] = t.y; zt[4*i+2] = t.z; zt[4*i+3] = t.w;
        }
    }
    float tx[DIN];
    #pragma unroll
    for (int l = 0; l < DIN; l++) tx[l] = 0.f;
    #pragma unroll
    for (int lp = 0; lp < LAT; lp++) {
        float ztl = zt[lp];
        const float4* t4 = (const float4*)(txws + lp * DIN);
        #pragma unroll
        for (int l4 = 0; l4 < 8; l4++) {
            float4 w = t4[l4];
            tx[4*l4]   = fmaf(ztl, w.x, tx[4*l4]);   tx[4*l4+1] = fmaf(ztl, w.y, tx[4*l4+1]);
            tx[4*l4+2] = fmaf(ztl, w.z, tx[4*l4+2]); tx[4*l4+3] = fmaf(ztl, w.w, tx[4*l4+3]);
        }
    }

    float4* xo = (float4*)(out + O_XHAT + r * DIN);
    #pragma unroll
    for (int l4 = 0; l4 < 8; l4++) {
        float4 t;
        #pragma unroll
        for (int q = 0; q < 4; q++) {
            int l = 4*l4 + q;
            float mlp  = __fadd_rn(o[l], rb2s[l]);
            float skp  = __fadd_rn(sk[l], skbs[l]);
            float base = __fadd_rn(mlp, skp);
            float texv = __fmul_rn(ts, __fadd_rn(tx[l], txbs[l]));
            ((float*)&t)[q] = __fadd_rn(base, texv);
        }
        xo[l4] = t;
    }
}

// ---------------- kernel D ----------------
__global__ void kD(float* __restrict__ out, int full) {
    if (full) out[O_VQ] = (float)(1.25 * g_vq / ((double)Bsz * (double)LAT));
}

// ---------------- launch ----------------
extern "C" void kernel_launch(void* const* d_in, const int* in_sizes, int n_in,
                              void* d_out, int out_size) {
    const float* x    = (const float*)d_in[0];
    const float* fw1  = (const float*)d_in[1];
    const float* fb1  = (const float*)d_in[2];
    const float* fw2  = (const float*)d_in[3];
    const float* fb2  = (const float*)d_in[4];
    const float* vpw  = (const float*)d_in[5];
    const float* vpb  = (const float*)d_in[6];
    const float* cc   = (const float*)d_in[7];
    const float* cbk  = (const float*)d_in[8];
    const float* sfw1 = (const float*)d_in[9];
    const float* sfb1 = (const float*)d_in[10];
    const float* sfw2 = (const float*)d_in[11];
    const float* sfb2 = (const float*)d_in[12];
    const float* decw = (const float*)d_in[13];
    const float* decb = (const float*)d_in[14];
    const float* lrw  = (const float*)d_in[15];
    const float* lrb  = (const float*)d_in[16];
    const float* txw  = (const float*)d_in[17];
    const float* txb  = (const float*)d_in[18];
    const float* tsc  = (const float*)d_in[19];
    const float* rw1  = (const float*)d_in[20];
    const float* rb1  = (const float*)d_in[21];
    const float* rw2  = (const float*)d_in[22];
    const float* rb2  = (const float*)d_in[23];
    const float* skw  = (const float*)d_in[24];
    const float* skb  = (const float*)d_in[25];

    float* out = (float*)d_out;
    int full = (out_size >= O_TOTAL) ? 1 : 0;

    const int SMEM_A = (DIN*HID + HID*HID + HID*LAT + HID + HID + LAT + HID*256) * 4;
    const int SMEM_V = (KC*LAT + KC + NC*LAT + LAT*NC) * 4;
    const int SMEM_W = (NC*HID*LAT + NC*HID + LAT*MID + MID*LAT + LAT*NC + MID + LAT + NC) * 4;
    const int SMEM_C = (HID*HID + HID*DIN + HID*DIN + LAT*DIN + HID + DIN + DIN + DIN) * 4;

    cudaFuncSetAttribute(kA, cudaFuncAttributeMaxDynamicSharedMemorySize, SMEM_A);
    cudaFuncSetAttribute(kV, cudaFuncAttributeMaxDynamicSharedMemorySize, SMEM_V);
    cudaFuncSetAttribute(kW, cudaFuncAttributeMaxDynamicSharedMemorySize, SMEM_W);
    cudaFuncSetAttribute(kC, cudaFuncAttributeMaxDynamicSharedMemorySize, SMEM_C);

    kPrep<<<16, 256>>>(cbk);
    kA<<<Bsz / 256, 256, SMEM_A>>>(x, fw1, fb1, fw2, fb2, vpw, vpb);
    kV<<<Bsz / 256, 256, SMEM_V>>>(cc, cbk, out, full);
    kW<<<Bsz / 256, 256, SMEM_W>>>(cbk, sfw1, sfb1, sfw2, sfb2, decw, decb, lrw, lrb, out, full);
    kC<<<Bsz / 256, 256, SMEM_C>>>(rw1, rb1, rw2, rb2, skw, skb, txw, txb, tsc, out);
    kD<<<1, 1>>>(out, full);
}

// round 11
// speedup vs baseline: 1.4814x; 1.1113x over previous
#include <cuda_runtime.h>

#define Bsz 65536
#define DIN 32
#define HID 128
#define LAT 32
#define NC  8
#define KC  512
#define MID 16

// ---------------- scratch (no allocations allowed) ----------------
static __device__ float  g_v[Bsz * LAT];     // v then v_local
static __device__ float  g_cb[Bsz * LAT];
static __device__ float  g_enc[Bsz * NC];
static __device__ int    g_bidx[Bsz * NC];
static __device__ float  g_hg[Bsz * HID];
static __device__ float  g_zt[Bsz * LAT];
static __device__ float  g_cbn[NC * KC];
static __device__ double g_vq;

// ---------------- output layout (concatenated tuple, f32) ----------------
#define O_XHAT 0
#define O_VQ   (Bsz * DIN)
#define O_ENC  (O_VQ + 1)
#define O_DEC  (O_ENC + Bsz * NC)
#define O_K    (O_DEC + Bsz * NC)
#define O_ZGEO (O_K + Bsz)
#define O_ZN   (O_ZGEO + Bsz * LAT)
#define O_CBAR (O_ZN + Bsz * LAT)
#define O_TOTAL (O_CBAR + Bsz * LAT)

__device__ __forceinline__ float gelu_ref(float x) {
    float u = __fdiv_rn(x, 1.4142135623730951f);
    float t = erff(u);
    return __fmul_rn(__fmul_rn(0.5f, x), __fadd_rn(1.0f, t));
}

// ---------------- prep ----------------
__global__ void kPrep(const float* __restrict__ cbk) {
    int idx = blockIdx.x * blockDim.x + threadIdx.x;
    if (idx == 0) g_vq = 0.0;
    if (idx < NC * KC) {
        const float* row = cbk + (size_t)idx * LAT;
        float s = 0.f;
        #pragma unroll
        for (int l = 0; l < LAT; l++) s = __fadd_rn(s, __fmul_rn(row[l], row[l]));
        g_cbn[idx] = s;
    }
}

// ---------------- kernel A: x -> features -> v (unchanged) ----------------
__global__ void __launch_bounds__(256) kA(
    const float* __restrict__ x,  const float* __restrict__ w1, const float* __restrict__ b1,
    const float* __restrict__ w2, const float* __restrict__ b2,
    const float* __restrict__ vp, const float* __restrict__ vpb)
{
    extern __shared__ float sm[];
    float* w1n  = sm;
    float* w2n  = w1n + DIN * HID;
    float* vps  = w2n + HID * HID;
    float* b1s  = vps + HID * LAT;
    float* b2s  = b1s + HID;
    float* vpbs = b2s + HID;
    float* h1s  = vpbs + LAT;

    int tid = threadIdx.x;
    for (int i = tid; i < DIN * HID; i += 256) w1n[i] = w1[i];
    for (int i = tid; i < HID * HID; i += 256) w2n[i] = w2[i];
    for (int i = tid; i < HID * LAT; i += 256) vps[i] = vp[i];
    if (tid < HID) { b1s[tid] = b1[tid]; b2s[tid] = b2[tid]; }
    if (tid < LAT) vpbs[tid] = vpb[tid];
    __syncthreads();

    size_t r = (size_t)blockIdx.x * 256 + tid;

    float xr[DIN];
    {
        const float4* xp = (const float4*)(x + r * DIN);
        #pragma unroll
        for (int i = 0; i < 8; i++) {
            float4 t = xp[i];
            xr[4*i] = t.x; xr[4*i+1] = t.y; xr[4*i+2] = t.z; xr[4*i+3] = t.w;
        }
    }

    for (int j = 0; j < HID; j += 4) {
        float a0 = 0.f, a1 = 0.f, a2 = 0.f, a3 = 0.f;
        #pragma unroll
        for (int i = 0; i < DIN; i++) {
            float xi = xr[i];
            float4 w = *(const float4*)(w1n + i * HID + j);
            a0 = fmaf(xi, w.x, a0); a1 = fmaf(xi, w.y, a1);
            a2 = fmaf(xi, w.z, a2); a3 = fmaf(xi, w.w, a3);
        }
        h1s[(j+0) * 256 + tid] = gelu_ref(__fadd_rn(a0, b1s[j+0]));
        h1s[(j+1) * 256 + tid] = gelu_ref(__fadd_rn(a1, b1s[j+1]));
        h1s[(j+2) * 256 + tid] = gelu_ref(__fadd_rn(a2, b1s[j+2]));
        h1s[(j+3) * 256 + tid] = gelu_ref(__fadd_rn(a3, b1s[j+3]));
    }

    float h1[HID];
    #pragma unroll
    for (int i = 0; i < HID; i++) h1[i] = h1s[i * 256 + tid];

    float vv[LAT];
    #pragma unroll
    for (int l = 0; l < LAT; l++) vv[l] = 0.f;
    for (int j = 0; j < HID; j += 4) {
        float a0 = 0.f, a1 = 0.f, a2 = 0.f, a3 = 0.f;
        #pragma unroll
        for (int i = 0; i < HID; i++) {
            float hi = h1[i];
            float4 w = *(const float4*)(w2n + i * HID + j);
            a0 = fmaf(hi, w.x, a0); a1 = fmaf(hi, w.y, a1);
            a2 = fmaf(hi, w.z, a2); a3 = fmaf(hi, w.w, a3);
        }
        float u0 = gelu_ref(__fadd_rn(a0, b2s[j+0]));
        float u1 = gelu_ref(__fadd_rn(a1, b2s[j+1]));
        float u2 = gelu_ref(__fadd_rn(a2, b2s[j+2]));
        float u3 = gelu_ref(__fadd_rn(a3, b2s[j+3]));
        const float4* vr0 = (const float4*)(vps + (j+0) * LAT);
        const float4* vr1 = (const float4*)(vps + (j+1) * LAT);
        const float4* vr2 = (const float4*)(vps + (j+2) * LAT);
        const float4* vr3 = (const float4*)(vps + (j+3) * LAT);
        #pragma unroll
        for (int l4 = 0; l4 < 8; l4++) {
            float4 w = vr0[l4];
            vv[4*l4]   = fmaf(u0, w.x, vv[4*l4]);   vv[4*l4+1] = fmaf(u0, w.y, vv[4*l4+1]);
            vv[4*l4+2] = fmaf(u0, w.z, vv[4*l4+2]); vv[4*l4+3] = fmaf(u0, w.w, vv[4*l4+3]);
        }
        #pragma unroll
        for (int l4 = 0; l4 < 8; l4++) {
            float4 w = vr1[l4];
            vv[4*l4]   = fmaf(u1, w.x, vv[4*l4]);   vv[4*l4+1] = fmaf(u1, w.y, vv[4*l4+1]);
            vv[4*l4+2] = fmaf(u1, w.z, vv[4*l4+2]); vv[4*l4+3] = fmaf(u1, w.w, vv[4*l4+3]);
        }
        #pragma unroll
        for (int l4 = 0; l4 < 8; l4++) {
            float4 w = vr2[l4];
            vv[4*l4]   = fmaf(u2, w.x, vv[4*l4]);   vv[4*l4+1] = fmaf(u2, w.y, vv[4*l4+1]);
            vv[4*l4+2] = fmaf(u2, w.z, vv[4*l4+2]); vv[4*l4+3] = fmaf(u2, w.w, vv[4*l4+3]);
        }
        #pragma unroll
        for (int l4 = 0; l4 < 8; l4++) {
            float4 w = vr3[l4];
            vv[4*l4]   = fmaf(u3, w.x, vv[4*l4]);   vv[4*l4+1] = fmaf(u3, w.y, vv[4*l4+1]);
            vv[4*l4+2] = fmaf(u3, w.z, vv[4*l4+2]); vv[4*l4+3] = fmaf(u3, w.w, vv[4*l4+3]);
        }
    }
    float4* vo = (float4*)(g_v + r * LAT);
    #pragma unroll
    for (int l4 = 0; l4 < 8; l4++) {
        float4 t;
        t.x = __fadd_rn(vv[4*l4],   vpbs[4*l4]);
        t.y = __fadd_rn(vv[4*l4+1], vpbs[4*l4+1]);
        t.z = __fadd_rn(vv[4*l4+2], vpbs[4*l4+2]);
        t.w = __fadd_rn(vv[4*l4+3], vpbs[4*l4+3]);
        vo[l4] = t;
    }
}

// ---------------- kernel V: softmax/K + c_bar/v_local + VQ argmin (unchanged) ----------------
__global__ void __launch_bounds__(256, 2) kV(
    const float* __restrict__ cc, const float* __restrict__ cbk,
    float* __restrict__ out, int full)
{
    extern __shared__ float sm[];
    float* cbs  = sm;               // KC*LAT
    float* cbns = cbs + KC * LAT;   // KC
    float* ccs  = cbns + KC;        // [c][l]
    float* cct  = ccs + NC * LAT;   // [l][c]

    int tid = threadIdx.x;
    for (int i = tid; i < NC * LAT; i += 256) {
        float t = cc[i]; ccs[i] = t;
        int c = i / LAT, l = i % LAT;
        cct[l * NC + c] = t;
    }

    size_t r = (size_t)blockIdx.x * 256 + tid;
    float v[LAT];
    {
        const float4* vp4 = (const float4*)(g_v + r * LAT);
        #pragma unroll
        for (int i = 0; i < 8; i++) {
            float4 t = vp4[i];
            v[4*i] = t.x; v[4*i+1] = t.y; v[4*i+2] = t.z; v[4*i+3] = t.w;
        }
    }
    __syncthreads();

    float enc[NC]; int K;
    {
        float sc[NC];
        #pragma unroll
        for (int c = 0; c < NC; c++) sc[c] = 0.f;
        #pragma unroll
        for (int l = 0; l < LAT; l++) {
            float vl = v[l];
            float4 wa = ((const float4*)(cct + l * NC))[0];
            float4 wb = ((const float4*)(cct + l * NC))[1];
            sc[0] = fmaf(vl, wa.x, sc[0]); sc[1] = fmaf(vl, wa.y, sc[1]);
            sc[2] = fmaf(vl, wa.z, sc[2]); sc[3] = fmaf(vl, wa.w, sc[3]);
            sc[4] = fmaf(vl, wb.x, sc[4]); sc[5] = fmaf(vl, wb.y, sc[5]);
            sc[6] = fmaf(vl, wb.z, sc[6]); sc[7] = fmaf(vl, wb.w, sc[7]);
        }
        #pragma unroll
        for (int c = 0; c < NC; c++) sc[c] = __fdiv_rn(sc[c], 5.656854249492381f);
        float m = sc[0];
        #pragma unroll
        for (int c = 1; c < NC; c++) m = fmaxf(m, sc[c]);
        float e[NC];
        #pragma unroll
        for (int c = 0; c < NC; c++)
            e[c] = (float)exp((double)__fsub_rn(sc[c], m));  // correctly-rounded fp32 exp
        float s01 = __fadd_rn(e[0], e[1]);
        float s23 = __fadd_rn(e[2], e[3]);
        float s45 = __fadd_rn(e[4], e[5]);
        float s67 = __fadd_rn(e[6], e[7]);
        float s = __fadd_rn(__fadd_rn(s01, s23), __fadd_rn(s45, s67));
        #pragma unroll
        for (int c = 0; c < NC; c++) enc[c] = __fdiv_rn(e[c], s);
        float bm = e[0]; K = 0;
        #pragma unroll
        for (int c = 1; c < NC; c++) if (e[c] > bm) { bm = e[c]; K = c; }
    }

    float cb[LAT];
    #pragma unroll
    for (int l = 0; l < LAT; l++) cb[l] = 0.f;
    #pragma unroll
    for (int c = 0; c < NC; c++) {
        float e = enc[c];
        #pragma unroll
        for (int l = 0; l < LAT; l++) cb[l] = fmaf(e, ccs[c * LAT + l], cb[l]);
    }
    #pragma unroll
    for (int l = 0; l < LAT; l++) v[l] = __fsub_rn(v[l], cb[l]);   // v_local

    {
        float4* vo = (float4*)(g_v + r * LAT);
        float4* co = (float4*)(g_cb + r * LAT);
        #pragma unroll
        for (int l4 = 0; l4 < 8; l4++) {
            float4 tv, tc;
            tv.x = v[4*l4];  tv.y = v[4*l4+1];  tv.z = v[4*l4+2];  tv.w = v[4*l4+3];
            tc.x = cb[4*l4]; tc.y = cb[4*l4+1]; tc.z = cb[4*l4+2]; tc.w = cb[4*l4+3];
            vo[l4] = tv; co[l4] = tc;
        }
        #pragma unroll
        for (int c = 0; c < NC; c++) g_enc[r * NC + c] = enc[c];
        if (full) {
            #pragma unroll
            for (int c = 0; c < NC; c++) out[O_ENC + r * NC + c] = enc[c];
            out[O_K + r] = (float)K;
            #pragma unroll
            for (int l = 0; l < LAT; l++) out[O_CBAR + r * LAT + l] = cb[l];
        }
    }

    float vn = 0.f;
    #pragma unroll
    for (int l = 0; l < LAT; l++) vn = __fadd_rn(vn, __fmul_rn(v[l], v[l]));

    #pragma unroll 1
    for (int c = 0; c < NC; c++) {
        __syncthreads();
        const float* src = cbk + (size_t)c * KC * LAT;
        for (int i = tid; i < KC * LAT; i += 256) cbs[i] = src[i];
        for (int i = tid; i < KC; i += 256) cbns[i] = g_cbn[c * KC + i];
        __syncthreads();
        float best = 3.4e38f; int bi = 0;
        for (int k = 0; k < KC; k += 4) {
            float e0 = 0.f, e1 = 0.f, e2 = 0.f, e3 = 0.f;
            const float4* r0 = (const float4*)(cbs + (k+0) * LAT);
            const float4* r1 = (const float4*)(cbs + (k+1) * LAT);
            const float4* r2 = (const float4*)(cbs + (k+2) * LAT);
            const float4* r3 = (const float4*)(cbs + (k+3) * LAT);
            #pragma unroll
            for (int i = 0; i < 8; i++) {
                float4 w0 = r0[i], w1 = r1[i], w2 = r2[i], w3 = r3[i];
                e0 = fmaf(v[4*i], w0.x, e0); e0 = fmaf(v[4*i+1], w0.y, e0);
                e0 = fmaf(v[4*i+2], w0.z, e0); e0 = fmaf(v[4*i+3], w0.w, e0);
                e1 = fmaf(v[4*i], w1.x, e1); e1 = fmaf(v[4*i+1], w1.y, e1);
                e1 = fmaf(v[4*i+2], w1.z, e1); e1 = fmaf(v[4*i+3], w1.w, e1);
                e2 = fmaf(v[4*i], w2.x, e2); e2 = fmaf(v[4*i+1], w2.y, e2);
                e2 = fmaf(v[4*i+2], w2.z, e2); e2 = fmaf(v[4*i+3], w2.w, e2);
                e3 = fmaf(v[4*i], w3.x, e3); e3 = fmaf(v[4*i+1], w3.y, e3);
                e3 = fmaf(v[4*i+2], w3.z, e3); e3 = fmaf(v[4*i+3], w3.w, e3);
            }
            float d0 = __fadd_rn(__fsub_rn(vn, __fmul_rn(2.0f, e0)), cbns[k+0]);
            float d1 = __fadd_rn(__fsub_rn(vn, __fmul_rn(2.0f, e1)), cbns[k+1]);
            float d2 = __fadd_rn(__fsub_rn(vn, __fmul_rn(2.0f, e2)), cbns[k+2]);
            float d3 = __fadd_rn(__fsub_rn(vn, __fmul_rn(2.0f, e3)), cbns[k+3]);
            if (d0 < best) { best = d0; bi = k+0; }
            if (d1 < best) { best = d1; bi = k+1; }
            if (d2 < best) { best = d2; bi = k+2; }
            if (d3 < best) { best = d3; bi = k+3; }
        }
        g_bidx[r * NC + c] = bi;
    }
}

// ---------------- kernel W: warp-per-row rewrite ----------------
// Lane l owns element l of the row. Shfl-broadcast dots preserve the exact
// sequential fma order of the previous passing version -> bit-identical
// zqb/zn/zgeo/dec/h_global. Tiny register state (no spills), 32 warps/block.
#define KWTH 1024
__global__ void __launch_bounds__(KWTH, 1) kW(
    const float* __restrict__ cbk,
    const float* __restrict__ sfw1, const float* __restrict__ sfb1,
    const float* __restrict__ sfw2, const float* __restrict__ sfb2,
    const float* __restrict__ decw, const float* __restrict__ decb,
    const float* __restrict__ lrw,  const float* __restrict__ lrb,
    float* __restrict__ out, int full)
{
    extern __shared__ float sm[];
    float* decwt = sm;                       // 32768: [(c*32+l)*128 + h]
    float* decbs = decwt + NC * HID * LAT;   // 1024
    float* sfw1n = decbs + NC * HID;         // 512 [l*16+m]
    float* sfw2s = sfw1n + LAT * MID;        // 512 [m*32+l]
    float* lrws  = sfw2s + MID * LAT;        // 256 [l*8+c]
    float* sfb1s = lrws + LAT * NC;          // 16
    float* sfb2s = sfb1s + MID;              // 32
    float* lrbs  = sfb2s + LAT;              // 8
    float* redv  = lrbs + NC;                // 32

    int tid = threadIdx.x;
    for (int i = tid; i < NC * HID * LAT; i += KWTH) {
        int c = i >> 12; int rem = i & 4095; int h = rem >> 5; int l = rem & 31;
        decwt[(c * 32 + l) * 128 + h] = decw[i];
    }
    for (int i = tid; i < NC * HID; i += KWTH) decbs[i] = decb[i];
    for (int i = tid; i < LAT * MID; i += KWTH) sfw1n[i] = sfw1[i];
    for (int i = tid; i < MID * LAT; i += KWTH) sfw2s[i] = sfw2[i];
    for (int i = tid; i < LAT * NC; i += KWTH) lrws[i] = lrw[i];
    if (tid < MID) sfb1s[tid] = sfb1[tid];
    if (tid < LAT) sfb2s[tid] = sfb2[tid];
    if (tid < NC)  lrbs[tid] = lrb[tid];
    __syncthreads();

    int warp = tid >> 5, lane = tid & 31;
    size_t r = (size_t)blockIdx.x * (KWTH / 32) + warp;

    float vl  = g_v[r * LAT + lane];    // coalesced
    float cbl = g_cb[r * LAT + lane];
    float enc[NC];
    #pragma unroll
    for (int c = 0; c < NC; c++) enc[c] = g_enc[r * NC + c];

    float zqb = 0.f, zn = 0.f, vqa = 0.f;
    #pragma unroll 1
    for (int c = 0; c < NC; c++) {
        int bi = g_bidx[r * NC + c];
        float zq = cbk[((size_t)c * KC + bi) * LAT + lane];
        float e = enc[c];
        zqb = fmaf(e, zq, zqb);
        float d = __fsub_rn(vl, zq);
        // vq partial (tree; scalar output, loose tolerance)
        float t = __fmul_rn(d, d);
        t += __shfl_xor_sync(0xFFFFFFFFu, t, 16);
        t += __shfl_xor_sync(0xFFFFFFFFu, t, 8);
        t += __shfl_xor_sync(0xFFFFFFFFu, t, 4);
        t += __shfl_xor_sync(0xFFFFFFFFu, t, 2);
        t += __shfl_xor_sync(0xFFFFFFFFu, t, 1);
        vqa = fmaf(e, t, vqa);
        // SF layer1: lanes m<16 compute a_m with the exact seq-l chain
        float a = 0.f;
        #pragma unroll
        for (int l = 0; l < 32; l++) {
            float db = __shfl_sync(0xFFFFFFFFu, d, l);
            a = fmaf(db, sfw1n[l * MID + (lane & 15)], a);
        }
        float mvv = gelu_ref(__fadd_rn(a, sfb1s[lane & 15]));
        // SF layer2: lane l accumulates seq-m chain
        float acc = 0.f;
        #pragma unroll
        for (int m = 0; m < MID; m++) {
            float mb = __shfl_sync(0xFFFFFFFFu, mvv, m);
            acc = fmaf(mb, sfw2s[m * LAT + lane], acc);
        }
        zn = fmaf(e, __fadd_rn(acc, sfb2s[lane]), zn);
    }

    float zgeo = __fadd_rn(__fadd_rn(cbl, zqb), zn);
    float zg = tanhf(zgeo);
    float ztv = tanhf(__fsub_rn(__fsub_rn(vl, zqb), zn));
    g_zt[r * LAT + lane] = ztv;                    // coalesced
    if (full) {
        out[O_ZGEO + r * LAT + lane] = zgeo;       // coalesced
        out[O_ZN   + r * LAT + lane] = zn;
    }

    // dec softmax: lanes c<8 compute lg_c (seq-l chain), then replicate
    float lg = 0.f;
    #pragma unroll
    for (int l = 0; l < 32; l++) {
        float zb = __shfl_sync(0xFFFFFFFFu, zg, l);
        lg = fmaf(zb, lrws[l * NC + (lane & 7)], lg);
    }
    lg = __fadd_rn(lg, lrbs[lane & 7]);
    float dec[NC];
    {
        float lgv[NC];
        #pragma unroll
        for (int c = 0; c < NC; c++) lgv[c] = __shfl_sync(0xFFFFFFFFu, lg, c);
        float m = lgv[0];
        #pragma unroll
        for (int c = 1; c < NC; c++) m = fmaxf(m, lgv[c]);
        float s = 0.f;
        #pragma unroll
        for (int c = 0; c < NC; c++) { dec[c] = expf(__fsub_rn(lgv[c], m)); s = __fadd_rn(s, dec[c]); }
        #pragma unroll
        for (int c = 0; c < NC; c++) dec[c] = __fdiv_rn(dec[c], s);
    }
    if (full && lane < NC) out[O_DEC + r * NC + lane] = dec[lane];

    // h_global: lane handles h = cp*64 + q*32 + lane; per-c seq-l chains
    #pragma unroll 1
    for (int cp = 0; cp < 2; cp++) {
        float a[NC][2];
        #pragma unroll
        for (int c = 0; c < NC; c++) { a[c][0] = 0.f; a[c][1] = 0.f; }
        #pragma unroll
        for (int l = 0; l < 32; l++) {
            float zb = __shfl_sync(0xFFFFFFFFu, zg, l);
            #pragma unroll
            for (int c = 0; c < NC; c++) {
                const float* base = decwt + (c * 32 + l) * 128 + cp * 64 + lane;
                a[c][0] = fmaf(zb, base[0],  a[c][0]);
                a[c][1] = fmaf(zb, base[32], a[c][1]);
            }
        }
        #pragma unroll
        for (int q = 0; q < 2; q++) {
            int h = cp * 64 + q * 32 + lane;
            float acc = 0.f;
            #pragma unroll
            for (int c = 0; c < NC; c++)
                acc = __fadd_rn(acc, __fmul_rn(dec[c], __fadd_rn(a[c][q], decbs[c * HID + h])));
            g_hg[r * HID + h] = acc;               // coalesced
        }
    }

    // vq reduce: warp partial -> block -> one atomic
    if (lane == 0) redv[warp] = vqa;
    __syncthreads();
    if (tid == 0) {
        float ssum = 0.f;
        #pragma unroll
        for (int w = 0; w < KWTH / 32; w++) ssum += redv[w];
        atomicAdd(&g_vq, (double)ssum);
    }
}

// ---------------- kernel C: h_global -> x_hat (unchanged) ----------------
__global__ void __launch_bounds__(256) kC(
    const float* __restrict__ rw1, const float* __restrict__ rb1,
    const float* __restrict__ rw2, const float* __restrict__ rb2,
    const float* __restrict__ skw, const float* __restrict__ skb,
    const float* __restrict__ txw, const float* __restrict__ txb,
    const float* __restrict__ tscale, float* __restrict__ out)
{
    extern __shared__ float sm[];
    float* rw1n = sm;
    float* rw2s = rw1n + HID * HID;
    float* skws = rw2s + HID * DIN;
    float* txws = skws + HID * DIN;
    float* rb1s = txws + LAT * DIN;
    float* rb2s = rb1s + HID;
    float* skbs = rb2s + DIN;
    float* txbs = skbs + DIN;

    int tid = threadIdx.x;
    for (int i = tid; i < HID * HID; i += 256) rw1n[i] = rw1[i];
    for (int i = tid; i < HID * DIN; i += 256) { rw2s[i] = rw2[i]; skws[i] = skw[i]; }
    for (int i = tid; i < LAT * DIN; i += 256) txws[i] = txw[i];
    if (tid < HID) rb1s[tid] = rb1[tid];
    if (tid < DIN) { rb2s[tid] = rb2[tid]; skbs[tid] = skb[tid]; txbs[tid] = txb[tid]; }
    __syncthreads();

    size_t r = (size_t)blockIdx.x * 256 + tid;
    float ts = tscale[0];

    const float* hgp = g_hg + r * HID;

    float hg[HID], g[HID];
    {
        const float4* h4 = (const float4*)hgp;
        #pragma unroll
        for (int i = 0; i < 32; i++) {
            float4 t = h4[i];
            hg[4*i] = t.x; hg[4*i+1] = t.y; hg[4*i+2] = t.z; hg[4*i+3] = t.w;
            g[4*i]   = gelu_ref(t.x); g[4*i+1] = gelu_ref(t.y);
            g[4*i+2] = gelu_ref(t.z); g[4*i+3] = gelu_ref(t.w);
        }
    }

    float o[DIN], sk[DIN];
    #pragma unroll
    for (int l = 0; l < DIN; l++) { o[l] = 0.f; sk[l] = 0.f; }

    for (int j = 0; j < HID; j += 4) {
        float a0 = 0.f, a1 = 0.f, a2 = 0.f, a3 = 0.f;
        #pragma unroll
        for (int i = 0; i < HID; i++) {
            float gi = g[i];
            float4 w = *(const float4*)(rw1n + i * HID + j);
            a0 = fmaf(gi, w.x, a0); a1 = fmaf(gi, w.y, a1);
            a2 = fmaf(gi, w.z, a2); a3 = fmaf(gi, w.w, a3);
        }
        float u0 = gelu_ref(__fadd_rn(a0, rb1s[j+0]));
        float u1 = gelu_ref(__fadd_rn(a1, rb1s[j+1]));
        float u2 = gelu_ref(__fadd_rn(a2, rb1s[j+2]));
        float u3 = gelu_ref(__fadd_rn(a3, rb1s[j+3]));
        const float4* r0 = (const float4*)(rw2s + (j+0) * DIN);
        const float4* r1 = (const float4*)(rw2s + (j+1) * DIN);
        const float4* r2 = (const float4*)(rw2s + (j+2) * DIN);
        const float4* r3 = (const float4*)(rw2s + (j+3) * DIN);
        #pragma unroll
        for (int l4 = 0; l4 < 8; l4++) {
            float4 w = r0[l4];
            o[4*l4]   = fmaf(u0, w.x, o[4*l4]);   o[4*l4+1] = fmaf(u0, w.y, o[4*l4+1]);
            o[4*l4+2] = fmaf(u0, w.z, o[4*l4+2]); o[4*l4+3] = fmaf(u0, w.w, o[4*l4+3]);
        }
        #pragma unroll
        for (int l4 = 0; l4 < 8; l4++) {
            float4 w = r1[l4];
            o[4*l4]   = fmaf(u1, w.x, o[4*l4]);   o[4*l4+1] = fmaf(u1, w.y, o[4*l4+1]);
            o[4*l4+2] = fmaf(u1, w.z, o[4*l4+2]); o[4*l4+3] = fmaf(u1, w.w, o[4*l4+3]);
        }
        #pragma unroll
        for (int l4 = 0; l4 < 8; l4++) {
            float4 w = r2[l4];
            o[4*l4]   = fmaf(u2, w.x, o[4*l4]);   o[4*l4+1] = fmaf(u2, w.y, o[4*l4+1]);
            o[4*l4+2] = fmaf(u2, w.z, o[4*l4+2]); o[4*l4+3] = fmaf(u2, w.w, o[4*l4+3]);
        }
        #pragma unroll
        for (int l4 = 0; l4 < 8; l4++) {
            float4 w = r3[l4];
            o[4*l4]   = fmaf(u3, w.x, o[4*l4]);   o[4*l4+1] = fmaf(u3, w.y, o[4*l4+1]);
            o[4*l4+2] = fmaf(u3, w.z, o[4*l4+2]); o[4*l4+3] = fmaf(u3, w.w, o[4*l4+3]);
        }
        const float4* s0 = (const float4*)(skws + (j+0) * DIN);
        const float4* s1 = (const float4*)(skws + (j+1) * DIN);
        const float4* s2 = (const float4*)(skws + (j+2) * DIN);
        const float4* s3 = (const float4*)(skws + (j+3) * DIN);
        float h0 = hg[j+0], h1v = hg[j+1], h2v = hg[j+2], h3v = hg[j+3];
        #pragma unroll
        for (int l4 = 0; l4 < 8; l4++) {
            float4 w = s0[l4];
            sk[4*l4]   = fmaf(h0, w.x, sk[4*l4]);   sk[4*l4+1] = fmaf(h0, w.y, sk[4*l4+1]);
            sk[4*l4+2] = fmaf(h0, w.z, sk[4*l4+2]); sk[4*l4+3] = fmaf(h0, w.w, sk[4*l4+3]);
        }
        #pragma unroll
        for (int l4 = 0; l4 < 8; l4++) {
            float4 w = s1[l4];
            sk[4*l4]   = fmaf(h1v, w.x, sk[4*l4]);   sk[4*l4+1] = fmaf(h1v, w.y, sk[4*l4+1]);
            sk[4*l4+2] = fmaf(h1v, w.z, sk[4*l4+2]); sk[4*l4+3] = fmaf(h1v, w.w, sk[4*l4+3]);
        }
        #pragma unroll
        for (int l4 = 0; l4 < 8; l4++) {
            float4 w = s2[l4];
            sk[4*l4]   = fmaf(h2v, w.x, sk[4*l4]);   sk[4*l4+1] = fmaf(h2v, w.y, sk[4*l4+1]);
            sk[4*l4+2] = fmaf(h2v, w.z, sk[4*l4+2]); sk[4*l4+3] = fmaf(h2v, w.w, sk[4*l4+3]);
        }
        #pragma unroll
        for (int l4 = 0; l4 < 8; l4++) {
            float4 w = s3[l4];
            sk[4*l4]   = fmaf(h3v, w.x, sk[4*l4]);   sk[4*l4+1] = fmaf(h3v, w.y, sk[4*l4+1]);
            sk[4*l4+2] = fmaf(h3v, w.z, sk[4*l4+2]); sk[4*l4+3] = fmaf(h3v, w.w, sk[4*l4+3]);
        }
    }

    float zt[LAT];
    {
        const float4* z4 = (const float4*)(g_zt + r * LAT);
        #pragma unroll
        for (int i = 0; i < 8; i++) {
            float4 t = z4[i];
            zt[4*i] = t.x; zt[4*i+1] = t.y; zt[4*i+2] = t.z; zt[4*i+3] = t.w;
        }
    }
    float tx[DIN];
    #pragma unroll
    for (int l = 0; l < DIN; l++) tx[l] = 0.f;
    #pragma unroll
    for (int lp = 0; lp < LAT; lp++) {
        float ztl = zt[lp];
        const float4* t4 = (const float4*)(txws + lp * DIN);
        #pragma unroll
        for (int l4 = 0; l4 < 8; l4++) {
            float4 w = t4[l4];
            tx[4*l4]   = fmaf(ztl, w.x, tx[4*l4]);   tx[4*l4+1] = fmaf(ztl, w.y, tx[4*l4+1]);
            tx[4*l4+2] = fmaf(ztl, w.z, tx[4*l4+2]); tx[4*l4+3] = fmaf(ztl, w.w, tx[4*l4+3]);
        }
    }

    float4* xo = (float4*)(out + O_XHAT + r * DIN);
    #pragma unroll
    for (int l4 = 0; l4 < 8; l4++) {
        float4 t;
        #pragma unroll
        for (int q = 0; q < 4; q++) {
            int l = 4*l4 + q;
            float mlp  = __fadd_rn(o[l], rb2s[l]);
            float skp  = __fadd_rn(sk[l], skbs[l]);
            float base = __fadd_rn(mlp, skp);
            float texv = __fmul_rn(ts, __fadd_rn(tx[l], txbs[l]));
            ((float*)&t)[q] = __fadd_rn(base, texv);
        }
        xo[l4] = t;
    }
}

// ---------------- kernel D ----------------
__global__ void kD(float* __restrict__ out, int full) {
    if (full) out[O_VQ] = (float)(1.25 * g_vq / ((double)Bsz * (double)LAT));
}

// ---------------- launch ----------------
extern "C" void kernel_launch(void* const* d_in, const int* in_sizes, int n_in,
                              void* d_out, int out_size) {
    const float* x    = (const float*)d_in[0];
    const float* fw1  = (const float*)d_in[1];
    const float* fb1  = (const float*)d_in[2];
    const float* fw2  = (const float*)d_in[3];
    const float* fb2  = (const float*)d_in[4];
    const float* vpw  = (const float*)d_in[5];
    const float* vpb  = (const float*)d_in[6];
    const float* cc   = (const float*)d_in[7];
    const float* cbk  = (const float*)d_in[8];
    const float* sfw1 = (const float*)d_in[9];
    const float* sfb1 = (const float*)d_in[10];
    const float* sfw2 = (const float*)d_in[11];
    const float* sfb2 = (const float*)d_in[12];
    const float* decw = (const float*)d_in[13];
    const float* decb = (const float*)d_in[14];
    const float* lrw  = (const float*)d_in[15];
    const float* lrb  = (const float*)d_in[16];
    const float* txw  = (const float*)d_in[17];
    const float* txb  = (const float*)d_in[18];
    const float* tsc  = (const float*)d_in[19];
    const float* rw1  = (const float*)d_in[20];
    const float* rb1  = (const float*)d_in[21];
    const float* rw2  = (const float*)d_in[22];
    const float* rb2  = (const float*)d_in[23];
    const float* skw  = (const float*)d_in[24];
    const float* skb  = (const float*)d_in[25];

    float* out = (float*)d_out;
    int full = (out_size >= O_TOTAL) ? 1 : 0;

    const int SMEM_A = (DIN*HID + HID*HID + HID*LAT + HID + HID + LAT + HID*256) * 4;
    const int SMEM_V = (KC*LAT + KC + NC*LAT + LAT*NC) * 4;
    const int SMEM_W = (NC*HID*LAT + NC*HID + LAT*MID + MID*LAT + LAT*NC + MID + LAT + NC + 32) * 4;
    const int SMEM_C = (HID*HID + HID*DIN + HID*DIN + LAT*DIN + HID + DIN + DIN + DIN) * 4;

    cudaFuncSetAttribute(kA, cudaFuncAttributeMaxDynamicSharedMemorySize, SMEM_A);
    cudaFuncSetAttribute(kV, cudaFuncAttributeMaxDynamicSharedMemorySize, SMEM_V);
    cudaFuncSetAttribute(kW, cudaFuncAttributeMaxDynamicSharedMemorySize, SMEM_W);
    cudaFuncSetAttribute(kC, cudaFuncAttributeMaxDynamicSharedMemorySize, SMEM_C);

    kPrep<<<16, 256>>>(cbk);
    kA<<<Bsz / 256, 256, SMEM_A>>>(x, fw1, fb1, fw2, fb2, vpw, vpb);
    kV<<<Bsz / 256, 256, SMEM_V>>>(cc, cbk, out, full);
    kW<<<Bsz / (KWTH / 32), KWTH, SMEM_W>>>(cbk, sfw1, sfb1, sfw2, sfb2, decw, decb, lrw, lrb, out, full);
    kC<<<Bsz / 256, 256, SMEM_C>>>(rw1, rb1, rw2, rb2, skw, skb, txw, txb, tsc, out);
    kD<<<1, 1>>>(out, full);
}

// round 12
// speedup vs baseline: 1.6068x; 1.0846x over previous
#include <cuda_runtime.h>

#define Bsz 65536
#define DIN 32
#define HID 128
#define LAT 32
#define NC  8
#define KC  512
#define MID 16

// ---------------- scratch (no allocations allowed) ----------------
static __device__ float  g_v[Bsz * LAT];     // v then v_local
static __device__ float  g_cb[Bsz * LAT];
static __device__ float  g_enc[Bsz * NC];
static __device__ int    g_bidx[Bsz * NC];
static __device__ float  g_hg[Bsz * HID];
static __device__ float  g_zt[Bsz * LAT];
static __device__ float  g_cbn[NC * KC];
static __device__ double g_vq;

// ---------------- output layout (concatenated tuple, f32) ----------------
#define O_XHAT 0
#define O_VQ   (Bsz * DIN)
#define O_ENC  (O_VQ + 1)
#define O_DEC  (O_ENC + Bsz * NC)
#define O_K    (O_DEC + Bsz * NC)
#define O_ZGEO (O_K + Bsz)
#define O_ZN   (O_ZGEO + Bsz * LAT)
#define O_CBAR (O_ZN + Bsz * LAT)
#define O_TOTAL (O_CBAR + Bsz * LAT)

__device__ __forceinline__ float gelu_ref(float x) {
    float u = __fdiv_rn(x, 1.4142135623730951f);
    float t = erff(u);
    return __fmul_rn(__fmul_rn(0.5f, x), __fadd_rn(1.0f, t));
}

// ---------------- prep ----------------
__global__ void kPrep(const float* __restrict__ cbk) {
    int idx = blockIdx.x * blockDim.x + threadIdx.x;
    if (idx == 0) g_vq = 0.0;
    if (idx < NC * KC) {
        const float* row = cbk + (size_t)idx * LAT;
        float s = 0.f;
        #pragma unroll
        for (int l = 0; l < LAT; l++) s = __fadd_rn(s, __fmul_rn(row[l], row[l]));
        g_cbn[idx] = s;
    }
}

// ---------------- kernel A: x -> features -> v (unchanged) ----------------
__global__ void __launch_bounds__(256) kA(
    const float* __restrict__ x,  const float* __restrict__ w1, const float* __restrict__ b1,
    const float* __restrict__ w2, const float* __restrict__ b2,
    const float* __restrict__ vp, const float* __restrict__ vpb)
{
    extern __shared__ float sm[];
    float* w1n  = sm;
    float* w2n  = w1n + DIN * HID;
    float* vps  = w2n + HID * HID;
    float* b1s  = vps + HID * LAT;
    float* b2s  = b1s + HID;
    float* vpbs = b2s + HID;
    float* h1s  = vpbs + LAT;

    int tid = threadIdx.x;
    for (int i = tid; i < DIN * HID; i += 256) w1n[i] = w1[i];
    for (int i = tid; i < HID * HID; i += 256) w2n[i] = w2[i];
    for (int i = tid; i < HID * LAT; i += 256) vps[i] = vp[i];
    if (tid < HID) { b1s[tid] = b1[tid]; b2s[tid] = b2[tid]; }
    if (tid < LAT) vpbs[tid] = vpb[tid];
    __syncthreads();

    size_t r = (size_t)blockIdx.x * 256 + tid;

    float xr[DIN];
    {
        const float4* xp = (const float4*)(x + r * DIN);
        #pragma unroll
        for (int i = 0; i < 8; i++) {
            float4 t = xp[i];
            xr[4*i] = t.x; xr[4*i+1] = t.y; xr[4*i+2] = t.z; xr[4*i+3] = t.w;
        }
    }

    for (int j = 0; j < HID; j += 4) {
        float a0 = 0.f, a1 = 0.f, a2 = 0.f, a3 = 0.f;
        #pragma unroll
        for (int i = 0; i < DIN; i++) {
            float xi = xr[i];
            float4 w = *(const float4*)(w1n + i * HID + j);
            a0 = fmaf(xi, w.x, a0); a1 = fmaf(xi, w.y, a1);
            a2 = fmaf(xi, w.z, a2); a3 = fmaf(xi, w.w, a3);
        }
        h1s[(j+0) * 256 + tid] = gelu_ref(__fadd_rn(a0, b1s[j+0]));
        h1s[(j+1) * 256 + tid] = gelu_ref(__fadd_rn(a1, b1s[j+1]));
        h1s[(j+2) * 256 + tid] = gelu_ref(__fadd_rn(a2, b1s[j+2]));
        h1s[(j+3) * 256 + tid] = gelu_ref(__fadd_rn(a3, b1s[j+3]));
    }

    float h1[HID];
    #pragma unroll
    for (int i = 0; i < HID; i++) h1[i] = h1s[i * 256 + tid];

    float vv[LAT];
    #pragma unroll
    for (int l = 0; l < LAT; l++) vv[l] = 0.f;
    for (int j = 0; j < HID; j += 4) {
        float a0 = 0.f, a1 = 0.f, a2 = 0.f, a3 = 0.f;
        #pragma unroll
        for (int i = 0; i < HID; i++) {
            float hi = h1[i];
            float4 w = *(const float4*)(w2n + i * HID + j);
            a0 = fmaf(hi, w.x, a0); a1 = fmaf(hi, w.y, a1);
            a2 = fmaf(hi, w.z, a2); a3 = fmaf(hi, w.w, a3);
        }
        float u0 = gelu_ref(__fadd_rn(a0, b2s[j+0]));
        float u1 = gelu_ref(__fadd_rn(a1, b2s[j+1]));
        float u2 = gelu_ref(__fadd_rn(a2, b2s[j+2]));
        float u3 = gelu_ref(__fadd_rn(a3, b2s[j+3]));
        const float4* vr0 = (const float4*)(vps + (j+0) * LAT);
        const float4* vr1 = (const float4*)(vps + (j+1) * LAT);
        const float4* vr2 = (const float4*)(vps + (j+2) * LAT);
        const float4* vr3 = (const float4*)(vps + (j+3) * LAT);
        #pragma unroll
        for (int l4 = 0; l4 < 8; l4++) {
            float4 w = vr0[l4];
            vv[4*l4]   = fmaf(u0, w.x, vv[4*l4]);   vv[4*l4+1] = fmaf(u0, w.y, vv[4*l4+1]);
            vv[4*l4+2] = fmaf(u0, w.z, vv[4*l4+2]); vv[4*l4+3] = fmaf(u0, w.w, vv[4*l4+3]);
        }
        #pragma unroll
        for (int l4 = 0; l4 < 8; l4++) {
            float4 w = vr1[l4];
            vv[4*l4]   = fmaf(u1, w.x, vv[4*l4]);   vv[4*l4+1] = fmaf(u1, w.y, vv[4*l4+1]);
            vv[4*l4+2] = fmaf(u1, w.z, vv[4*l4+2]); vv[4*l4+3] = fmaf(u1, w.w, vv[4*l4+3]);
        }
        #pragma unroll
        for (int l4 = 0; l4 < 8; l4++) {
            float4 w = vr2[l4];
            vv[4*l4]   = fmaf(u2, w.x, vv[4*l4]);   vv[4*l4+1] = fmaf(u2, w.y, vv[4*l4+1]);
            vv[4*l4+2] = fmaf(u2, w.z, vv[4*l4+2]); vv[4*l4+3] = fmaf(u2, w.w, vv[4*l4+3]);
        }
        #pragma unroll
        for (int l4 = 0; l4 < 8; l4++) {
            float4 w = vr3[l4];
            vv[4*l4]   = fmaf(u3, w.x, vv[4*l4]);   vv[4*l4+1] = fmaf(u3, w.y, vv[4*l4+1]);
            vv[4*l4+2] = fmaf(u3, w.z, vv[4*l4+2]); vv[4*l4+3] = fmaf(u3, w.w, vv[4*l4+3]);
        }
    }
    float4* vo = (float4*)(g_v + r * LAT);
    #pragma unroll
    for (int l4 = 0; l4 < 8; l4++) {
        float4 t;
        t.x = __fadd_rn(vv[4*l4],   vpbs[4*l4]);
        t.y = __fadd_rn(vv[4*l4+1], vpbs[4*l4+1]);
        t.z = __fadd_rn(vv[4*l4+2], vpbs[4*l4+2]);
        t.w = __fadd_rn(vv[4*l4+3], vpbs[4*l4+3]);
        vo[l4] = t;
    }
}

// ---------------- kernel V: softmax/K + c_bar/v_local + VQ argmin (unchanged) ----------------
__global__ void __launch_bounds__(256, 2) kV(
    const float* __restrict__ cc, const float* __restrict__ cbk,
    float* __restrict__ out, int full)
{
    extern __shared__ float sm[];
    float* cbs  = sm;               // KC*LAT
    float* cbns = cbs + KC * LAT;   // KC
    float* ccs  = cbns + KC;        // [c][l]
    float* cct  = ccs + NC * LAT;   // [l][c]

    int tid = threadIdx.x;
    for (int i = tid; i < NC * LAT; i += 256) {
        float t = cc[i]; ccs[i] = t;
        int c = i / LAT, l = i % LAT;
        cct[l * NC + c] = t;
    }

    size_t r = (size_t)blockIdx.x * 256 + tid;
    float v[LAT];
    {
        const float4* vp4 = (const float4*)(g_v + r * LAT);
        #pragma unroll
        for (int i = 0; i < 8; i++) {
            float4 t = vp4[i];
            v[4*i] = t.x; v[4*i+1] = t.y; v[4*i+2] = t.z; v[4*i+3] = t.w;
        }
    }
    __syncthreads();

    float enc[NC]; int K;
    {
        float sc[NC];
        #pragma unroll
        for (int c = 0; c < NC; c++) sc[c] = 0.f;
        #pragma unroll
        for (int l = 0; l < LAT; l++) {
            float vl = v[l];
            float4 wa = ((const float4*)(cct + l * NC))[0];
            float4 wb = ((const float4*)(cct + l * NC))[1];
            sc[0] = fmaf(vl, wa.x, sc[0]); sc[1] = fmaf(vl, wa.y, sc[1]);
            sc[2] = fmaf(vl, wa.z, sc[2]); sc[3] = fmaf(vl, wa.w, sc[3]);
            sc[4] = fmaf(vl, wb.x, sc[4]); sc[5] = fmaf(vl, wb.y, sc[5]);
            sc[6] = fmaf(vl, wb.z, sc[6]); sc[7] = fmaf(vl, wb.w, sc[7]);
        }
        #pragma unroll
        for (int c = 0; c < NC; c++) sc[c] = __fdiv_rn(sc[c], 5.656854249492381f);
        float m = sc[0];
        #pragma unroll
        for (int c = 1; c < NC; c++) m = fmaxf(m, sc[c]);
        float e[NC];
        #pragma unroll
        for (int c = 0; c < NC; c++)
            e[c] = (float)exp((double)__fsub_rn(sc[c], m));  // correctly-rounded fp32 exp
        float s01 = __fadd_rn(e[0], e[1]);
        float s23 = __fadd_rn(e[2], e[3]);
        float s45 = __fadd_rn(e[4], e[5]);
        float s67 = __fadd_rn(e[6], e[7]);
        float s = __fadd_rn(__fadd_rn(s01, s23), __fadd_rn(s45, s67));
        #pragma unroll
        for (int c = 0; c < NC; c++) enc[c] = __fdiv_rn(e[c], s);
        float bm = e[0]; K = 0;
        #pragma unroll
        for (int c = 1; c < NC; c++) if (e[c] > bm) { bm = e[c]; K = c; }
    }

    float cb[LAT];
    #pragma unroll
    for (int l = 0; l < LAT; l++) cb[l] = 0.f;
    #pragma unroll
    for (int c = 0; c < NC; c++) {
        float e = enc[c];
        #pragma unroll
        for (int l = 0; l < LAT; l++) cb[l] = fmaf(e, ccs[c * LAT + l], cb[l]);
    }
    #pragma unroll
    for (int l = 0; l < LAT; l++) v[l] = __fsub_rn(v[l], cb[l]);   // v_local

    {
        float4* vo = (float4*)(g_v + r * LAT);
        float4* co = (float4*)(g_cb + r * LAT);
        #pragma unroll
        for (int l4 = 0; l4 < 8; l4++) {
            float4 tv, tc;
            tv.x = v[4*l4];  tv.y = v[4*l4+1];  tv.z = v[4*l4+2];  tv.w = v[4*l4+3];
            tc.x = cb[4*l4]; tc.y = cb[4*l4+1]; tc.z = cb[4*l4+2]; tc.w = cb[4*l4+3];
            vo[l4] = tv; co[l4] = tc;
        }
        #pragma unroll
        for (int c = 0; c < NC; c++) g_enc[r * NC + c] = enc[c];
        if (full) {
            #pragma unroll
            for (int c = 0; c < NC; c++) out[O_ENC + r * NC + c] = enc[c];
            out[O_K + r] = (float)K;
            #pragma unroll
            for (int l = 0; l < LAT; l++) out[O_CBAR + r * LAT + l] = cb[l];
        }
    }

    float vn = 0.f;
    #pragma unroll
    for (int l = 0; l < LAT; l++) vn = __fadd_rn(vn, __fmul_rn(v[l], v[l]));

    #pragma unroll 1
    for (int c = 0; c < NC; c++) {
        __syncthreads();
        const float* src = cbk + (size_t)c * KC * LAT;
        for (int i = tid; i < KC * LAT; i += 256) cbs[i] = src[i];
        for (int i = tid; i < KC; i += 256) cbns[i] = g_cbn[c * KC + i];
        __syncthreads();
        float best = 3.4e38f; int bi = 0;
        for (int k = 0; k < KC; k += 4) {
            float e0 = 0.f, e1 = 0.f, e2 = 0.f, e3 = 0.f;
            const float4* r0 = (const float4*)(cbs + (k+0) * LAT);
            const float4* r1 = (const float4*)(cbs + (k+1) * LAT);
            const float4* r2 = (const float4*)(cbs + (k+2) * LAT);
            const float4* r3 = (const float4*)(cbs + (k+3) * LAT);
            #pragma unroll
            for (int i = 0; i < 8; i++) {
                float4 w0 = r0[i], w1 = r1[i], w2 = r2[i], w3 = r3[i];
                e0 = fmaf(v[4*i], w0.x, e0); e0 = fmaf(v[4*i+1], w0.y, e0);
                e0 = fmaf(v[4*i+2], w0.z, e0); e0 = fmaf(v[4*i+3], w0.w, e0);
                e1 = fmaf(v[4*i], w1.x, e1); e1 = fmaf(v[4*i+1], w1.y, e1);
                e1 = fmaf(v[4*i+2], w1.z, e1); e1 = fmaf(v[4*i+3], w1.w, e1);
                e2 = fmaf(v[4*i], w2.x, e2); e2 = fmaf(v[4*i+1], w2.y, e2);
                e2 = fmaf(v[4*i+2], w2.z, e2); e2 = fmaf(v[4*i+3], w2.w, e2);
                e3 = fmaf(v[4*i], w3.x, e3); e3 = fmaf(v[4*i+1], w3.y, e3);
                e3 = fmaf(v[4*i+2], w3.z, e3); e3 = fmaf(v[4*i+3], w3.w, e3);
            }
            float d0 = __fadd_rn(__fsub_rn(vn, __fmul_rn(2.0f, e0)), cbns[k+0]);
            float d1 = __fadd_rn(__fsub_rn(vn, __fmul_rn(2.0f, e1)), cbns[k+1]);
            float d2 = __fadd_rn(__fsub_rn(vn, __fmul_rn(2.0f, e2)), cbns[k+2]);
            float d3 = __fadd_rn(__fsub_rn(vn, __fmul_rn(2.0f, e3)), cbns[k+3]);
            if (d0 < best) { best = d0; bi = k+0; }
            if (d1 < best) { best = d1; bi = k+1; }
            if (d2 < best) { best = d2; bi = k+2; }
            if (d3 < best) { best = d3; bi = k+3; }
        }
        g_bidx[r * NC + c] = bi;
    }
}

// ---------------- kernel W: warp-per-row phase1 + row-amortized h_global ----------------
#define KWTH 1024
#define KWROWS (KWTH / 32)
__global__ void __launch_bounds__(KWTH, 1) kW(
    const float* __restrict__ cbk,
    const float* __restrict__ sfw1, const float* __restrict__ sfb1,
    const float* __restrict__ sfw2, const float* __restrict__ sfb2,
    const float* __restrict__ decw, const float* __restrict__ decb,
    const float* __restrict__ lrw,  const float* __restrict__ lrb,
    float* __restrict__ out, int full)
{
    extern __shared__ float sm[];
    float* decwt = sm;                       // 32768: [(c*32+l)*128 + h]
    float* decbs = decwt + NC * HID * LAT;   // 1024
    float* sfw1n = decbs + NC * HID;         // 512 [l*16+m]
    float* sfw2s = sfw1n + LAT * MID;        // 512 [m*32+l]
    float* lrws  = sfw2s + MID * LAT;        // 256 [l*8+c]
    float* sfb1s = lrws + LAT * NC;          // 16
    float* sfb2s = sfb1s + MID;              // 32
    float* lrbs  = sfb2s + LAT;              // 8
    float* redv  = lrbs + NC;                // 32
    float* zg_s  = redv + 32;                // 32 rows * 33 = 1056
    float* dec_s = zg_s + KWROWS * 33;       // 32 rows * 8 = 256

    int tid = threadIdx.x;
    for (int i = tid; i < NC * HID * LAT; i += KWTH) {
        int c = i >> 12; int rem = i & 4095; int h = rem >> 5; int l = rem & 31;
        decwt[(c * 32 + l) * 128 + h] = decw[i];
    }
    for (int i = tid; i < NC * HID; i += KWTH) decbs[i] = decb[i];
    for (int i = tid; i < LAT * MID; i += KWTH) sfw1n[i] = sfw1[i];
    for (int i = tid; i < MID * LAT; i += KWTH) sfw2s[i] = sfw2[i];
    for (int i = tid; i < LAT * NC; i += KWTH) lrws[i] = lrw[i];
    if (tid < MID) sfb1s[tid] = sfb1[tid];
    if (tid < LAT) sfb2s[tid] = sfb2[tid];
    if (tid < NC)  lrbs[tid] = lrb[tid];
    __syncthreads();

    int warp = tid >> 5, lane = tid & 31;
    size_t r = (size_t)blockIdx.x * KWROWS + warp;

    float vl  = g_v[r * LAT + lane];    // coalesced
    float cbl = g_cb[r * LAT + lane];
    float enc[NC];
    #pragma unroll
    for (int c = 0; c < NC; c++) enc[c] = g_enc[r * NC + c];

    float zqb = 0.f, zn = 0.f, vqa = 0.f;
    #pragma unroll 1
    for (int c = 0; c < NC; c++) {
        int bi = g_bidx[r * NC + c];
        float zq = cbk[((size_t)c * KC + bi) * LAT + lane];
        float e = enc[c];
        zqb = fmaf(e, zq, zqb);
        float d = __fsub_rn(vl, zq);
        float t = __fmul_rn(d, d);
        t += __shfl_xor_sync(0xFFFFFFFFu, t, 16);
        t += __shfl_xor_sync(0xFFFFFFFFu, t, 8);
        t += __shfl_xor_sync(0xFFFFFFFFu, t, 4);
        t += __shfl_xor_sync(0xFFFFFFFFu, t, 2);
        t += __shfl_xor_sync(0xFFFFFFFFu, t, 1);
        vqa = fmaf(e, t, vqa);
        // SF layer1: lanes m<16 compute a_m with the exact seq-l chain
        float a = 0.f;
        #pragma unroll
        for (int l = 0; l < 32; l++) {
            float db = __shfl_sync(0xFFFFFFFFu, d, l);
            a = fmaf(db, sfw1n[l * MID + (lane & 15)], a);
        }
        float mvv = gelu_ref(__fadd_rn(a, sfb1s[lane & 15]));
        // SF layer2: lane l accumulates seq-m chain
        float acc = 0.f;
        #pragma unroll
        for (int m = 0; m < MID; m++) {
            float mb = __shfl_sync(0xFFFFFFFFu, mvv, m);
            acc = fmaf(mb, sfw2s[m * LAT + lane], acc);
        }
        zn = fmaf(e, __fadd_rn(acc, sfb2s[lane]), zn);
    }

    float zgeo = __fadd_rn(__fadd_rn(cbl, zqb), zn);
    float zg = tanhf(zgeo);
    float ztv = tanhf(__fsub_rn(__fsub_rn(vl, zqb), zn));
    g_zt[r * LAT + lane] = ztv;
    if (full) {
        out[O_ZGEO + r * LAT + lane] = zgeo;
        out[O_ZN   + r * LAT + lane] = zn;
    }

    // dec softmax: lanes c<8 compute lg_c (seq-l chain), then replicate
    float lg = 0.f;
    #pragma unroll
    for (int l = 0; l < 32; l++) {
        float zb = __shfl_sync(0xFFFFFFFFu, zg, l);
        lg = fmaf(zb, lrws[l * NC + (lane & 7)], lg);
    }
    lg = __fadd_rn(lg, lrbs[lane & 7]);
    float dec[NC];
    {
        float lgv[NC];
        #pragma unroll
        for (int c = 0; c < NC; c++) lgv[c] = __shfl_sync(0xFFFFFFFFu, lg, c);
        float m = lgv[0];
        #pragma unroll
        for (int c = 1; c < NC; c++) m = fmaxf(m, lgv[c]);
        float s = 0.f;
        #pragma unroll
        for (int c = 0; c < NC; c++) { dec[c] = expf(__fsub_rn(lgv[c], m)); s = __fadd_rn(s, dec[c]); }
        #pragma unroll
        for (int c = 0; c < NC; c++) dec[c] = __fdiv_rn(dec[c], s);
    }
    if (full && lane < NC) out[O_DEC + r * NC + lane] = dec[lane];

    // stage zg and dec for the amortized h_global phase
    zg_s[warp * 33 + lane] = zg;
    if (lane == 0) {
        #pragma unroll
        for (int c = 0; c < NC; c++) dec_s[warp * NC + c] = dec[c];
    }
    if (lane == 0) redv[warp] = vqa;
    __syncthreads();

    // ---- phase 2: h_global, 4 rows per warp, one 32-wide h-block per warp ----
    // warp w: rows group g = w>>2 (rows g*4..g*4+3), h = (w&3)*32 + lane.
    // Per (row,c): a accumulates sequentially over l (identical chain to the
    // passing version); epilogue keeps the exact c-ordered add chain.
    {
        int g  = warp >> 2;
        int hb = (warp & 3) * 32;
        int h  = hb + lane;
        int row0 = g * 4;
        float a[4][NC];
        #pragma unroll
        for (int q = 0; q < 4; q++)
            #pragma unroll
            for (int c = 0; c < NC; c++) a[q][c] = 0.f;

        #pragma unroll 4
        for (int l = 0; l < 32; l++) {
            float z0 = zg_s[(row0+0) * 33 + l];
            float z1 = zg_s[(row0+1) * 33 + l];
            float z2 = zg_s[(row0+2) * 33 + l];
            float z3 = zg_s[(row0+3) * 33 + l];
            #pragma unroll
            for (int c = 0; c < NC; c++) {
                float wl = decwt[(c * 32 + l) * 128 + h];
                a[0][c] = fmaf(z0, wl, a[0][c]);
                a[1][c] = fmaf(z1, wl, a[1][c]);
                a[2][c] = fmaf(z2, wl, a[2][c]);
                a[3][c] = fmaf(z3, wl, a[3][c]);
            }
        }
        size_t rb = (size_t)blockIdx.x * KWROWS + row0;
        #pragma unroll
        for (int q = 0; q < 4; q++) {
            float acc = 0.f;
            #pragma unroll
            for (int c = 0; c < NC; c++) {
                float db = decbs[c * HID + h];
                float dc = dec_s[(row0+q) * NC + c];
                acc = __fadd_rn(acc, __fmul_rn(dc, __fadd_rn(a[q][c], db)));
            }
            g_hg[(rb + q) * HID + h] = acc;   // coalesced
        }
    }

    // vq reduce
    if (tid == 0) {
        float ssum = 0.f;
        #pragma unroll
        for (int w = 0; w < KWROWS; w++) ssum += redv[w];
        atomicAdd(&g_vq, (double)ssum);
    }
}

// ---------------- kernel C: h_global -> x_hat (unchanged) ----------------
__global__ void __launch_bounds__(256) kC(
    const float* __restrict__ rw1, const float* __restrict__ rb1,
    const float* __restrict__ rw2, const float* __restrict__ rb2,
    const float* __restrict__ skw, const float* __restrict__ skb,
    const float* __restrict__ txw, const float* __restrict__ txb,
    const float* __restrict__ tscale, float* __restrict__ out)
{
    extern __shared__ float sm[];
    float* rw1n = sm;
    float* rw2s = rw1n + HID * HID;
    float* skws = rw2s + HID * DIN;
    float* txws = skws + HID * DIN;
    float* rb1s = txws + LAT * DIN;
    float* rb2s = rb1s + HID;
    float* skbs = rb2s + DIN;
    float* txbs = skbs + DIN;

    int tid = threadIdx.x;
    for (int i = tid; i < HID * HID; i += 256) rw1n[i] = rw1[i];
    for (int i = tid; i < HID * DIN; i += 256) { rw2s[i] = rw2[i]; skws[i] = skw[i]; }
    for (int i = tid; i < LAT * DIN; i += 256) txws[i] = txw[i];
    if (tid < HID) rb1s[tid] = rb1[tid];
    if (tid < DIN) { rb2s[tid] = rb2[tid]; skbs[tid] = skb[tid]; txbs[tid] = txb[tid]; }
    __syncthreads();

    size_t r = (size_t)blockIdx.x * 256 + tid;
    float ts = tscale[0];

    const float* hgp = g_hg + r * HID;

    float hg[HID], g[HID];
    {
        const float4* h4 = (const float4*)hgp;
        #pragma unroll
        for (int i = 0; i < 32; i++) {
            float4 t = h4[i];
            hg[4*i] = t.x; hg[4*i+1] = t.y; hg[4*i+2] = t.z; hg[4*i+3] = t.w;
            g[4*i]   = gelu_ref(t.x); g[4*i+1] = gelu_ref(t.y);
            g[4*i+2] = gelu_ref(t.z); g[4*i+3] = gelu_ref(t.w);
        }
    }

    float o[DIN], sk[DIN];
    #pragma unroll
    for (int l = 0; l < DIN; l++) { o[l] = 0.f; sk[l] = 0.f; }

    for (int j = 0; j < HID; j += 4) {
        float a0 = 0.f, a1 = 0.f, a2 = 0.f, a3 = 0.f;
        #pragma unroll
        for (int i = 0; i < HID; i++) {
            float gi = g[i];
            float4 w = *(const float4*)(rw1n + i * HID + j);
            a0 = fmaf(gi, w.x, a0); a1 = fmaf(gi, w.y, a1);
            a2 = fmaf(gi, w.z, a2); a3 = fmaf(gi, w.w, a3);
        }
        float u0 = gelu_ref(__fadd_rn(a0, rb1s[j+0]));
        float u1 = gelu_ref(__fadd_rn(a1, rb1s[j+1]));
        float u2 = gelu_ref(__fadd_rn(a2, rb1s[j+2]));
        float u3 = gelu_ref(__fadd_rn(a3, rb1s[j+3]));
        const float4* r0 = (const float4*)(rw2s + (j+0) * DIN);
        const float4* r1 = (const float4*)(rw2s + (j+1) * DIN);
        const float4* r2 = (const float4*)(rw2s + (j+2) * DIN);
        const float4* r3 = (const float4*)(rw2s + (j+3) * DIN);
        #pragma unroll
        for (int l4 = 0; l4 < 8; l4++) {
            float4 w = r0[l4];
            o[4*l4]   = fmaf(u0, w.x, o[4*l4]);   o[4*l4+1] = fmaf(u0, w.y, o[4*l4+1]);
            o[4*l4+2] = fmaf(u0, w.z, o[4*l4+2]); o[4*l4+3] = fmaf(u0, w.w, o[4*l4+3]);
        }
        #pragma unroll
        for (int l4 = 0; l4 < 8; l4++) {
            float4 w = r1[l4];
            o[4*l4]   = fmaf(u1, w.x, o[4*l4]);   o[4*l4+1] = fmaf(u1, w.y, o[4*l4+1]);
            o[4*l4+2] = fmaf(u1, w.z, o[4*l4+2]); o[4*l4+3] = fmaf(u1, w.w, o[4*l4+3]);
        }
        #pragma unroll
        for (int l4 = 0; l4 < 8; l4++) {
            float4 w = r2[l4];
            o[4*l4]   = fmaf(u2, w.x, o[4*l4]);   o[4*l4+1] = fmaf(u2, w.y, o[4*l4+1]);
            o[4*l4+2] = fmaf(u2, w.z, o[4*l4+2]); o[4*l4+3] = fmaf(u2, w.w, o[4*l4+3]);
        }
        #pragma unroll
        for (int l4 = 0; l4 < 8; l4++) {
            float4 w = r3[l4];
            o[4*l4]   = fmaf(u3, w.x, o[4*l4]);   o[4*l4+1] = fmaf(u3, w.y, o[4*l4+1]);
            o[4*l4+2] = fmaf(u3, w.z, o[4*l4+2]); o[4*l4+3] = fmaf(u3, w.w, o[4*l4+3]);
        }
        const float4* s0 = (const float4*)(skws + (j+0) * DIN);
        const float4* s1 = (const float4*)(skws + (j+1) * DIN);
        const float4* s2 = (const float4*)(skws + (j+2) * DIN);
        const float4* s3 = (const float4*)(skws + (j+3) * DIN);
        float h0 = hg[j+0], h1v = hg[j+1], h2v = hg[j+2], h3v = hg[j+3];
        #pragma unroll
        for (int l4 = 0; l4 < 8; l4++) {
            float4 w = s0[l4];
            sk[4*l4]   = fmaf(h0, w.x, sk[4*l4]);   sk[4*l4+1] = fmaf(h0, w.y, sk[4*l4+1]);
            sk[4*l4+2] = fmaf(h0, w.z, sk[4*l4+2]); sk[4*l4+3] = fmaf(h0, w.w, sk[4*l4+3]);
        }
        #pragma unroll
        for (int l4 = 0; l4 < 8; l4++) {
            float4 w = s1[l4];
            sk[4*l4]   = fmaf(h1v, w.x, sk[4*l4]);   sk[4*l4+1] = fmaf(h1v, w.y, sk[4*l4+1]);
            sk[4*l4+2] = fmaf(h1v, w.z, sk[4*l4+2]); sk[4*l4+3] = fmaf(h1v, w.w, sk[4*l4+3]);
        }
        #pragma unroll
        for (int l4 = 0; l4 < 8; l4++) {
            float4 w = s2[l4];
            sk[4*l4]   = fmaf(h2v, w.x, sk[4*l4]);   sk[4*l4+1] = fmaf(h2v, w.y, sk[4*l4+1]);
            sk[4*l4+2] = fmaf(h2v, w.z, sk[4*l4+2]); sk[4*l4+3] = fmaf(h2v, w.w, sk[4*l4+3]);
        }
        #pragma unroll
        for (int l4 = 0; l4 < 8; l4++) {
            float4 w = s3[l4];
            sk[4*l4]   = fmaf(h3v, w.x, sk[4*l4]);   sk[4*l4+1] = fmaf(h3v, w.y, sk[4*l4+1]);
            sk[4*l4+2] = fmaf(h3v, w.z, sk[4*l4+2]); sk[4*l4+3] = fmaf(h3v, w.w, sk[4*l4+3]);
        }
    }

    float zt[LAT];
    {
        const float4* z4 = (const float4*)(g_zt + r * LAT);
        #pragma unroll
        for (int i = 0; i < 8; i++) {
            float4 t = z4[i];
            zt[4*i] = t.x; zt[4*i+1] = t.y; zt[4*i+2] = t.z; zt[4*i+3] = t.w;
        }
    }
    float tx[DIN];
    #pragma unroll
    for (int l = 0; l < DIN; l++) tx[l] = 0.f;
    #pragma unroll
    for (int lp = 0; lp < LAT; lp++) {
        float ztl = zt[lp];
        const float4* t4 = (const float4*)(txws + lp * DIN);
        #pragma unroll
        for (int l4 = 0; l4 < 8; l4++) {
            float4 w = t4[l4];
            tx[4*l4]   = fmaf(ztl, w.x, tx[4*l4]);   tx[4*l4+1] = fmaf(ztl, w.y, tx[4*l4+1]);
            tx[4*l4+2] = fmaf(ztl, w.z, tx[4*l4+2]); tx[4*l4+3] = fmaf(ztl, w.w, tx[4*l4+3]);
        }
    }

    float4* xo = (float4*)(out + O_XHAT + r * DIN);
    #pragma unroll
    for (int l4 = 0; l4 < 8; l4++) {
        float4 t;
        #pragma unroll
        for (int q = 0; q < 4; q++) {
            int l = 4*l4 + q;
            float mlp  = __fadd_rn(o[l], rb2s[l]);
            float skp  = __fadd_rn(sk[l], skbs[l]);
            float base = __fadd_rn(mlp, skp);
            float texv = __fmul_rn(ts, __fadd_rn(tx[l], txbs[l]));
            ((float*)&t)[q] = __fadd_rn(base, texv);
        }
        xo[l4] = t;
    }
}

// ---------------- kernel D ----------------
__global__ void kD(float* __restrict__ out, int full) {
    if (full) out[O_VQ] = (float)(1.25 * g_vq / ((double)Bsz * (double)LAT));
}

// ---------------- launch ----------------
extern "C" void kernel_launch(void* const* d_in, const int* in_sizes, int n_in,
                              void* d_out, int out_size) {
    const float* x    = (const float*)d_in[0];
    const float* fw1  = (const float*)d_in[1];
    const float* fb1  = (const float*)d_in[2];
    const float* fw2  = (const float*)d_in[3];
    const float* fb2  = (const float*)d_in[4];
    const float* vpw  = (const float*)d_in[5];
    const float* vpb  = (const float*)d_in[6];
    const float* cc   = (const float*)d_in[7];
    const float* cbk  = (const float*)d_in[8];
    const float* sfw1 = (const float*)d_in[9];
    const float* sfb1 = (const float*)d_in[10];
    const float* sfw2 = (const float*)d_in[11];
    const float* sfb2 = (const float*)d_in[12];
    const float* decw = (const float*)d_in[13];
    const float* decb = (const float*)d_in[14];
    const float* lrw  = (const float*)d_in[15];
    const float* lrb  = (const float*)d_in[16];
    const float* txw  = (const float*)d_in[17];
    const float* txb  = (const float*)d_in[18];
    const float* tsc  = (const float*)d_in[19];
    const float* rw1  = (const float*)d_in[20];
    const float* rb1  = (const float*)d_in[21];
    const float* rw2  = (const float*)d_in[22];
    const float* rb2  = (const float*)d_in[23];
    const float* skw  = (const float*)d_in[24];
    const float* skb  = (const float*)d_in[25];

    float* out = (float*)d_out;
    int full = (out_size >= O_TOTAL) ? 1 : 0;

    const int SMEM_A = (DIN*HID + HID*HID + HID*LAT + HID + HID + LAT + HID*256) * 4;
    const int SMEM_V = (KC*LAT + KC + NC*LAT + LAT*NC) * 4;
    const int SMEM_W = (NC*HID*LAT + NC*HID + LAT*MID + MID*LAT + LAT*NC + MID + LAT + NC
                        + 32 + KWROWS*33 + KWROWS*NC) * 4;
    const int SMEM_C = (HID*HID + HID*DIN + HID*DIN + LAT*DIN + HID + DIN + DIN + DIN) * 4;

    cudaFuncSetAttribute(kA, cudaFuncAttributeMaxDynamicSharedMemorySize, SMEM_A);
    cudaFuncSetAttribute(kV, cudaFuncAttributeMaxDynamicSharedMemorySize, SMEM_V);
    cudaFuncSetAttribute(kW, cudaFuncAttributeMaxDynamicSharedMemorySize, SMEM_W);
    cudaFuncSetAttribute(kC, cudaFuncAttributeMaxDynamicSharedMemorySize, SMEM_C);

    kPrep<<<16, 256>>>(cbk);
    kA<<<Bsz / 256, 256, SMEM_A>>>(x, fw1, fb1, fw2, fb2, vpw, vpb);
    kV<<<Bsz / 256, 256, SMEM_V>>>(cc, cbk, out, full);
    kW<<<Bsz / KWROWS, KWTH, SMEM_W>>>(cbk, sfw1, sfb1, sfw2, sfb2, decw, decb, lrw, lrb, out, full);
    kC<<<Bsz / 256, 256, SMEM_C>>>(rw1, rb1, rw2, rb2, skw, skb, txw, txb, tsc, out);
    kD<<<1, 1>>>(out, full);
}

// round 13
// speedup vs baseline: 1.7176x; 1.0690x over previous
#include <cuda_runtime.h>

#define Bsz 65536
#define DIN 32
#define HID 128
#define LAT 32
#define NC  8
#define KC  512
#define MID 16

// ---------------- scratch (no allocations allowed) ----------------
static __device__ float  g_v[Bsz * LAT];     // v then v_local
static __device__ float  g_cb[Bsz * LAT];
static __device__ float  g_enc[Bsz * NC];
static __device__ int    g_bidx[Bsz * NC];
static __device__ float  g_hg[Bsz * HID];
static __device__ float  g_zt[Bsz * LAT];
static __device__ float  g_cbn[NC * KC];
static __device__ double g_vq;

// ---------------- output layout (concatenated tuple, f32) ----------------
#define O_XHAT 0
#define O_VQ   (Bsz * DIN)
#define O_ENC  (O_VQ + 1)
#define O_DEC  (O_ENC + Bsz * NC)
#define O_K    (O_DEC + Bsz * NC)
#define O_ZGEO (O_K + Bsz)
#define O_ZN   (O_ZGEO + Bsz * LAT)
#define O_CBAR (O_ZN + Bsz * LAT)
#define O_TOTAL (O_CBAR + Bsz * LAT)

__device__ __forceinline__ float gelu_ref(float x) {
    float u = __fdiv_rn(x, 1.4142135623730951f);
    float t = erff(u);
    return __fmul_rn(__fmul_rn(0.5f, x), __fadd_rn(1.0f, t));
}

// ---------------- prep ----------------
__global__ void kPrep(const float* __restrict__ cbk) {
    int idx = blockIdx.x * blockDim.x + threadIdx.x;
    if (idx == 0) g_vq = 0.0;
    if (idx < NC * KC) {
        const float* row = cbk + (size_t)idx * LAT;
        float s = 0.f;
        #pragma unroll
        for (int l = 0; l < LAT; l++) s = __fadd_rn(s, __fmul_rn(row[l], row[l]));
        g_cbn[idx] = s;
    }
}

// ---------------- kernel A: x -> features -> v (unchanged) ----------------
__global__ void __launch_bounds__(256) kA(
    const float* __restrict__ x,  const float* __restrict__ w1, const float* __restrict__ b1,
    const float* __restrict__ w2, const float* __restrict__ b2,
    const float* __restrict__ vp, const float* __restrict__ vpb)
{
    extern __shared__ float sm[];
    float* w1n  = sm;
    float* w2n  = w1n + DIN * HID;
    float* vps  = w2n + HID * HID;
    float* b1s  = vps + HID * LAT;
    float* b2s  = b1s + HID;
    float* vpbs = b2s + HID;
    float* h1s  = vpbs + LAT;

    int tid = threadIdx.x;
    for (int i = tid; i < DIN * HID; i += 256) w1n[i] = w1[i];
    for (int i = tid; i < HID * HID; i += 256) w2n[i] = w2[i];
    for (int i = tid; i < HID * LAT; i += 256) vps[i] = vp[i];
    if (tid < HID) { b1s[tid] = b1[tid]; b2s[tid] = b2[tid]; }
    if (tid < LAT) vpbs[tid] = vpb[tid];
    __syncthreads();

    size_t r = (size_t)blockIdx.x * 256 + tid;

    float xr[DIN];
    {
        const float4* xp = (const float4*)(x + r * DIN);
        #pragma unroll
        for (int i = 0; i < 8; i++) {
            float4 t = xp[i];
            xr[4*i] = t.x; xr[4*i+1] = t.y; xr[4*i+2] = t.z; xr[4*i+3] = t.w;
        }
    }

    for (int j = 0; j < HID; j += 4) {
        float a0 = 0.f, a1 = 0.f, a2 = 0.f, a3 = 0.f;
        #pragma unroll
        for (int i = 0; i < DIN; i++) {
            float xi = xr[i];
            float4 w = *(const float4*)(w1n + i * HID + j);
            a0 = fmaf(xi, w.x, a0); a1 = fmaf(xi, w.y, a1);
            a2 = fmaf(xi, w.z, a2); a3 = fmaf(xi, w.w, a3);
        }
        h1s[(j+0) * 256 + tid] = gelu_ref(__fadd_rn(a0, b1s[j+0]));
        h1s[(j+1) * 256 + tid] = gelu_ref(__fadd_rn(a1, b1s[j+1]));
        h1s[(j+2) * 256 + tid] = gelu_ref(__fadd_rn(a2, b1s[j+2]));
        h1s[(j+3) * 256 + tid] = gelu_ref(__fadd_rn(a3, b1s[j+3]));
    }

    float h1[HID];
    #pragma unroll
    for (int i = 0; i < HID; i++) h1[i] = h1s[i * 256 + tid];

    float vv[LAT];
    #pragma unroll
    for (int l = 0; l < LAT; l++) vv[l] = 0.f;
    for (int j = 0; j < HID; j += 4) {
        float a0 = 0.f, a1 = 0.f, a2 = 0.f, a3 = 0.f;
        #pragma unroll
        for (int i = 0; i < HID; i++) {
            float hi = h1[i];
            float4 w = *(const float4*)(w2n + i * HID + j);
            a0 = fmaf(hi, w.x, a0); a1 = fmaf(hi, w.y, a1);
            a2 = fmaf(hi, w.z, a2); a3 = fmaf(hi, w.w, a3);
        }
        float u0 = gelu_ref(__fadd_rn(a0, b2s[j+0]));
        float u1 = gelu_ref(__fadd_rn(a1, b2s[j+1]));
        float u2 = gelu_ref(__fadd_rn(a2, b2s[j+2]));
        float u3 = gelu_ref(__fadd_rn(a3, b2s[j+3]));
        const float4* vr0 = (const float4*)(vps + (j+0) * LAT);
        const float4* vr1 = (const float4*)(vps + (j+1) * LAT);
        const float4* vr2 = (const float4*)(vps + (j+2) * LAT);
        const float4* vr3 = (const float4*)(vps + (j+3) * LAT);
        #pragma unroll
        for (int l4 = 0; l4 < 8; l4++) {
            float4 w = vr0[l4];
            vv[4*l4]   = fmaf(u0, w.x, vv[4*l4]);   vv[4*l4+1] = fmaf(u0, w.y, vv[4*l4+1]);
            vv[4*l4+2] = fmaf(u0, w.z, vv[4*l4+2]); vv[4*l4+3] = fmaf(u0, w.w, vv[4*l4+3]);
        }
        #pragma unroll
        for (int l4 = 0; l4 < 8; l4++) {
            float4 w = vr1[l4];
            vv[4*l4]   = fmaf(u1, w.x, vv[4*l4]);   vv[4*l4+1] = fmaf(u1, w.y, vv[4*l4+1]);
            vv[4*l4+2] = fmaf(u1, w.z, vv[4*l4+2]); vv[4*l4+3] = fmaf(u1, w.w, vv[4*l4+3]);
        }
        #pragma unroll
        for (int l4 = 0; l4 < 8; l4++) {
            float4 w = vr2[l4];
            vv[4*l4]   = fmaf(u2, w.x, vv[4*l4]);   vv[4*l4+1] = fmaf(u2, w.y, vv[4*l4+1]);
            vv[4*l4+2] = fmaf(u2, w.z, vv[4*l4+2]); vv[4*l4+3] = fmaf(u2, w.w, vv[4*l4+3]);
        }
        #pragma unroll
        for (int l4 = 0; l4 < 8; l4++) {
            float4 w = vr3[l4];
            vv[4*l4]   = fmaf(u3, w.x, vv[4*l4]);   vv[4*l4+1] = fmaf(u3, w.y, vv[4*l4+1]);
            vv[4*l4+2] = fmaf(u3, w.z, vv[4*l4+2]); vv[4*l4+3] = fmaf(u3, w.w, vv[4*l4+3]);
        }
    }
    float4* vo = (float4*)(g_v + r * LAT);
    #pragma unroll
    for (int l4 = 0; l4 < 8; l4++) {
        float4 t;
        t.x = __fadd_rn(vv[4*l4],   vpbs[4*l4]);
        t.y = __fadd_rn(vv[4*l4+1], vpbs[4*l4+1]);
        t.z = __fadd_rn(vv[4*l4+2], vpbs[4*l4+2]);
        t.w = __fadd_rn(vv[4*l4+3], vpbs[4*l4+3]);
        vo[l4] = t;
    }
}

// ---------------- kernel Va: softmax/K + c_bar/v_local (1 row/thread, bit-exact) ----------------
__global__ void __launch_bounds__(256) kVa(
    const float* __restrict__ cc, float* __restrict__ out, int full)
{
    __shared__ float ccs[NC * LAT];
    __shared__ float cct[LAT * NC];

    int tid = threadIdx.x;
    for (int i = tid; i < NC * LAT; i += 256) {
        float t = cc[i]; ccs[i] = t;
        int c = i / LAT, l = i % LAT;
        cct[l * NC + c] = t;
    }

    size_t r = (size_t)blockIdx.x * 256 + tid;
    float v[LAT];
    {
        const float4* vp4 = (const float4*)(g_v + r * LAT);
        #pragma unroll
        for (int i = 0; i < 8; i++) {
            float4 t = vp4[i];
            v[4*i] = t.x; v[4*i+1] = t.y; v[4*i+2] = t.z; v[4*i+3] = t.w;
        }
    }
    __syncthreads();

    // ---- enc softmax + K: BYTE-IDENTICAL to the passing version ----
    float enc[NC]; int K;
    {
        float sc[NC];
        #pragma unroll
        for (int c = 0; c < NC; c++) sc[c] = 0.f;
        #pragma unroll
        for (int l = 0; l < LAT; l++) {
            float vl = v[l];
            float4 wa = ((const float4*)(cct + l * NC))[0];
            float4 wb = ((const float4*)(cct + l * NC))[1];
            sc[0] = fmaf(vl, wa.x, sc[0]); sc[1] = fmaf(vl, wa.y, sc[1]);
            sc[2] = fmaf(vl, wa.z, sc[2]); sc[3] = fmaf(vl, wa.w, sc[3]);
            sc[4] = fmaf(vl, wb.x, sc[4]); sc[5] = fmaf(vl, wb.y, sc[5]);
            sc[6] = fmaf(vl, wb.z, sc[6]); sc[7] = fmaf(vl, wb.w, sc[7]);
        }
        #pragma unroll
        for (int c = 0; c < NC; c++) sc[c] = __fdiv_rn(sc[c], 5.656854249492381f);
        float m = sc[0];
        #pragma unroll
        for (int c = 1; c < NC; c++) m = fmaxf(m, sc[c]);
        float e[NC];
        #pragma unroll
        for (int c = 0; c < NC; c++)
            e[c] = (float)exp((double)__fsub_rn(sc[c], m));  // correctly-rounded fp32 exp
        float s01 = __fadd_rn(e[0], e[1]);
        float s23 = __fadd_rn(e[2], e[3]);
        float s45 = __fadd_rn(e[4], e[5]);
        float s67 = __fadd_rn(e[6], e[7]);
        float s = __fadd_rn(__fadd_rn(s01, s23), __fadd_rn(s45, s67));
        #pragma unroll
        for (int c = 0; c < NC; c++) enc[c] = __fdiv_rn(e[c], s);
        float bm = e[0]; K = 0;
        #pragma unroll
        for (int c = 1; c < NC; c++) if (e[c] > bm) { bm = e[c]; K = c; }
    }

    float cb[LAT];
    #pragma unroll
    for (int l = 0; l < LAT; l++) cb[l] = 0.f;
    #pragma unroll
    for (int c = 0; c < NC; c++) {
        float e = enc[c];
        #pragma unroll
        for (int l = 0; l < LAT; l++) cb[l] = fmaf(e, ccs[c * LAT + l], cb[l]);
    }
    #pragma unroll
    for (int l = 0; l < LAT; l++) v[l] = __fsub_rn(v[l], cb[l]);   // v_local

    float4* vo = (float4*)(g_v + r * LAT);
    float4* co = (float4*)(g_cb + r * LAT);
    #pragma unroll
    for (int l4 = 0; l4 < 8; l4++) {
        float4 tv, tc;
        tv.x = v[4*l4];  tv.y = v[4*l4+1];  tv.z = v[4*l4+2];  tv.w = v[4*l4+3];
        tc.x = cb[4*l4]; tc.y = cb[4*l4+1]; tc.z = cb[4*l4+2]; tc.w = cb[4*l4+3];
        vo[l4] = tv; co[l4] = tc;
    }
    #pragma unroll
    for (int c = 0; c < NC; c++) g_enc[r * NC + c] = enc[c];
    if (full) {
        #pragma unroll
        for (int c = 0; c < NC; c++) out[O_ENC + r * NC + c] = enc[c];
        out[O_K + r] = (float)K;
        #pragma unroll
        for (int l = 0; l < LAT; l++) out[O_CBAR + r * LAT + l] = cb[l];
    }
}

// ---------------- kernel Vb: VQ argmin, 2 rows/thread (codebook LDS amortized) ----------------
// Each row's accumulator chain / compare sequence is identical to the passing
// version -> bit-identical indices. One tile load + shared w0..w3 float4 loads
// feed both rows (8 FMA per LDS.128 instead of 4).
__global__ void __launch_bounds__(256, 2) kVb(
    const float* __restrict__ cbk)
{
    extern __shared__ float sm[];
    float* cbs  = sm;               // KC*LAT
    float* cbns = cbs + KC * LAT;   // KC

    int tid = threadIdx.x;
    size_t r0 = (size_t)blockIdx.x * 512 + tid;
    size_t r1 = r0 + 256;

    float v0[LAT], v1[LAT];
    {
        const float4* p0 = (const float4*)(g_v + r0 * LAT);
        const float4* p1 = (const float4*)(g_v + r1 * LAT);
        #pragma unroll
        for (int i = 0; i < 8; i++) {
            float4 t = p0[i];
            v0[4*i] = t.x; v0[4*i+1] = t.y; v0[4*i+2] = t.z; v0[4*i+3] = t.w;
            float4 u = p1[i];
            v1[4*i] = u.x; v1[4*i+1] = u.y; v1[4*i+2] = u.z; v1[4*i+3] = u.w;
        }
    }

    // ||v_local||^2 exactly as before (separate mul + seq add)
    float vn0 = 0.f, vn1 = 0.f;
    #pragma unroll
    for (int l = 0; l < LAT; l++) vn0 = __fadd_rn(vn0, __fmul_rn(v0[l], v0[l]));
    #pragma unroll
    for (int l = 0; l < LAT; l++) vn1 = __fadd_rn(vn1, __fmul_rn(v1[l], v1[l]));

    #pragma unroll 1
    for (int c = 0; c < NC; c++) {
        __syncthreads();
        const float* src = cbk + (size_t)c * KC * LAT;
        for (int i = tid; i < KC * LAT; i += 256) cbs[i] = src[i];
        for (int i = tid; i < KC; i += 256) cbns[i] = g_cbn[c * KC + i];
        __syncthreads();
        float bestA = 3.4e38f, bestB = 3.4e38f; int biA = 0, biB = 0;
        for (int k = 0; k < KC; k += 4) {
            float a0 = 0.f, a1 = 0.f, a2 = 0.f, a3 = 0.f;   // row0
            float b0 = 0.f, b1 = 0.f, b2 = 0.f, b3 = 0.f;   // row1
            const float* rp0 = cbs + (k+0) * LAT;
            const float* rp1 = cbs + (k+1) * LAT;
            const float* rp2 = cbs + (k+2) * LAT;
            const float* rp3 = cbs + (k+3) * LAT;
            #pragma unroll
            for (int i = 0; i < 8; i++) {
                float4 w0 = ((const float4*)rp0)[i];
                float4 w1 = ((const float4*)rp1)[i];
                float4 w2 = ((const float4*)rp2)[i];
                float4 w3 = ((const float4*)rp3)[i];
                a0 = fmaf(v0[4*i], w0.x, a0); a0 = fmaf(v0[4*i+1], w0.y, a0);
                a0 = fmaf(v0[4*i+2], w0.z, a0); a0 = fmaf(v0[4*i+3], w0.w, a0);
                a1 = fmaf(v0[4*i], w1.x, a1); a1 = fmaf(v0[4*i+1], w1.y, a1);
                a1 = fmaf(v0[4*i+2], w1.z, a1); a1 = fmaf(v0[4*i+3], w1.w, a1);
                a2 = fmaf(v0[4*i], w2.x, a2); a2 = fmaf(v0[4*i+1], w2.y, a2);
                a2 = fmaf(v0[4*i+2], w2.z, a2); a2 = fmaf(v0[4*i+3], w2.w, a2);
                a3 = fmaf(v0[4*i], w3.x, a3); a3 = fmaf(v0[4*i+1], w3.y, a3);
                a3 = fmaf(v0[4*i+2], w3.z, a3); a3 = fmaf(v0[4*i+3], w3.w, a3);
                b0 = fmaf(v1[4*i], w0.x, b0); b0 = fmaf(v1[4*i+1], w0.y, b0);
                b0 = fmaf(v1[4*i+2], w0.z, b0); b0 = fmaf(v1[4*i+3], w0.w, b0);
                b1 = fmaf(v1[4*i], w1.x, b1); b1 = fmaf(v1[4*i+1], w1.y, b1);
                b1 = fmaf(v1[4*i+2], w1.z, b1); b1 = fmaf(v1[4*i+3], w1.w, b1);
                b2 = fmaf(v1[4*i], w2.x, b2); b2 = fmaf(v1[4*i+1], w2.y, b2);
                b2 = fmaf(v1[4*i+2], w2.z, b2); b2 = fmaf(v1[4*i+3], w2.w, b2);
                b3 = fmaf(v1[4*i], w3.x, b3); b3 = fmaf(v1[4*i+1], w3.y, b3);
                b3 = fmaf(v1[4*i+2], w3.z, b3); b3 = fmaf(v1[4*i+3], w3.w, b3);
            }
            float n0 = cbns[k+0], n1 = cbns[k+1], n2 = cbns[k+2], n3 = cbns[k+3];
            float dA0 = __fadd_rn(__fsub_rn(vn0, __fmul_rn(2.0f, a0)), n0);
            float dA1 = __fadd_rn(__fsub_rn(vn0, __fmul_rn(2.0f, a1)), n1);
            float dA2 = __fadd_rn(__fsub_rn(vn0, __fmul_rn(2.0f, a2)), n2);
            float dA3 = __fadd_rn(__fsub_rn(vn0, __fmul_rn(2.0f, a3)), n3);
            if (dA0 < bestA) { bestA = dA0; biA = k+0; }
            if (dA1 < bestA) { bestA = dA1; biA = k+1; }
            if (dA2 < bestA) { bestA = dA2; biA = k+2; }
            if (dA3 < bestA) { bestA = dA3; biA = k+3; }
            float dB0 = __fadd_rn(__fsub_rn(vn1, __fmul_rn(2.0f, b0)), n0);
            float dB1 = __fadd_rn(__fsub_rn(vn1, __fmul_rn(2.0f, b1)), n1);
            float dB2 = __fadd_rn(__fsub_rn(vn1, __fmul_rn(2.0f, b2)), n2);
            float dB3 = __fadd_rn(__fsub_rn(vn1, __fmul_rn(2.0f, b3)), n3);
            if (dB0 < bestB) { bestB = dB0; biB = k+0; }
            if (dB1 < bestB) { bestB = dB1; biB = k+1; }
            if (dB2 < bestB) { bestB = dB2; biB = k+2; }
            if (dB3 < bestB) { bestB = dB3; biB = k+3; }
        }
        g_bidx[r0 * NC + c] = biA;
        g_bidx[r1 * NC + c] = biB;
    }
}

// ---------------- kernel W: warp-per-row phase1 + row-amortized h_global (unchanged) ----------------
#define KWTH 1024
#define KWROWS (KWTH / 32)
__global__ void __launch_bounds__(KWTH, 1) kW(
    const float* __restrict__ cbk,
    const float* __restrict__ sfw1, const float* __restrict__ sfb1,
    const float* __restrict__ sfw2, const float* __restrict__ sfb2,
    const float* __restrict__ decw, const float* __restrict__ decb,
    const float* __restrict__ lrw,  const float* __restrict__ lrb,
    float* __restrict__ out, int full)
{
    extern __shared__ float sm[];
    float* decwt = sm;                       // 32768: [(c*32+l)*128 + h]
    float* decbs = decwt + NC * HID * LAT;   // 1024
    float* sfw1n = decbs + NC * HID;         // 512 [l*16+m]
    float* sfw2s = sfw1n + LAT * MID;        // 512 [m*32+l]
    float* lrws  = sfw2s + MID * LAT;        // 256 [l*8+c]
    float* sfb1s = lrws + LAT * NC;          // 16
    float* sfb2s = sfb1s + MID;              // 32
    float* lrbs  = sfb2s + LAT;              // 8
    float* redv  = lrbs + NC;                // 32
    float* zg_s  = redv + 32;                // 32 rows * 33 = 1056
    float* dec_s = zg_s + KWROWS * 33;       // 32 rows * 8 = 256

    int tid = threadIdx.x;
    for (int i = tid; i < NC * HID * LAT; i += KWTH) {
        int c = i >> 12; int rem = i & 4095; int h = rem >> 5; int l = rem & 31;
        decwt[(c * 32 + l) * 128 + h] = decw[i];
    }
    for (int i = tid; i < NC * HID; i += KWTH) decbs[i] = decb[i];
    for (int i = tid; i < LAT * MID; i += KWTH) sfw1n[i] = sfw1[i];
    for (int i = tid; i < MID * LAT; i += KWTH) sfw2s[i] = sfw2[i];
    for (int i = tid; i < LAT * NC; i += KWTH) lrws[i] = lrw[i];
    if (tid < MID) sfb1s[tid] = sfb1[tid];
    if (tid < LAT) sfb2s[tid] = sfb2[tid];
    if (tid < NC)  lrbs[tid] = lrb[tid];
    __syncthreads();

    int warp = tid >> 5, lane = tid & 31;
    size_t r = (size_t)blockIdx.x * KWROWS + warp;

    float vl  = g_v[r * LAT + lane];    // coalesced
    float cbl = g_cb[r * LAT + lane];
    float enc[NC];
    #pragma unroll
    for (int c = 0; c < NC; c++) enc[c] = g_enc[r * NC + c];

    float zqb = 0.f, zn = 0.f, vqa = 0.f;
    #pragma unroll 1
    for (int c = 0; c < NC; c++) {
        int bi = g_bidx[r * NC + c];
        float zq = cbk[((size_t)c * KC + bi) * LAT + lane];
        float e = enc[c];
        zqb = fmaf(e, zq, zqb);
        float d = __fsub_rn(vl, zq);
        float t = __fmul_rn(d, d);
        t += __shfl_xor_sync(0xFFFFFFFFu, t, 16);
        t += __shfl_xor_sync(0xFFFFFFFFu, t, 8);
        t += __shfl_xor_sync(0xFFFFFFFFu, t, 4);
        t += __shfl_xor_sync(0xFFFFFFFFu, t, 2);
        t += __shfl_xor_sync(0xFFFFFFFFu, t, 1);
        vqa = fmaf(e, t, vqa);
        float a = 0.f;
        #pragma unroll
        for (int l = 0; l < 32; l++) {
            float db = __shfl_sync(0xFFFFFFFFu, d, l);
            a = fmaf(db, sfw1n[l * MID + (lane & 15)], a);
        }
        float mvv = gelu_ref(__fadd_rn(a, sfb1s[lane & 15]));
        float acc = 0.f;
        #pragma unroll
        for (int m = 0; m < MID; m++) {
            float mb = __shfl_sync(0xFFFFFFFFu, mvv, m);
            acc = fmaf(mb, sfw2s[m * LAT + lane], acc);
        }
        zn = fmaf(e, __fadd_rn(acc, sfb2s[lane]), zn);
    }

    float zgeo = __fadd_rn(__fadd_rn(cbl, zqb), zn);
    float zg = tanhf(zgeo);
    float ztv = tanhf(__fsub_rn(__fsub_rn(vl, zqb), zn));
    g_zt[r * LAT + lane] = ztv;
    if (full) {
        out[O_ZGEO + r * LAT + lane] = zgeo;
        out[O_ZN   + r * LAT + lane] = zn;
    }

    float lg = 0.f;
    #pragma unroll
    for (int l = 0; l < 32; l++) {
        float zb = __shfl_sync(0xFFFFFFFFu, zg, l);
        lg = fmaf(zb, lrws[l * NC + (lane & 7)], lg);
    }
    lg = __fadd_rn(lg, lrbs[lane & 7]);
    float dec[NC];
    {
        float lgv[NC];
        #pragma unroll
        for (int c = 0; c < NC; c++) lgv[c] = __shfl_sync(0xFFFFFFFFu, lg, c);
        float m = lgv[0];
        #pragma unroll
        for (int c = 1; c < NC; c++) m = fmaxf(m, lgv[c]);
        float s = 0.f;
        #pragma unroll
        for (int c = 0; c < NC; c++) { dec[c] = expf(__fsub_rn(lgv[c], m)); s = __fadd_rn(s, dec[c]); }
        #pragma unroll
        for (int c = 0; c < NC; c++) dec[c] = __fdiv_rn(dec[c], s);
    }
    if (full && lane < NC) out[O_DEC + r * NC + lane] = dec[lane];

    zg_s[warp * 33 + lane] = zg;
    if (lane == 0) {
        #pragma unroll
        for (int c = 0; c < NC; c++) dec_s[warp * NC + c] = dec[c];
    }
    if (lane == 0) redv[warp] = vqa;
    __syncthreads();

    {
        int g  = warp >> 2;
        int hb = (warp & 3) * 32;
        int h  = hb + lane;
        int row0 = g * 4;
        float a[4][NC];
        #pragma unroll
        for (int q = 0; q < 4; q++)
            #pragma unroll
            for (int c = 0; c < NC; c++) a[q][c] = 0.f;

        #pragma unroll 4
        for (int l = 0; l < 32; l++) {
            float z0 = zg_s[(row0+0) * 33 + l];
            float z1 = zg_s[(row0+1) * 33 + l];
            float z2 = zg_s[(row0+2) * 33 + l];
            float z3 = zg_s[(row0+3) * 33 + l];
            #pragma unroll
            for (int c = 0; c < NC; c++) {
                float wl = decwt[(c * 32 + l) * 128 + h];
                a[0][c] = fmaf(z0, wl, a[0][c]);
                a[1][c] = fmaf(z1, wl, a[1][c]);
                a[2][c] = fmaf(z2, wl, a[2][c]);
                a[3][c] = fmaf(z3, wl, a[3][c]);
            }
        }
        size_t rb = (size_t)blockIdx.x * KWROWS + row0;
        #pragma unroll
        for (int q = 0; q < 4; q++) {
            float acc = 0.f;
            #pragma unroll
            for (int c = 0; c < NC; c++) {
                float db = decbs[c * HID + h];
                float dc = dec_s[(row0+q) * NC + c];
                acc = __fadd_rn(acc, __fmul_rn(dc, __fadd_rn(a[q][c], db)));
            }
            g_hg[(rb + q) * HID + h] = acc;
        }
    }

    if (tid == 0) {
        float ssum = 0.f;
        #pragma unroll
        for (int w = 0; w < KWROWS; w++) ssum += redv[w];
        atomicAdd(&g_vq, (double)ssum);
    }
}

// ---------------- kernel C: h_global -> x_hat (unchanged) ----------------
__global__ void __launch_bounds__(256) kC(
    const float* __restrict__ rw1, const float* __restrict__ rb1,
    const float* __restrict__ rw2, const float* __restrict__ rb2,
    const float* __restrict__ skw, const float* __restrict__ skb,
    const float* __restrict__ txw, const float* __restrict__ txb,
    const float* __restrict__ tscale, float* __restrict__ out)
{
    extern __shared__ float sm[];
    float* rw1n = sm;
    float* rw2s = rw1n + HID * HID;
    float* skws = rw2s + HID * DIN;
    float* txws = skws + HID * DIN;
    float* rb1s = txws + LAT * DIN;
    float* rb2s = rb1s + HID;
    float* skbs = rb2s + DIN;
    float* txbs = skbs + DIN;

    int tid = threadIdx.x;
    for (int i = tid; i < HID * HID; i += 256) rw1n[i] = rw1[i];
    for (int i = tid; i < HID * DIN; i += 256) { rw2s[i] = rw2[i]; skws[i] = skw[i]; }
    for (int i = tid; i < LAT * DIN; i += 256) txws[i] = txw[i];
    if (tid < HID) rb1s[tid] = rb1[tid];
    if (tid < DIN) { rb2s[tid] = rb2[tid]; skbs[tid] = skb[tid]; txbs[tid] = txb[tid]; }
    __syncthreads();

    size_t r = (size_t)blockIdx.x * 256 + tid;
    float ts = tscale[0];

    const float* hgp = g_hg + r * HID;

    float hg[HID], g[HID];
    {
        const float4* h4 = (const float4*)hgp;
        #pragma unroll
        for (int i = 0; i < 32; i++) {
            float4 t = h4[i];
            hg[4*i] = t.x; hg[4*i+1] = t.y; hg[4*i+2] = t.z; hg[4*i+3] = t.w;
            g[4*i]   = gelu_ref(t.x); g[4*i+1] = gelu_ref(t.y);
            g[4*i+2] = gelu_ref(t.z); g[4*i+3] = gelu_ref(t.w);
        }
    }

    float o[DIN], sk[DIN];
    #pragma unroll
    for (int l = 0; l < DIN; l++) { o[l] = 0.f; sk[l] = 0.f; }

    for (int j = 0; j < HID; j += 4) {
        float a0 = 0.f, a1 = 0.f, a2 = 0.f, a3 = 0.f;
        #pragma unroll
        for (int i = 0; i < HID; i++) {
            float gi = g[i];
            float4 w = *(const float4*)(rw1n + i * HID + j);
            a0 = fmaf(gi, w.x, a0); a1 = fmaf(gi, w.y, a1);
            a2 = fmaf(gi, w.z, a2); a3 = fmaf(gi, w.w, a3);
        }
        float u0 = gelu_ref(__fadd_rn(a0, rb1s[j+0]));
        float u1 = gelu_ref(__fadd_rn(a1, rb1s[j+1]));
        float u2 = gelu_ref(__fadd_rn(a2, rb1s[j+2]));
        float u3 = gelu_ref(__fadd_rn(a3, rb1s[j+3]));
        const float4* r0 = (const float4*)(rw2s + (j+0) * DIN);
        const float4* r1 = (const float4*)(rw2s + (j+1) * DIN);
        const float4* r2 = (const float4*)(rw2s + (j+2) * DIN);
        const float4* r3 = (const float4*)(rw2s + (j+3) * DIN);
        #pragma unroll
        for (int l4 = 0; l4 < 8; l4++) {
            float4 w = r0[l4];
            o[4*l4]   = fmaf(u0, w.x, o[4*l4]);   o[4*l4+1] = fmaf(u0, w.y, o[4*l4+1]);
            o[4*l4+2] = fmaf(u0, w.z, o[4*l4+2]); o[4*l4+3] = fmaf(u0, w.w, o[4*l4+3]);
        }
        #pragma unroll
        for (int l4 = 0; l4 < 8; l4++) {
            float4 w = r1[l4];
            o[4*l4]   = fmaf(u1, w.x, o[4*l4]);   o[4*l4+1] = fmaf(u1, w.y, o[4*l4+1]);
            o[4*l4+2] = fmaf(u1, w.z, o[4*l4+2]); o[4*l4+3] = fmaf(u1, w.w, o[4*l4+3]);
        }
        #pragma unroll
        for (int l4 = 0; l4 < 8; l4++) {
            float4 w = r2[l4];
            o[4*l4]   = fmaf(u2, w.x, o[4*l4]);   o[4*l4+1] = fmaf(u2, w.y, o[4*l4+1]);
            o[4*l4+2] = fmaf(u2, w.z, o[4*l4+2]); o[4*l4+3] = fmaf(u2, w.w, o[4*l4+3]);
        }
        #pragma unroll
        for (int l4 = 0; l4 < 8; l4++) {
            float4 w = r3[l4];
            o[4*l4]   = fmaf(u3, w.x, o[4*l4]);   o[4*l4+1] = fmaf(u3, w.y, o[4*l4+1]);
            o[4*l4+2] = fmaf(u3, w.z, o[4*l4+2]); o[4*l4+3] = fmaf(u3, w.w, o[4*l4+3]);
        }
        const float4* s0 = (const float4*)(skws + (j+0) * DIN);
        const float4* s1 = (const float4*)(skws + (j+1) * DIN);
        const float4* s2 = (const float4*)(skws + (j+2) * DIN);
        const float4* s3 = (const float4*)(skws + (j+3) * DIN);
        float h0 = hg[j+0], h1v = hg[j+1], h2v = hg[j+2], h3v = hg[j+3];
        #pragma unroll
        for (int l4 = 0; l4 < 8; l4++) {
            float4 w = s0[l4];
            sk[4*l4]   = fmaf(h0, w.x, sk[4*l4]);   sk[4*l4+1] = fmaf(h0, w.y, sk[4*l4+1]);
            sk[4*l4+2] = fmaf(h0, w.z, sk[4*l4+2]); sk[4*l4+3] = fmaf(h0, w.w, sk[4*l4+3]);
        }
        #pragma unroll
        for (int l4 = 0; l4 < 8; l4++) {
            float4 w = s1[l4];
            sk[4*l4]   = fmaf(h1v, w.x, sk[4*l4]);   sk[4*l4+1] = fmaf(h1v, w.y, sk[4*l4+1]);
            sk[4*l4+2] = fmaf(h1v, w.z, sk[4*l4+2]); sk[4*l4+3] = fmaf(h1v, w.w, sk[4*l4+3]);
        }
        #pragma unroll
        for (int l4 = 0; l4 < 8; l4++) {
            float4 w = s2[l4];
            sk[4*l4]   = fmaf(h2v, w.x, sk[4*l4]);   sk[4*l4+1] = fmaf(h2v, w.y, sk[4*l4+1]);
            sk[4*l4+2] = fmaf(h2v, w.z, sk[4*l4+2]); sk[4*l4+3] = fmaf(h2v, w.w, sk[4*l4+3]);
        }
        #pragma unroll
        for (int l4 = 0; l4 < 8; l4++) {
            float4 w = s3[l4];
            sk[4*l4]   = fmaf(h3v, w.x, sk[4*l4]);   sk[4*l4+1] = fmaf(h3v, w.y, sk[4*l4+1]);
            sk[4*l4+2] = fmaf(h3v, w.z, sk[4*l4+2]); sk[4*l4+3] = fmaf(h3v, w.w, sk[4*l4+3]);
        }
    }

    float zt[LAT];
    {
        const float4* z4 = (const float4*)(g_zt + r * LAT);
        #pragma unroll
        for (int i = 0; i < 8; i++) {
            float4 t = z4[i];
            zt[4*i] = t.x; zt[4*i+1] = t.y; zt[4*i+2] = t.z; zt[4*i+3] = t.w;
        }
    }
    float tx[DIN];
    #pragma unroll
    for (int l = 0; l < DIN; l++) tx[l] = 0.f;
    #pragma unroll
    for (int lp = 0; lp < LAT; lp++) {
        float ztl = zt[lp];
        const float4* t4 = (const float4*)(txws + lp * DIN);
        #pragma unroll
        for (int l4 = 0; l4 < 8; l4++) {
            float4 w = t4[l4];
            tx[4*l4]   = fmaf(ztl, w.x, tx[4*l4]);   tx[4*l4+1] = fmaf(ztl, w.y, tx[4*l4+1]);
            tx[4*l4+2] = fmaf(ztl, w.z, tx[4*l4+2]); tx[4*l4+3] = fmaf(ztl, w.w, tx[4*l4+3]);
        }
    }

    float4* xo = (float4*)(out + O_XHAT + r * DIN);
    #pragma unroll
    for (int l4 = 0; l4 < 8; l4++) {
        float4 t;
        #pragma unroll
        for (int q = 0; q < 4; q++) {
            int l = 4*l4 + q;
            float mlp  = __fadd_rn(o[l], rb2s[l]);
            float skp  = __fadd_rn(sk[l], skbs[l]);
            float base = __fadd_rn(mlp, skp);
            float texv = __fmul_rn(ts, __fadd_rn(tx[l], txbs[l]));
            ((float*)&t)[q] = __fadd_rn(base, texv);
        }
        xo[l4] = t;
    }
}

// ---------------- kernel D ----------------
__global__ void kD(float* __restrict__ out, int full) {
    if (full) out[O_VQ] = (float)(1.25 * g_vq / ((double)Bsz * (double)LAT));
}

// ---------------- launch ----------------
extern "C" void kernel_launch(void* const* d_in, const int* in_sizes, int n_in,
                              void* d_out, int out_size) {
    const float* x    = (const float*)d_in[0];
    const float* fw1  = (const float*)d_in[1];
    const float* fb1  = (const float*)d_in[2];
    const float* fw2  = (const float*)d_in[3];
    const float* fb2  = (const float*)d_in[4];
    const float* vpw  = (const float*)d_in[5];
    const float* vpb  = (const float*)d_in[6];
    const float* cc   = (const float*)d_in[7];
    const float* cbk  = (const float*)d_in[8];
    const float* sfw1 = (const float*)d_in[9];
    const float* sfb1 = (const float*)d_in[10];
    const float* sfw2 = (const float*)d_in[11];
    const float* sfb2 = (const float*)d_in[12];
    const float* decw = (const float*)d_in[13];
    const float* decb = (const float*)d_in[14];
    const float* lrw  = (const float*)d_in[15];
    const float* lrb  = (const float*)d_in[16];
    const float* txw  = (const float*)d_in[17];
    const float* txb  = (const float*)d_in[18];
    const float* tsc  = (const float*)d_in[19];
    const float* rw1  = (const float*)d_in[20];
    const float* rb1  = (const float*)d_in[21];
    const float* rw2  = (const float*)d_in[22];
    const float* rb2  = (const float*)d_in[23];
    const float* skw  = (const float*)d_in[24];
    const float* skb  = (const float*)d_in[25];

    float* out = (float*)d_out;
    int full = (out_size >= O_TOTAL) ? 1 : 0;

    const int SMEM_A  = (DIN*HID + HID*HID + HID*LAT + HID + HID + LAT + HID*256) * 4;
    const int SMEM_VB = (KC*LAT + KC) * 4;
    const int SMEM_W  = (NC*HID*LAT + NC*HID + LAT*MID + MID*LAT + LAT*NC + MID + LAT + NC
                         + 32 + KWROWS*33 + KWROWS*NC) * 4;
    const int SMEM_C  = (HID*HID + HID*DIN + HID*DIN + LAT*DIN + HID + DIN + DIN + DIN) * 4;

    cudaFuncSetAttribute(kA,  cudaFuncAttributeMaxDynamicSharedMemorySize, SMEM_A);
    cudaFuncSetAttribute(kVb, cudaFuncAttributeMaxDynamicSharedMemorySize, SMEM_VB);
    cudaFuncSetAttribute(kW,  cudaFuncAttributeMaxDynamicSharedMemorySize, SMEM_W);
    cudaFuncSetAttribute(kC,  cudaFuncAttributeMaxDynamicSharedMemorySize, SMEM_C);

    kPrep<<<16, 256>>>(cbk);
    kA<<<Bsz / 256, 256, SMEM_A>>>(x, fw1, fb1, fw2, fb2, vpw, vpb);
    kVa<<<Bsz / 256, 256>>>(cc, out, full);
    kVb<<<Bsz / 512, 256, SMEM_VB>>>(cbk);
    kW<<<Bsz / KWROWS, KWTH, SMEM_W>>>(cbk, sfw1, sfb1, sfw2, sfb2, decw, decb, lrw, lrb, out, full);
    kC<<<Bsz / 256, 256, SMEM_C>>>(rw1, rb1, rw2, rb2, skw, skb, txw, txb, tsc, out);
    kD<<<1, 1>>>(out, full);
}

// round 15
// speedup vs baseline: 1.8686x; 1.0879x over previous
#include <cuda_runtime.h>

#define Bsz 65536
#define DIN 32
#define HID 128
#define LAT 32
#define NC  8
#define KC  512
#define MID 16

// ---------------- scratch (no allocations allowed) ----------------
static __device__ float  g_v[Bsz * LAT];     // v then v_local
static __device__ float  g_cb[Bsz * LAT];
static __device__ float  g_enc[Bsz * NC];
static __device__ int    g_bidx[Bsz * NC];
static __device__ float  g_hg[Bsz * HID];
static __device__ float  g_zt[Bsz * LAT];
static __device__ float  g_cbn[NC * KC];
static __device__ double g_vq;

// ---------------- output layout (concatenated tuple, f32) ----------------
#define O_XHAT 0
#define O_VQ   (Bsz * DIN)
#define O_ENC  (O_VQ + 1)
#define O_DEC  (O_ENC + Bsz * NC)
#define O_K    (O_DEC + Bsz * NC)
#define O_ZGEO (O_K + Bsz)
#define O_ZN   (O_ZGEO + Bsz * LAT)
#define O_CBAR (O_ZN + Bsz * LAT)
#define O_TOTAL (O_CBAR + Bsz * LAT)

__device__ __forceinline__ float gelu_ref(float x) {
    float u = __fdiv_rn(x, 1.4142135623730951f);
    float t = erff(u);
    return __fmul_rn(__fmul_rn(0.5f, x), __fadd_rn(1.0f, t));
}

// ---------------- prep ----------------
__global__ void kPrep(const float* __restrict__ cbk) {
    int idx = blockIdx.x * blockDim.x + threadIdx.x;
    if (idx == 0) g_vq = 0.0;
    if (idx < NC * KC) {
        const float* row = cbk + (size_t)idx * LAT;
        float s = 0.f;
        #pragma unroll
        for (int l = 0; l < LAT; l++) s = __fadd_rn(s, __fmul_rn(row[l], row[l]));
        g_cbn[idx] = s;
    }
}

// ---------------- kernel A: x -> features -> v (unchanged) ----------------
__global__ void __launch_bounds__(256) kA(
    const float* __restrict__ x,  const float* __restrict__ w1, const float* __restrict__ b1,
    const float* __restrict__ w2, const float* __restrict__ b2,
    const float* __restrict__ vp, const float* __restrict__ vpb)
{
    extern __shared__ float sm[];
    float* w1n  = sm;
    float* w2n  = w1n + DIN * HID;
    float* vps  = w2n + HID * HID;
    float* b1s  = vps + HID * LAT;
    float* b2s  = b1s + HID;
    float* vpbs = b2s + HID;
    float* h1s  = vpbs + LAT;

    int tid = threadIdx.x;
    for (int i = tid; i < DIN * HID; i += 256) w1n[i] = w1[i];
    for (int i = tid; i < HID * HID; i += 256) w2n[i] = w2[i];
    for (int i = tid; i < HID * LAT; i += 256) vps[i] = vp[i];
    if (tid < HID) { b1s[tid] = b1[tid]; b2s[tid] = b2[tid]; }
    if (tid < LAT) vpbs[tid] = vpb[tid];
    __syncthreads();

    size_t r = (size_t)blockIdx.x * 256 + tid;

    float xr[DIN];
    {
        const float4* xp = (const float4*)(x + r * DIN);
        #pragma unroll
        for (int i = 0; i < 8; i++) {
            float4 t = xp[i];
            xr[4*i] = t.x; xr[4*i+1] = t.y; xr[4*i+2] = t.z; xr[4*i+3] = t.w;
        }
    }

    for (int j = 0; j < HID; j += 4) {
        float a0 = 0.f, a1 = 0.f, a2 = 0.f, a3 = 0.f;
        #pragma unroll
        for (int i = 0; i < DIN; i++) {
            float xi = xr[i];
            float4 w = *(const float4*)(w1n + i * HID + j);
            a0 = fmaf(xi, w.x, a0); a1 = fmaf(xi, w.y, a1);
            a2 = fmaf(xi, w.z, a2); a3 = fmaf(xi, w.w, a3);
        }
        h1s[(j+0) * 256 + tid] = gelu_ref(__fadd_rn(a0, b1s[j+0]));
        h1s[(j+1) * 256 + tid] = gelu_ref(__fadd_rn(a1, b1s[j+1]));
        h1s[(j+2) * 256 + tid] = gelu_ref(__fadd_rn(a2, b1s[j+2]));
        h1s[(j+3) * 256 + tid] = gelu_ref(__fadd_rn(a3, b1s[j+3]));
    }

    float h1[HID];
    #pragma unroll
    for (int i = 0; i < HID; i++) h1[i] = h1s[i * 256 + tid];

    float vv[LAT];
    #pragma unroll
    for (int l = 0; l < LAT; l++) vv[l] = 0.f;
    for (int j = 0; j < HID; j += 4) {
        float a0 = 0.f, a1 = 0.f, a2 = 0.f, a3 = 0.f;
        #pragma unroll
        for (int i = 0; i < HID; i++) {
            float hi = h1[i];
            float4 w = *(const float4*)(w2n + i * HID + j);
            a0 = fmaf(hi, w.x, a0); a1 = fmaf(hi, w.y, a1);
            a2 = fmaf(hi, w.z, a2); a3 = fmaf(hi, w.w, a3);
        }
        float u0 = gelu_ref(__fadd_rn(a0, b2s[j+0]));
        float u1 = gelu_ref(__fadd_rn(a1, b2s[j+1]));
        float u2 = gelu_ref(__fadd_rn(a2, b2s[j+2]));
        float u3 = gelu_ref(__fadd_rn(a3, b2s[j+3]));
        const float4* vr0 = (const float4*)(vps + (j+0) * LAT);
        const float4* vr1 = (const float4*)(vps + (j+1) * LAT);
        const float4* vr2 = (const float4*)(vps + (j+2) * LAT);
        const float4* vr3 = (const float4*)(vps + (j+3) * LAT);
        #pragma unroll
        for (int l4 = 0; l4 < 8; l4++) {
            float4 w = vr0[l4];
            vv[4*l4]   = fmaf(u0, w.x, vv[4*l4]);   vv[4*l4+1] = fmaf(u0, w.y, vv[4*l4+1]);
            vv[4*l4+2] = fmaf(u0, w.z, vv[4*l4+2]); vv[4*l4+3] = fmaf(u0, w.w, vv[4*l4+3]);
        }
        #pragma unroll
        for (int l4 = 0; l4 < 8; l4++) {
            float4 w = vr1[l4];
            vv[4*l4]   = fmaf(u1, w.x, vv[4*l4]);   vv[4*l4+1] = fmaf(u1, w.y, vv[4*l4+1]);
            vv[4*l4+2] = fmaf(u1, w.z, vv[4*l4+2]); vv[4*l4+3] = fmaf(u1, w.w, vv[4*l4+3]);
        }
        #pragma unroll
        for (int l4 = 0; l4 < 8; l4++) {
            float4 w = vr2[l4];
            vv[4*l4]   = fmaf(u2, w.x, vv[4*l4]);   vv[4*l4+1] = fmaf(u2, w.y, vv[4*l4+1]);
            vv[4*l4+2] = fmaf(u2, w.z, vv[4*l4+2]); vv[4*l4+3] = fmaf(u2, w.w, vv[4*l4+3]);
        }
        #pragma unroll
        for (int l4 = 0; l4 < 8; l4++) {
            float4 w = vr3[l4];
            vv[4*l4]   = fmaf(u3, w.x, vv[4*l4]);   vv[4*l4+1] = fmaf(u3, w.y, vv[4*l4+1]);
            vv[4*l4+2] = fmaf(u3, w.z, vv[4*l4+2]); vv[4*l4+3] = fmaf(u3, w.w, vv[4*l4+3]);
        }
    }
    float4* vo = (float4*)(g_v + r * LAT);
    #pragma unroll
    for (int l4 = 0; l4 < 8; l4++) {
        float4 t;
        t.x = __fadd_rn(vv[4*l4],   vpbs[4*l4]);
        t.y = __fadd_rn(vv[4*l4+1], vpbs[4*l4+1]);
        t.z = __fadd_rn(vv[4*l4+2], vpbs[4*l4+2]);
        t.w = __fadd_rn(vv[4*l4+3], vpbs[4*l4+3]);
        vo[l4] = t;
    }
}

// ---------------- kernel Va: softmax/K + c_bar/v_local (1 row/thread, bit-exact) ----------------
__global__ void __launch_bounds__(256) kVa(
    const float* __restrict__ cc, float* __restrict__ out, int full)
{
    __shared__ float ccs[NC * LAT];
    __shared__ float cct[LAT * NC];

    int tid = threadIdx.x;
    for (int i = tid; i < NC * LAT; i += 256) {
        float t = cc[i]; ccs[i] = t;
        int c = i / LAT, l = i % LAT;
        cct[l * NC + c] = t;
    }

    size_t r = (size_t)blockIdx.x * 256 + tid;
    float v[LAT];
    {
        const float4* vp4 = (const float4*)(g_v + r * LAT);
        #pragma unroll
        for (int i = 0; i < 8; i++) {
            float4 t = vp4[i];
            v[4*i] = t.x; v[4*i+1] = t.y; v[4*i+2] = t.z; v[4*i+3] = t.w;
        }
    }
    __syncthreads();

    // ---- enc softmax + K: BYTE-IDENTICAL to the passing version ----
    float enc[NC]; int K;
    {
        float sc[NC];
        #pragma unroll
        for (int c = 0; c < NC; c++) sc[c] = 0.f;
        #pragma unroll
        for (int l = 0; l < LAT; l++) {
            float vl = v[l];
            float4 wa = ((const float4*)(cct + l * NC))[0];
            float4 wb = ((const float4*)(cct + l * NC))[1];
            sc[0] = fmaf(vl, wa.x, sc[0]); sc[1] = fmaf(vl, wa.y, sc[1]);
            sc[2] = fmaf(vl, wa.z, sc[2]); sc[3] = fmaf(vl, wa.w, sc[3]);
            sc[4] = fmaf(vl, wb.x, sc[4]); sc[5] = fmaf(vl, wb.y, sc[5]);
            sc[6] = fmaf(vl, wb.z, sc[6]); sc[7] = fmaf(vl, wb.w, sc[7]);
        }
        #pragma unroll
        for (int c = 0; c < NC; c++) sc[c] = __fdiv_rn(sc[c], 5.656854249492381f);
        float m = sc[0];
        #pragma unroll
        for (int c = 1; c < NC; c++) m = fmaxf(m, sc[c]);
        float e[NC];
        #pragma unroll
        for (int c = 0; c < NC; c++)
            e[c] = (float)exp((double)__fsub_rn(sc[c], m));  // correctly-rounded fp32 exp
        float s01 = __fadd_rn(e[0], e[1]);
        float s23 = __fadd_rn(e[2], e[3]);
        float s45 = __fadd_rn(e[4], e[5]);
        float s67 = __fadd_rn(e[6], e[7]);
        float s = __fadd_rn(__fadd_rn(s01, s23), __fadd_rn(s45, s67));
        #pragma unroll
        for (int c = 0; c < NC; c++) enc[c] = __fdiv_rn(e[c], s);
        float bm = e[0]; K = 0;
        #pragma unroll
        for (int c = 1; c < NC; c++) if (e[c] > bm) { bm = e[c]; K = c; }
    }

    float cb[LAT];
    #pragma unroll
    for (int l = 0; l < LAT; l++) cb[l] = 0.f;
    #pragma unroll
    for (int c = 0; c < NC; c++) {
        float e = enc[c];
        #pragma unroll
        for (int l = 0; l < LAT; l++) cb[l] = fmaf(e, ccs[c * LAT + l], cb[l]);
    }
    #pragma unroll
    for (int l = 0; l < LAT; l++) v[l] = __fsub_rn(v[l], cb[l]);   // v_local

    float4* vo = (float4*)(g_v + r * LAT);
    float4* co = (float4*)(g_cb + r * LAT);
    #pragma unroll
    for (int l4 = 0; l4 < 8; l4++) {
        float4 tv, tc;
        tv.x = v[4*l4];  tv.y = v[4*l4+1];  tv.z = v[4*l4+2];  tv.w = v[4*l4+3];
        tc.x = cb[4*l4]; tc.y = cb[4*l4+1]; tc.z = cb[4*l4+2]; tc.w = cb[4*l4+3];
        vo[l4] = tv; co[l4] = tc;
    }
    #pragma unroll
    for (int c = 0; c < NC; c++) g_enc[r * NC + c] = enc[c];
    if (full) {
        #pragma unroll
        for (int c = 0; c < NC; c++) out[O_ENC + r * NC + c] = enc[c];
        out[O_K + r] = (float)K;
        #pragma unroll
        for (int l = 0; l < LAT; l++) out[O_CBAR + r * LAT + l] = cb[l];
    }
}

// ---------------- kernel Vb: VQ argmin, chart-split across blocks ----------------
// Block b: chart c = b & 7, row-group rg = b >> 3 (512 rows, 2 per thread).
// Grid = 1024 -> full SM coverage, 2 blocks/SM. Per-(row,chart) arithmetic is
// byte-identical to the passing version -> bit-identical indices.
__global__ void __launch_bounds__(256, 2) kVb(
    const float* __restrict__ cbk)
{
    extern __shared__ float sm[];
    float* cbs  = sm;               // KC*LAT
    float* cbns = cbs + KC * LAT;   // KC

    int tid = threadIdx.x;
    int c   = blockIdx.x & 7;
    int rg  = blockIdx.x >> 3;
    size_t r0 = (size_t)rg * 512 + tid;
    size_t r1 = r0 + 256;

    // tile load for this block's chart
    {
        const float* src = cbk + (size_t)c * KC * LAT;
        for (int i = tid; i < KC * LAT; i += 256) cbs[i] = src[i];
        for (int i = tid; i < KC; i += 256) cbns[i] = g_cbn[c * KC + i];
    }

    float v0[LAT], v1[LAT];
    {
        const float4* p0 = (const float4*)(g_v + r0 * LAT);
        const float4* p1 = (const float4*)(g_v + r1 * LAT);
        #pragma unroll
        for (int i = 0; i < 8; i++) {
            float4 t = p0[i];
            v0[4*i] = t.x; v0[4*i+1] = t.y; v0[4*i+2] = t.z; v0[4*i+3] = t.w;
            float4 u = p1[i];
            v1[4*i] = u.x; v1[4*i+1] = u.y; v1[4*i+2] = u.z; v1[4*i+3] = u.w;
        }
    }

    // ||v_local||^2 exactly as before (separate mul + seq add)
    float vn0 = 0.f, vn1 = 0.f;
    #pragma unroll
    for (int l = 0; l < LAT; l++) vn0 = __fadd_rn(vn0, __fmul_rn(v0[l], v0[l]));
    #pragma unroll
    for (int l = 0; l < LAT; l++) vn1 = __fadd_rn(vn1, __fmul_rn(v1[l], v1[l]));

    __syncthreads();

    float bestA = 3.4e38f, bestB = 3.4e38f; int biA = 0, biB = 0;
    for (int k = 0; k < KC; k += 4) {
        float a0 = 0.f, a1 = 0.f, a2 = 0.f, a3 = 0.f;   // row0
        float b0 = 0.f, b1 = 0.f, b2 = 0.f, b3 = 0.f;   // row1
        const float* rp0 = cbs + (k+0) * LAT;
        const float* rp1 = cbs + (k+1) * LAT;
        const float* rp2 = cbs + (k+2) * LAT;
        const float* rp3 = cbs + (k+3) * LAT;
        #pragma unroll
        for (int i = 0; i < 8; i++) {
            float4 w0 = ((const float4*)rp0)[i];
            float4 w1 = ((const float4*)rp1)[i];
            float4 w2 = ((const float4*)rp2)[i];
            float4 w3 = ((const float4*)rp3)[i];
            a0 = fmaf(v0[4*i], w0.x, a0); a0 = fmaf(v0[4*i+1], w0.y, a0);
            a0 = fmaf(v0[4*i+2], w0.z, a0); a0 = fmaf(v0[4*i+3], w0.w, a0);
            a1 = fmaf(v0[4*i], w1.x, a1); a1 = fmaf(v0[4*i+1], w1.y, a1);
            a1 = fmaf(v0[4*i+2], w1.z, a1); a1 = fmaf(v0[4*i+3], w1.w, a1);
            a2 = fmaf(v0[4*i], w2.x, a2); a2 = fmaf(v0[4*i+1], w2.y, a2);
            a2 = fmaf(v0[4*i+2], w2.z, a2); a2 = fmaf(v0[4*i+3], w2.w, a2);
            a3 = fmaf(v0[4*i], w3.x, a3); a3 = fmaf(v0[4*i+1], w3.y, a3);
            a3 = fmaf(v0[4*i+2], w3.z, a3); a3 = fmaf(v0[4*i+3], w3.w, a3);
            b0 = fmaf(v1[4*i], w0.x, b0); b0 = fmaf(v1[4*i+1], w0.y, b0);
            b0 = fmaf(v1[4*i+2], w0.z, b0); b0 = fmaf(v1[4*i+3], w0.w, b0);
            b1 = fmaf(v1[4*i], w1.x, b1); b1 = fmaf(v1[4*i+1], w1.y, b1);
            b1 = fmaf(v1[4*i+2], w1.z, b1); b1 = fmaf(v1[4*i+3], w1.w, b1);
            b2 = fmaf(v1[4*i], w2.x, b2); b2 = fmaf(v1[4*i+1], w2.y, b2);
            b2 = fmaf(v1[4*i+2], w2.z, b2); b2 = fmaf(v1[4*i+3], w2.w, b2);
            b3 = fmaf(v1[4*i], w3.x, b3); b3 = fmaf(v1[4*i+1], w3.y, b3);
            b3 = fmaf(v1[4*i+2], w3.z, b3); b3 = fmaf(v1[4*i+3], w3.w, b3);
        }
        float n0 = cbns[k+0], n1 = cbns[k+1], n2 = cbns[k+2], n3 = cbns[k+3];
        float dA0 = __fadd_rn(__fsub_rn(vn0, __fmul_rn(2.0f, a0)), n0);
        float dA1 = __fadd_rn(__fsub_rn(vn0, __fmul_rn(2.0f, a1)), n1);
        float dA2 = __fadd_rn(__fsub_rn(vn0, __fmul_rn(2.0f, a2)), n2);
        float dA3 = __fadd_rn(__fsub_rn(vn0, __fmul_rn(2.0f, a3)), n3);
        if (dA0 < bestA) { bestA = dA0; biA = k+0; }
        if (dA1 < bestA) { bestA = dA1; biA = k+1; }
        if (dA2 < bestA) { bestA = dA2; biA = k+2; }
        if (dA3 < bestA) { bestA = dA3; biA = k+3; }
        float dB0 = __fadd_rn(__fsub_rn(vn1, __fmul_rn(2.0f, b0)), n0);
        float dB1 = __fadd_rn(__fsub_rn(vn1, __fmul_rn(2.0f, b1)), n1);
        float dB2 = __fadd_rn(__fsub_rn(vn1, __fmul_rn(2.0f, b2)), n2);
        float dB3 = __fadd_rn(__fsub_rn(vn1, __fmul_rn(2.0f, b3)), n3);
        if (dB0 < bestB) { bestB = dB0; biB = k+0; }
        if (dB1 < bestB) { bestB = dB1; biB = k+1; }
        if (dB2 < bestB) { bestB = dB2; biB = k+2; }
        if (dB3 < bestB) { bestB = dB3; biB = k+3; }
    }
    g_bidx[r0 * NC + c] = biA;
    g_bidx[r1 * NC + c] = biB;
}

// ---------------- kernel W: warp-per-row phase1 + row-amortized h_global (unchanged) ----------------
#define KWTH 1024
#define KWROWS (KWTH / 32)
__global__ void __launch_bounds__(KWTH, 1) kW(
    const float* __restrict__ cbk,
    const float* __restrict__ sfw1, const float* __restrict__ sfb1,
    const float* __restrict__ sfw2, const float* __restrict__ sfb2,
    const float* __restrict__ decw, const float* __restrict__ decb,
    const float* __restrict__ lrw,  const float* __restrict__ lrb,
    float* __restrict__ out, int full)
{
    extern __shared__ float sm[];
    float* decwt = sm;                       // 32768: [(c*32+l)*128 + h]
    float* decbs = decwt + NC * HID * LAT;   // 1024
    float* sfw1n = decbs + NC * HID;         // 512 [l*16+m]
    float* sfw2s = sfw1n + LAT * MID;        // 512 [m*32+l]
    float* lrws  = sfw2s + MID * LAT;        // 256 [l*8+c]
    float* sfb1s = lrws + LAT * NC;          // 16
    float* sfb2s = sfb1s + MID;              // 32
    float* lrbs  = sfb2s + LAT;              // 8
    float* redv  = lrbs + NC;                // 32
    float* zg_s  = redv + 32;                // 32 rows * 33 = 1056
    float* dec_s = zg_s + KWROWS * 33;       // 32 rows * 8 = 256

    int tid = threadIdx.x;
    for (int i = tid; i < NC * HID * LAT; i += KWTH) {
        int c = i >> 12; int rem = i & 4095; int h = rem >> 5; int l = rem & 31;
        decwt[(c * 32 + l) * 128 + h] = decw[i];
    }
    for (int i = tid; i < NC * HID; i += KWTH) decbs[i] = decb[i];
    for (int i = tid; i < LAT * MID; i += KWTH) sfw1n[i] = sfw1[i];
    for (int i = tid; i < MID * LAT; i += KWTH) sfw2s[i] = sfw2[i];
    for (int i = tid; i < LAT * NC; i += KWTH) lrws[i] = lrw[i];
    if (tid < MID) sfb1s[tid] = sfb1[tid];
    if (tid < LAT) sfb2s[tid] = sfb2[tid];
    if (tid < NC)  lrbs[tid] = lrb[tid];
    __syncthreads();

    int warp = tid >> 5, lane = tid & 31;
    size_t r = (size_t)blockIdx.x * KWROWS + warp;

    float vl  = g_v[r * LAT + lane];    // coalesced
    float cbl = g_cb[r * LAT + lane];
    float enc[NC];
    #pragma unroll
    for (int c = 0; c < NC; c++) enc[c] = g_enc[r * NC + c];

    float zqb = 0.f, zn = 0.f, vqa = 0.f;
    #pragma unroll 1
    for (int c = 0; c < NC; c++) {
        int bi = g_bidx[r * NC + c];
        float zq = cbk[((size_t)c * KC + bi) * LAT + lane];
        float e = enc[c];
        zqb = fmaf(e, zq, zqb);
        float d = __fsub_rn(vl, zq);
        float t = __fmul_rn(d, d);
        t += __shfl_xor_sync(0xFFFFFFFFu, t, 16);
        t += __shfl_xor_sync(0xFFFFFFFFu, t, 8);
        t += __shfl_xor_sync(0xFFFFFFFFu, t, 4);
        t += __shfl_xor_sync(0xFFFFFFFFu, t, 2);
        t += __shfl_xor_sync(0xFFFFFFFFu, t, 1);
        vqa = fmaf(e, t, vqa);
        float a = 0.f;
        #pragma unroll
        for (int l = 0; l < 32; l++) {
            float db = __shfl_sync(0xFFFFFFFFu, d, l);
            a = fmaf(db, sfw1n[l * MID + (lane & 15)], a);
        }
        float mvv = gelu_ref(__fadd_rn(a, sfb1s[lane & 15]));
        float acc = 0.f;
        #pragma unroll
        for (int m = 0; m < MID; m++) {
            float mb = __shfl_sync(0xFFFFFFFFu, mvv, m);
            acc = fmaf(mb, sfw2s[m * LAT + lane], acc);
        }
        zn = fmaf(e, __fadd_rn(acc, sfb2s[lane]), zn);
    }

    float zgeo = __fadd_rn(__fadd_rn(cbl, zqb), zn);
    float zg = tanhf(zgeo);
    float ztv = tanhf(__fsub_rn(__fsub_rn(vl, zqb), zn));
    g_zt[r * LAT + lane] = ztv;
    if (full) {
        out[O_ZGEO + r * LAT + lane] = zgeo;
        out[O_ZN   + r * LAT + lane] = zn;
    }

    float lg = 0.f;
    #pragma unroll
    for (int l = 0; l < 32; l++) {
        float zb = __shfl_sync(0xFFFFFFFFu, zg, l);
        lg = fmaf(zb, lrws[l * NC + (lane & 7)], lg);
    }
    lg = __fadd_rn(lg, lrbs[lane & 7]);
    float dec[NC];
    {
        float lgv[NC];
        #pragma unroll
        for (int c = 0; c < NC; c++) lgv[c] = __shfl_sync(0xFFFFFFFFu, lg, c);
        float m = lgv[0];
        #pragma unroll
        for (int c = 1; c < NC; c++) m = fmaxf(m, lgv[c]);
        float s = 0.f;
        #pragma unroll
        for (int c = 0; c < NC; c++) { dec[c] = expf(__fsub_rn(lgv[c], m)); s = __fadd_rn(s, dec[c]); }
        #pragma unroll
        for (int c = 0; c < NC; c++) dec[c] = __fdiv_rn(dec[c], s);
    }
    if (full && lane < NC) out[O_DEC + r * NC + lane] = dec[lane];

    zg_s[warp * 33 + lane] = zg;
    if (lane == 0) {
        #pragma unroll
        for (int c = 0; c < NC; c++) dec_s[warp * NC + c] = dec[c];
    }
    if (lane == 0) redv[warp] = vqa;
    __syncthreads();

    {
        int g  = warp >> 2;
        int hb = (warp & 3) * 32;
        int h  = hb + lane;
        int row0 = g * 4;
        float a[4][NC];
        #pragma unroll
        for (int q = 0; q < 4; q++)
            #pragma unroll
            for (int c = 0; c < NC; c++) a[q][c] = 0.f;

        #pragma unroll 4
        for (int l = 0; l < 32; l++) {
            float z0 = zg_s[(row0+0) * 33 + l];
            float z1 = zg_s[(row0+1) * 33 + l];
            float z2 = zg_s[(row0+2) * 33 + l];
            float z3 = zg_s[(row0+3) * 33 + l];
            #pragma unroll
            for (int c = 0; c < NC; c++) {
                float wl = decwt[(c * 32 + l) * 128 + h];
                a[0][c] = fmaf(z0, wl, a[0][c]);
                a[1][c] = fmaf(z1, wl, a[1][c]);
                a[2][c] = fmaf(z2, wl, a[2][c]);
                a[3][c] = fmaf(z3, wl, a[3][c]);
            }
        }
        size_t rb = (size_t)blockIdx.x * KWROWS + row0;
        #pragma unroll
        for (int q = 0; q < 4; q++) {
            float acc = 0.f;
            #pragma unroll
            for (int c = 0; c < NC; c++) {
                float db = decbs[c * HID + h];
                float dc = dec_s[(row0+q) * NC + c];
                acc = __fadd_rn(acc, __fmul_rn(dc, __fadd_rn(a[q][c], db)));
            }
            g_hg[(rb + q) * HID + h] = acc;
        }
    }

    if (tid == 0) {
        float ssum = 0.f;
        #pragma unroll
        for (int w = 0; w < KWROWS; w++) ssum += redv[w];
        atomicAdd(&g_vq, (double)ssum);
    }
}

// ---------------- kernel C: h_global -> x_hat (unchanged) ----------------
__global__ void __launch_bounds__(256) kC(
    const float* __restrict__ rw1, const float* __restrict__ rb1,
    const float* __restrict__ rw2, const float* __restrict__ rb2,
    const float* __restrict__ skw, const float* __restrict__ skb,
    const float* __restrict__ txw, const float* __restrict__ txb,
    const float* __restrict__ tscale, float* __restrict__ out)
{
    extern __shared__ float sm[];
    float* rw1n = sm;
    float* rw2s = rw1n + HID * HID;
    float* skws = rw2s + HID * DIN;
    float* txws = skws + HID * DIN;
    float* rb1s = txws + LAT * DIN;
    float* rb2s = rb1s + HID;
    float* skbs = rb2s + DIN;
    float* txbs = skbs + DIN;

    int tid = threadIdx.x;
    for (int i = tid; i < HID * HID; i += 256) rw1n[i] = rw1[i];
    for (int i = tid; i < HID * DIN; i += 256) { rw2s[i] = rw2[i]; skws[i] = skw[i]; }
    for (int i = tid; i < LAT * DIN; i += 256) txws[i] = txw[i];
    if (tid < HID) rb1s[tid] = rb1[tid];
    if (tid < DIN) { rb2s[tid] = rb2[tid]; skbs[tid] = skb[tid]; txbs[tid] = txb[tid]; }
    __syncthreads();

    size_t r = (size_t)blockIdx.x * 256 + tid;
    float ts = tscale[0];

    const float* hgp = g_hg + r * HID;

    float hg[HID], g[HID];
    {
        const float4* h4 = (const float4*)hgp;
        #pragma unroll
        for (int i = 0; i < 32; i++) {
            float4 t = h4[i];
            hg[4*i] = t.x; hg[4*i+1] = t.y; hg[4*i+2] = t.z; hg[4*i+3] = t.w;
            g[4*i]   = gelu_ref(t.x); g[4*i+1] = gelu_ref(t.y);
            g[4*i+2] = gelu_ref(t.z); g[4*i+3] = gelu_ref(t.w);
        }
    }

    float o[DIN], sk[DIN];
    #pragma unroll
    for (int l = 0; l < DIN; l++) { o[l] = 0.f; sk[l] = 0.f; }

    for (int j = 0; j < HID; j += 4) {
        float a0 = 0.f, a1 = 0.f, a2 = 0.f, a3 = 0.f;
        #pragma unroll
        for (int i = 0; i < HID; i++) {
            float gi = g[i];
            float4 w = *(const float4*)(rw1n + i * HID + j);
            a0 = fmaf(gi, w.x, a0); a1 = fmaf(gi, w.y, a1);
            a2 = fmaf(gi, w.z, a2); a3 = fmaf(gi, w.w, a3);
        }
        float u0 = gelu_ref(__fadd_rn(a0, rb1s[j+0]));
        float u1 = gelu_ref(__fadd_rn(a1, rb1s[j+1]));
        float u2 = gelu_ref(__fadd_rn(a2, rb1s[j+2]));
        float u3 = gelu_ref(__fadd_rn(a3, rb1s[j+3]));
        const float4* r0 = (const float4*)(rw2s + (j+0) * DIN);
        const float4* r1 = (const float4*)(rw2s + (j+1) * DIN);
        const float4* r2 = (const float4*)(rw2s + (j+2) * DIN);
        const float4* r3 = (const float4*)(rw2s + (j+3) * DIN);
        #pragma unroll
        for (int l4 = 0; l4 < 8; l4++) {
            float4 w = r0[l4];
            o[4*l4]   = fmaf(u0, w.x, o[4*l4]);   o[4*l4+1] = fmaf(u0, w.y, o[4*l4+1]);
            o[4*l4+2] = fmaf(u0, w.z, o[4*l4+2]); o[4*l4+3] = fmaf(u0, w.w, o[4*l4+3]);
        }
        #pragma unroll
        for (int l4 = 0; l4 < 8; l4++) {
            float4 w = r1[l4];
            o[4*l4]   = fmaf(u1, w.x, o[4*l4]);   o[4*l4+1] = fmaf(u1, w.y, o[4*l4+1]);
            o[4*l4+2] = fmaf(u1, w.z, o[4*l4+2]); o[4*l4+3] = fmaf(u1, w.w, o[4*l4+3]);
        }
        #pragma unroll
        for (int l4 = 0; l4 < 8; l4++) {
            float4 w = r2[l4];
            o[4*l4]   = fmaf(u2, w.x, o[4*l4]);   o[4*l4+1] = fmaf(u2, w.y, o[4*l4+1]);
            o[4*l4+2] = fmaf(u2, w.z, o[4*l4+2]); o[4*l4+3] = fmaf(u2, w.w, o[4*l4+3]);
        }
        #pragma unroll
        for (int l4 = 0; l4 < 8; l4++) {
            float4 w = r3[l4];
            o[4*l4]   = fmaf(u3, w.x, o[4*l4]);   o[4*l4+1] = fmaf(u3, w.y, o[4*l4+1]);
            o[4*l4+2] = fmaf(u3, w.z, o[4*l4+2]); o[4*l4+3] = fmaf(u3, w.w, o[4*l4+3]);
        }
        const float4* s0 = (const float4*)(skws + (j+0) * DIN);
        const float4* s1 = (const float4*)(skws + (j+1) * DIN);
        const float4* s2 = (const float4*)(skws + (j+2) * DIN);
        const float4* s3 = (const float4*)(skws + (j+3) * DIN);
        float h0 = hg[j+0], h1v = hg[j+1], h2v = hg[j+2], h3v = hg[j+3];
        #pragma unroll
        for (int l4 = 0; l4 < 8; l4++) {
            float4 w = s0[l4];
            sk[4*l4]   = fmaf(h0, w.x, sk[4*l4]);   sk[4*l4+1] = fmaf(h0, w.y, sk[4*l4+1]);
            sk[4*l4+2] = fmaf(h0, w.z, sk[4*l4+2]); sk[4*l4+3] = fmaf(h0, w.w, sk[4*l4+3]);
        }
        #pragma unroll
        for (int l4 = 0; l4 < 8; l4++) {
            float4 w = s1[l4];
            sk[4*l4]   = fmaf(h1v, w.x, sk[4*l4]);   sk[4*l4+1] = fmaf(h1v, w.y, sk[4*l4+1]);
            sk[4*l4+2] = fmaf(h1v, w.z, sk[4*l4+2]); sk[4*l4+3] = fmaf(h1v, w.w, sk[4*l4+3]);
        }
        #pragma unroll
        for (int l4 = 0; l4 < 8; l4++) {
            float4 w = s2[l4];
            sk[4*l4]   = fmaf(h2v, w.x, sk[4*l4]);   sk[4*l4+1] = fmaf(h2v, w.y, sk[4*l4+1]);
            sk[4*l4+2] = fmaf(h2v, w.z, sk[4*l4+2]); sk[4*l4+3] = fmaf(h2v, w.w, sk[4*l4+3]);
        }
        #pragma unroll
        for (int l4 = 0; l4 < 8; l4++) {
            float4 w = s3[l4];
            sk[4*l4]   = fmaf(h3v, w.x, sk[4*l4]);   sk[4*l4+1] = fmaf(h3v, w.y, sk[4*l4+1]);
            sk[4*l4+2] = fmaf(h3v, w.z, sk[4*l4+2]); sk[4*l4+3] = fmaf(h3v, w.w, sk[4*l4+3]);
        }
    }

    float zt[LAT];
    {
        const float4* z4 = (const float4*)(g_zt + r * LAT);
        #pragma unroll
        for (int i = 0; i < 8; i++) {
            float4 t = z4[i];
            zt[4*i] = t.x; zt[4*i+1] = t.y; zt[4*i+2] = t.z; zt[4*i+3] = t.w;
        }
    }
    float tx[DIN];
    #pragma unroll
    for (int l = 0; l < DIN; l++) tx[l] = 0.f;
    #pragma unroll
    for (int lp = 0; lp < LAT; lp++) {
        float ztl = zt[lp];
        const float4* t4 = (const float4*)(txws + lp * DIN);
        #pragma unroll
        for (int l4 = 0; l4 < 8; l4++) {
            float4 w = t4[l4];
            tx[4*l4]   = fmaf(ztl, w.x, tx[4*l4]);   tx[4*l4+1] = fmaf(ztl, w.y, tx[4*l4+1]);
            tx[4*l4+2] = fmaf(ztl, w.z, tx[4*l4+2]); tx[4*l4+3] = fmaf(ztl, w.w, tx[4*l4+3]);
        }
    }

    float4* xo = (float4*)(out + O_XHAT + r * DIN);
    #pragma unroll
    for (int l4 = 0; l4 < 8; l4++) {
        float4 t;
        #pragma unroll
        for (int q = 0; q < 4; q++) {
            int l = 4*l4 + q;
            float mlp  = __fadd_rn(o[l], rb2s[l]);
            float skp  = __fadd_rn(sk[l], skbs[l]);
            float base = __fadd_rn(mlp, skp);
            float texv = __fmul_rn(ts, __fadd_rn(tx[l], txbs[l]));
            ((float*)&t)[q] = __fadd_rn(base, texv);
        }
        xo[l4] = t;
    }
}

// ---------------- kernel D ----------------
__global__ void kD(float* __restrict__ out, int full) {
    if (full) out[O_VQ] = (float)(1.25 * g_vq / ((double)Bsz * (double)LAT));
}

// ---------------- launch ----------------
extern "C" void kernel_launch(void* const* d_in, const int* in_sizes, int n_in,
                              void* d_out, int out_size) {
    const float* x    = (const float*)d_in[0];
    const float* fw1  = (const float*)d_in[1];
    const float* fb1  = (const float*)d_in[2];
    const float* fw2  = (const float*)d_in[3];
    const float* fb2  = (const float*)d_in[4];
    const float* vpw  = (const float*)d_in[5];
    const float* vpb  = (const float*)d_in[6];
    const float* cc   = (const float*)d_in[7];
    const float* cbk  = (const float*)d_in[8];
    const float* sfw1 = (const float*)d_in[9];
    const float* sfb1 = (const float*)d_in[10];
    const float* sfw2 = (const float*)d_in[11];
    const float* sfb2 = (const float*)d_in[12];
    const float* decw = (const float*)d_in[13];
    const float* decb = (const float*)d_in[14];
    const float* lrw  = (const float*)d_in[15];
    const float* lrb  = (const float*)d_in[16];
    const float* txw  = (const float*)d_in[17];
    const float* txb  = (const float*)d_in[18];
    const float* tsc  = (const float*)d_in[19];
    const float* rw1  = (const float*)d_in[20];
    const float* rb1  = (const float*)d_in[21];
    const float* rw2  = (const float*)d_in[22];
    const float* rb2  = (const float*)d_in[23];
    const float* skw  = (const float*)d_in[24];
    const float* skb  = (const float*)d_in[25];

    float* out = (float*)d_out;
    int full = (out_size >= O_TOTAL) ? 1 : 0;

    const int SMEM_A  = (DIN*HID + HID*HID + HID*LAT + HID + HID + LAT + HID*256) * 4;
    const int SMEM_VB = (KC*LAT + KC) * 4;
    const int SMEM_W  = (NC*HID*LAT + NC*HID + LAT*MID + MID*LAT + LAT*NC + MID + LAT + NC
                         + 32 + KWROWS*33 + KWROWS*NC) * 4;
    const int SMEM_C  = (HID*HID + HID*DIN + HID*DIN + LAT*DIN + HID + DIN + DIN + DIN) * 4;

    cudaFuncSetAttribute(kA,  cudaFuncAttributeMaxDynamicSharedMemorySize, SMEM_A);
    cudaFuncSetAttribute(kVb, cudaFuncAttributeMaxDynamicSharedMemorySize, SMEM_VB);
    cudaFuncSetAttribute(kW,  cudaFuncAttributeMaxDynamicSharedMemorySize, SMEM_W);
    cudaFuncSetAttribute(kC,  cudaFuncAttributeMaxDynamicSharedMemorySize, SMEM_C);

    kPrep<<<16, 256>>>(cbk);
    kA<<<Bsz / 256, 256, SMEM_A>>>(x, fw1, fb1, fw2, fb2, vpw, vpb);
    kVa<<<Bsz / 256, 256>>>(cc, out, full);
    kVb<<<(Bsz / 512) * NC, 256, SMEM_VB>>>(cbk);
    kW<<<Bsz / KWROWS, KWTH, SMEM_W>>>(cbk, sfw1, sfb1, sfw2, sfb2, decw, decb, lrw, lrb, out, full);
    kC<<<Bsz / 256, 256, SMEM_C>>>(rw1, rb1, rw2, rb2, skw, skb, txw, txb, tsc, out);
    kD<<<1, 1>>>(out, full);
}

// round 16
// speedup vs baseline: 1.9143x; 1.0245x over previous
#include <cuda_runtime.h>

#define Bsz 65536
#define DIN 32
#define HID 128
#define LAT 32
#define NC  8
#define KC  512
#define MID 16

// ---------------- scratch (no allocations allowed) ----------------
static __device__ float  g_v[Bsz * LAT];     // v then v_local
static __device__ float  g_cb[Bsz * LAT];
static __device__ float  g_enc[Bsz * NC];
static __device__ int    g_bidx[Bsz * NC];
static __device__ float  g_hg[Bsz * HID];
static __device__ float  g_zt[Bsz * LAT];
static __device__ float  g_cbn[NC * KC];
static __device__ double g_vq;

// ---------------- output layout (concatenated tuple, f32) ----------------
#define O_XHAT 0
#define O_VQ   (Bsz * DIN)
#define O_ENC  (O_VQ + 1)
#define O_DEC  (O_ENC + Bsz * NC)
#define O_K    (O_DEC + Bsz * NC)
#define O_ZGEO (O_K + Bsz)
#define O_ZN   (O_ZGEO + Bsz * LAT)
#define O_CBAR (O_ZN + Bsz * LAT)
#define O_TOTAL (O_CBAR + Bsz * LAT)

__device__ __forceinline__ float gelu_ref(float x) {
    float u = __fdiv_rn(x, 1.4142135623730951f);
    float t = erff(u);
    return __fmul_rn(__fmul_rn(0.5f, x), __fadd_rn(1.0f, t));
}

// ---------------- prep ----------------
__global__ void kPrep(const float* __restrict__ cbk) {
    int idx = blockIdx.x * blockDim.x + threadIdx.x;
    if (idx == 0) g_vq = 0.0;
    if (idx < NC * KC) {
        const float* row = cbk + (size_t)idx * LAT;
        float s = 0.f;
        #pragma unroll
        for (int l = 0; l < LAT; l++) s = __fadd_rn(s, __fmul_rn(row[l], row[l]));
        g_cbn[idx] = s;
    }
}

// ---------------- kernel A: x -> features -> v (unchanged, bit-exact) ----------------
__global__ void __launch_bounds__(256) kA(
    const float* __restrict__ x,  const float* __restrict__ w1, const float* __restrict__ b1,
    const float* __restrict__ w2, const float* __restrict__ b2,
    const float* __restrict__ vp, const float* __restrict__ vpb)
{
    extern __shared__ float sm[];
    float* w1n  = sm;
    float* w2n  = w1n + DIN * HID;
    float* vps  = w2n + HID * HID;
    float* b1s  = vps + HID * LAT;
    float* b2s  = b1s + HID;
    float* vpbs = b2s + HID;
    float* h1s  = vpbs + LAT;

    int tid = threadIdx.x;
    for (int i = tid; i < DIN * HID; i += 256) w1n[i] = w1[i];
    for (int i = tid; i < HID * HID; i += 256) w2n[i] = w2[i];
    for (int i = tid; i < HID * LAT; i += 256) vps[i] = vp[i];
    if (tid < HID) { b1s[tid] = b1[tid]; b2s[tid] = b2[tid]; }
    if (tid < LAT) vpbs[tid] = vpb[tid];
    __syncthreads();

    size_t r = (size_t)blockIdx.x * 256 + tid;

    float xr[DIN];
    {
        const float4* xp = (const float4*)(x + r * DIN);
        #pragma unroll
        for (int i = 0; i < 8; i++) {
            float4 t = xp[i];
            xr[4*i] = t.x; xr[4*i+1] = t.y; xr[4*i+2] = t.z; xr[4*i+3] = t.w;
        }
    }

    for (int j = 0; j < HID; j += 4) {
        float a0 = 0.f, a1 = 0.f, a2 = 0.f, a3 = 0.f;
        #pragma unroll
        for (int i = 0; i < DIN; i++) {
            float xi = xr[i];
            float4 w = *(const float4*)(w1n + i * HID + j);
            a0 = fmaf(xi, w.x, a0); a1 = fmaf(xi, w.y, a1);
            a2 = fmaf(xi, w.z, a2); a3 = fmaf(xi, w.w, a3);
        }
        h1s[(j+0) * 256 + tid] = gelu_ref(__fadd_rn(a0, b1s[j+0]));
        h1s[(j+1) * 256 + tid] = gelu_ref(__fadd_rn(a1, b1s[j+1]));
        h1s[(j+2) * 256 + tid] = gelu_ref(__fadd_rn(a2, b1s[j+2]));
        h1s[(j+3) * 256 + tid] = gelu_ref(__fadd_rn(a3, b1s[j+3]));
    }

    float h1[HID];
    #pragma unroll
    for (int i = 0; i < HID; i++) h1[i] = h1s[i * 256 + tid];

    float vv[LAT];
    #pragma unroll
    for (int l = 0; l < LAT; l++) vv[l] = 0.f;
    for (int j = 0; j < HID; j += 4) {
        float a0 = 0.f, a1 = 0.f, a2 = 0.f, a3 = 0.f;
        #pragma unroll
        for (int i = 0; i < HID; i++) {
            float hi = h1[i];
            float4 w = *(const float4*)(w2n + i * HID + j);
            a0 = fmaf(hi, w.x, a0); a1 = fmaf(hi, w.y, a1);
            a2 = fmaf(hi, w.z, a2); a3 = fmaf(hi, w.w, a3);
        }
        float u0 = gelu_ref(__fadd_rn(a0, b2s[j+0]));
        float u1 = gelu_ref(__fadd_rn(a1, b2s[j+1]));
        float u2 = gelu_ref(__fadd_rn(a2, b2s[j+2]));
        float u3 = gelu_ref(__fadd_rn(a3, b2s[j+3]));
        const float4* vr0 = (const float4*)(vps + (j+0) * LAT);
        const float4* vr1 = (const float4*)(vps + (j+1) * LAT);
        const float4* vr2 = (const float4*)(vps + (j+2) * LAT);
        const float4* vr3 = (const float4*)(vps + (j+3) * LAT);
        #pragma unroll
        for (int l4 = 0; l4 < 8; l4++) {
            float4 w = vr0[l4];
            vv[4*l4]   = fmaf(u0, w.x, vv[4*l4]);   vv[4*l4+1] = fmaf(u0, w.y, vv[4*l4+1]);
            vv[4*l4+2] = fmaf(u0, w.z, vv[4*l4+2]); vv[4*l4+3] = fmaf(u0, w.w, vv[4*l4+3]);
        }
        #pragma unroll
        for (int l4 = 0; l4 < 8; l4++) {
            float4 w = vr1[l4];
            vv[4*l4]   = fmaf(u1, w.x, vv[4*l4]);   vv[4*l4+1] = fmaf(u1, w.y, vv[4*l4+1]);
            vv[4*l4+2] = fmaf(u1, w.z, vv[4*l4+2]); vv[4*l4+3] = fmaf(u1, w.w, vv[4*l4+3]);
        }
        #pragma unroll
        for (int l4 = 0; l4 < 8; l4++) {
            float4 w = vr2[l4];
            vv[4*l4]   = fmaf(u2, w.x, vv[4*l4]);   vv[4*l4+1] = fmaf(u2, w.y, vv[4*l4+1]);
            vv[4*l4+2] = fmaf(u2, w.z, vv[4*l4+2]); vv[4*l4+3] = fmaf(u2, w.w, vv[4*l4+3]);
        }
        #pragma unroll
        for (int l4 = 0; l4 < 8; l4++) {
            float4 w = vr3[l4];
            vv[4*l4]   = fmaf(u3, w.x, vv[4*l4]);   vv[4*l4+1] = fmaf(u3, w.y, vv[4*l4+1]);
            vv[4*l4+2] = fmaf(u3, w.z, vv[4*l4+2]); vv[4*l4+3] = fmaf(u3, w.w, vv[4*l4+3]);
        }
    }
    float4* vo = (float4*)(g_v + r * LAT);
    #pragma unroll
    for (int l4 = 0; l4 < 8; l4++) {
        float4 t;
        t.x = __fadd_rn(vv[4*l4],   vpbs[4*l4]);
        t.y = __fadd_rn(vv[4*l4+1], vpbs[4*l4+1]);
        t.z = __fadd_rn(vv[4*l4+2], vpbs[4*l4+2]);
        t.w = __fadd_rn(vv[4*l4+3], vpbs[4*l4+3]);
        vo[l4] = t;
    }
}

// ---------------- kernel Va: softmax/K + c_bar/v_local (bit-exact, unchanged) ----------------
__global__ void __launch_bounds__(256) kVa(
    const float* __restrict__ cc, float* __restrict__ out, int full)
{
    __shared__ float ccs[NC * LAT];
    __shared__ float cct[LAT * NC];

    int tid = threadIdx.x;
    for (int i = tid; i < NC * LAT; i += 256) {
        float t = cc[i]; ccs[i] = t;
        int c = i / LAT, l = i % LAT;
        cct[l * NC + c] = t;
    }

    size_t r = (size_t)blockIdx.x * 256 + tid;
    float v[LAT];
    {
        const float4* vp4 = (const float4*)(g_v + r * LAT);
        #pragma unroll
        for (int i = 0; i < 8; i++) {
            float4 t = vp4[i];
            v[4*i] = t.x; v[4*i+1] = t.y; v[4*i+2] = t.z; v[4*i+3] = t.w;
        }
    }
    __syncthreads();

    float enc[NC]; int K;
    {
        float sc[NC];
        #pragma unroll
        for (int c = 0; c < NC; c++) sc[c] = 0.f;
        #pragma unroll
        for (int l = 0; l < LAT; l++) {
            float vl = v[l];
            float4 wa = ((const float4*)(cct + l * NC))[0];
            float4 wb = ((const float4*)(cct + l * NC))[1];
            sc[0] = fmaf(vl, wa.x, sc[0]); sc[1] = fmaf(vl, wa.y, sc[1]);
            sc[2] = fmaf(vl, wa.z, sc[2]); sc[3] = fmaf(vl, wa.w, sc[3]);
            sc[4] = fmaf(vl, wb.x, sc[4]); sc[5] = fmaf(vl, wb.y, sc[5]);
            sc[6] = fmaf(vl, wb.z, sc[6]); sc[7] = fmaf(vl, wb.w, sc[7]);
        }
        #pragma unroll
        for (int c = 0; c < NC; c++) sc[c] = __fdiv_rn(sc[c], 5.656854249492381f);
        float m = sc[0];
        #pragma unroll
        for (int c = 1; c < NC; c++) m = fmaxf(m, sc[c]);
        float e[NC];
        #pragma unroll
        for (int c = 0; c < NC; c++)
            e[c] = (float)exp((double)__fsub_rn(sc[c], m));  // correctly-rounded fp32 exp
        float s01 = __fadd_rn(e[0], e[1]);
        float s23 = __fadd_rn(e[2], e[3]);
        float s45 = __fadd_rn(e[4], e[5]);
        float s67 = __fadd_rn(e[6], e[7]);
        float s = __fadd_rn(__fadd_rn(s01, s23), __fadd_rn(s45, s67));
        #pragma unroll
        for (int c = 0; c < NC; c++) enc[c] = __fdiv_rn(e[c], s);
        float bm = e[0]; K = 0;
        #pragma unroll
        for (int c = 1; c < NC; c++) if (e[c] > bm) { bm = e[c]; K = c; }
    }

    float cb[LAT];
    #pragma unroll
    for (int l = 0; l < LAT; l++) cb[l] = 0.f;
    #pragma unroll
    for (int c = 0; c < NC; c++) {
        float e = enc[c];
        #pragma unroll
        for (int l = 0; l < LAT; l++) cb[l] = fmaf(e, ccs[c * LAT + l], cb[l]);
    }
    #pragma unroll
    for (int l = 0; l < LAT; l++) v[l] = __fsub_rn(v[l], cb[l]);   // v_local

    float4* vo = (float4*)(g_v + r * LAT);
    float4* co = (float4*)(g_cb + r * LAT);
    #pragma unroll
    for (int l4 = 0; l4 < 8; l4++) {
        float4 tv, tc;
        tv.x = v[4*l4];  tv.y = v[4*l4+1];  tv.z = v[4*l4+2];  tv.w = v[4*l4+3];
        tc.x = cb[4*l4]; tc.y = cb[4*l4+1]; tc.z = cb[4*l4+2]; tc.w = cb[4*l4+3];
        vo[l4] = tv; co[l4] = tc;
    }
    #pragma unroll
    for (int c = 0; c < NC; c++) g_enc[r * NC + c] = enc[c];
    if (full) {
        #pragma unroll
        for (int c = 0; c < NC; c++) out[O_ENC + r * NC + c] = enc[c];
        out[O_K + r] = (float)K;
        #pragma unroll
        for (int l = 0; l < LAT; l++) out[O_CBAR + r * LAT + l] = cb[l];
    }
}

// ---------------- kernel Vb: VQ argmin, chart-split (bit-exact, unchanged) ----------------
__global__ void __launch_bounds__(256, 2) kVb(
    const float* __restrict__ cbk)
{
    extern __shared__ float sm[];
    float* cbs  = sm;               // KC*LAT
    float* cbns = cbs + KC * LAT;   // KC

    int tid = threadIdx.x;
    int c   = blockIdx.x & 7;
    int rg  = blockIdx.x >> 3;
    size_t r0 = (size_t)rg * 512 + tid;
    size_t r1 = r0 + 256;

    {
        const float* src = cbk + (size_t)c * KC * LAT;
        for (int i = tid; i < KC * LAT; i += 256) cbs[i] = src[i];
        for (int i = tid; i < KC; i += 256) cbns[i] = g_cbn[c * KC + i];
    }

    float v0[LAT], v1[LAT];
    {
        const float4* p0 = (const float4*)(g_v + r0 * LAT);
        const float4* p1 = (const float4*)(g_v + r1 * LAT);
        #pragma unroll
        for (int i = 0; i < 8; i++) {
            float4 t = p0[i];
            v0[4*i] = t.x; v0[4*i+1] = t.y; v0[4*i+2] = t.z; v0[4*i+3] = t.w;
            float4 u = p1[i];
            v1[4*i] = u.x; v1[4*i+1] = u.y; v1[4*i+2] = u.z; v1[4*i+3] = u.w;
        }
    }

    float vn0 = 0.f, vn1 = 0.f;
    #pragma unroll
    for (int l = 0; l < LAT; l++) vn0 = __fadd_rn(vn0, __fmul_rn(v0[l], v0[l]));
    #pragma unroll
    for (int l = 0; l < LAT; l++) vn1 = __fadd_rn(vn1, __fmul_rn(v1[l], v1[l]));

    __syncthreads();

    float bestA = 3.4e38f, bestB = 3.4e38f; int biA = 0, biB = 0;
    for (int k = 0; k < KC; k += 4) {
        float a0 = 0.f, a1 = 0.f, a2 = 0.f, a3 = 0.f;
        float b0 = 0.f, b1 = 0.f, b2 = 0.f, b3 = 0.f;
        const float* rp0 = cbs + (k+0) * LAT;
        const float* rp1 = cbs + (k+1) * LAT;
        const float* rp2 = cbs + (k+2) * LAT;
        const float* rp3 = cbs + (k+3) * LAT;
        #pragma unroll
        for (int i = 0; i < 8; i++) {
            float4 w0 = ((const float4*)rp0)[i];
            float4 w1 = ((const float4*)rp1)[i];
            float4 w2 = ((const float4*)rp2)[i];
            float4 w3 = ((const float4*)rp3)[i];
            a0 = fmaf(v0[4*i], w0.x, a0); a0 = fmaf(v0[4*i+1], w0.y, a0);
            a0 = fmaf(v0[4*i+2], w0.z, a0); a0 = fmaf(v0[4*i+3], w0.w, a0);
            a1 = fmaf(v0[4*i], w1.x, a1); a1 = fmaf(v0[4*i+1], w1.y, a1);
            a1 = fmaf(v0[4*i+2], w1.z, a1); a1 = fmaf(v0[4*i+3], w1.w, a1);
            a2 = fmaf(v0[4*i], w2.x, a2); a2 = fmaf(v0[4*i+1], w2.y, a2);
            a2 = fmaf(v0[4*i+2], w2.z, a2); a2 = fmaf(v0[4*i+3], w2.w, a2);
            a3 = fmaf(v0[4*i], w3.x, a3); a3 = fmaf(v0[4*i+1], w3.y, a3);
            a3 = fmaf(v0[4*i+2], w3.z, a3); a3 = fmaf(v0[4*i+3], w3.w, a3);
            b0 = fmaf(v1[4*i], w0.x, b0); b0 = fmaf(v1[4*i+1], w0.y, b0);
            b0 = fmaf(v1[4*i+2], w0.z, b0); b0 = fmaf(v1[4*i+3], w0.w, b0);
            b1 = fmaf(v1[4*i], w1.x, b1); b1 = fmaf(v1[4*i+1], w1.y, b1);
            b1 = fmaf(v1[4*i+2], w1.z, b1); b1 = fmaf(v1[4*i+3], w1.w, b1);
            b2 = fmaf(v1[4*i], w2.x, b2); b2 = fmaf(v1[4*i+1], w2.y, b2);
            b2 = fmaf(v1[4*i+2], w2.z, b2); b2 = fmaf(v1[4*i+3], w2.w, b2);
            b3 = fmaf(v1[4*i], w3.x, b3); b3 = fmaf(v1[4*i+1], w3.y, b3);
            b3 = fmaf(v1[4*i+2], w3.z, b3); b3 = fmaf(v1[4*i+3], w3.w, b3);
        }
        float n0 = cbns[k+0], n1 = cbns[k+1], n2 = cbns[k+2], n3 = cbns[k+3];
        float dA0 = __fadd_rn(__fsub_rn(vn0, __fmul_rn(2.0f, a0)), n0);
        float dA1 = __fadd_rn(__fsub_rn(vn0, __fmul_rn(2.0f, a1)), n1);
        float dA2 = __fadd_rn(__fsub_rn(vn0, __fmul_rn(2.0f, a2)), n2);
        float dA3 = __fadd_rn(__fsub_rn(vn0, __fmul_rn(2.0f, a3)), n3);
        if (dA0 < bestA) { bestA = dA0; biA = k+0; }
        if (dA1 < bestA) { bestA = dA1; biA = k+1; }
        if (dA2 < bestA) { bestA = dA2; biA = k+2; }
        if (dA3 < bestA) { bestA = dA3; biA = k+3; }
        float dB0 = __fadd_rn(__fsub_rn(vn1, __fmul_rn(2.0f, b0)), n0);
        float dB1 = __fadd_rn(__fsub_rn(vn1, __fmul_rn(2.0f, b1)), n1);
        float dB2 = __fadd_rn(__fsub_rn(vn1, __fmul_rn(2.0f, b2)), n2);
        float dB3 = __fadd_rn(__fsub_rn(vn1, __fmul_rn(2.0f, b3)), n3);
        if (dB0 < bestB) { bestB = dB0; biB = k+0; }
        if (dB1 < bestB) { bestB = dB1; biB = k+1; }
        if (dB2 < bestB) { bestB = dB2; biB = k+2; }
        if (dB3 < bestB) { bestB = dB3; biB = k+3; }
    }
    g_bidx[r0 * NC + c] = biA;
    g_bidx[r1 * NC + c] = biB;
}

// ---------------- kernel W: warp-per-row; SF layer1 half-split + dec quarter-split ----------------
// The split changes ONLY the summation tree of a (SF layer1) and lg (dec logits),
// which feed tolerance-1e-3 outputs (z_n/z_geo/dec/h_global/x_hat) currently at
// ~1e-7. Bit-fragile outputs (enc/K, VQ indices) live in kVa/kVb, untouched.
#define KWTH 1024
#define KWROWS (KWTH / 32)
__global__ void __launch_bounds__(KWTH, 1) kW(
    const float* __restrict__ cbk,
    const float* __restrict__ sfw1, const float* __restrict__ sfb1,
    const float* __restrict__ sfw2, const float* __restrict__ sfb2,
    const float* __restrict__ decw, const float* __restrict__ decb,
    const float* __restrict__ lrw,  const float* __restrict__ lrb,
    float* __restrict__ out, int full)
{
    extern __shared__ float sm[];
    float* decwt = sm;                       // 32768: [(c*32+l)*128 + h]
    float* decbs = decwt + NC * HID * LAT;   // 1024
    float* sfw1n = decbs + NC * HID;         // 512 [l*16+m]
    float* sfw2s = sfw1n + LAT * MID;        // 512 [m*32+l]
    float* lrws  = sfw2s + MID * LAT;        // 256 [l*8+c]
    float* sfb1s = lrws + LAT * NC;          // 16
    float* sfb2s = sfb1s + MID;              // 32
    float* lrbs  = sfb2s + LAT;              // 8
    float* redv  = lrbs + NC;                // 32
    float* zg_s  = redv + 32;                // 32 rows * 33 = 1056
    float* dec_s = zg_s + KWROWS * 33;       // 32 rows * 8 = 256

    int tid = threadIdx.x;
    for (int i = tid; i < NC * HID * LAT; i += KWTH) {
        int c = i >> 12; int rem = i & 4095; int h = rem >> 5; int l = rem & 31;
        decwt[(c * 32 + l) * 128 + h] = decw[i];
    }
    for (int i = tid; i < NC * HID; i += KWTH) decbs[i] = decb[i];
    for (int i = tid; i < LAT * MID; i += KWTH) sfw1n[i] = sfw1[i];
    for (int i = tid; i < MID * LAT; i += KWTH) sfw2s[i] = sfw2[i];
    for (int i = tid; i < LAT * NC; i += KWTH) lrws[i] = lrw[i];
    if (tid < MID) sfb1s[tid] = sfb1[tid];
    if (tid < LAT) sfb2s[tid] = sfb2[tid];
    if (tid < NC)  lrbs[tid] = lrb[tid];
    __syncthreads();

    int warp = tid >> 5, lane = tid & 31;
    size_t r = (size_t)blockIdx.x * KWROWS + warp;

    float vl  = g_v[r * LAT + lane];
    float cbl = g_cb[r * LAT + lane];
    float enc[NC];
    #pragma unroll
    for (int c = 0; c < NC; c++) enc[c] = g_enc[r * NC + c];

    int lbase = (lane >> 4) * 16;    // SF layer1 half-split base
    int lq    = (lane >> 3) * 8;     // dec quarter-split base

    float zqb = 0.f, zn = 0.f, vqa = 0.f;
    #pragma unroll 1
    for (int c = 0; c < NC; c++) {
        int bi = g_bidx[r * NC + c];
        float zq = cbk[((size_t)c * KC + bi) * LAT + lane];
        float e = enc[c];
        zqb = fmaf(e, zq, zqb);
        float d = __fsub_rn(vl, zq);
        float t = __fmul_rn(d, d);
        t += __shfl_xor_sync(0xFFFFFFFFu, t, 16);
        t += __shfl_xor_sync(0xFFFFFFFFu, t, 8);
        t += __shfl_xor_sync(0xFFFFFFFFu, t, 4);
        t += __shfl_xor_sync(0xFFFFFFFFu, t, 2);
        t += __shfl_xor_sync(0xFFFFFFFFu, t, 1);
        vqa = fmaf(e, t, vqa);
        // SF layer1, half-l split: lanes 0-15 sum l<16, lanes 16-31 sum l>=16,
        // then one xor-16 add combines. (tree-sum; tolerance-safe)
        float a = 0.f;
        #pragma unroll
        for (int l = 0; l < 16; l++) {
            float db = __shfl_sync(0xFFFFFFFFu, d, lbase + l);
            a = fmaf(db, sfw1n[(lbase + l) * MID + (lane & 15)], a);
        }
        a = __fadd_rn(a, __shfl_xor_sync(0xFFFFFFFFu, a, 16));
        float mvv = gelu_ref(__fadd_rn(a, sfb1s[lane & 15]));
        // SF layer2: lane l accumulates seq-m chain (no redundancy; unchanged)
        float acc = 0.f;
        #pragma unroll
        for (int m = 0; m < MID; m++) {
            float mb = __shfl_sync(0xFFFFFFFFu, mvv, m);
            acc = fmaf(mb, sfw2s[m * LAT + lane], acc);
        }
        zn = fmaf(e, __fadd_rn(acc, sfb2s[lane]), zn);
    }

    float zgeo = __fadd_rn(__fadd_rn(cbl, zqb), zn);
    float zg = tanhf(zgeo);
    float ztv = tanhf(__fsub_rn(__fsub_rn(vl, zqb), zn));
    g_zt[r * LAT + lane] = ztv;
    if (full) {
        out[O_ZGEO + r * LAT + lane] = zgeo;
        out[O_ZN   + r * LAT + lane] = zn;
    }

    // dec logits, quarter-l split: lane sums its 8-l range for c = lane&7,
    // then two xor adds combine quarters. (tree-sum; tolerance-safe)
    float lg = 0.f;
    #pragma unroll
    for (int l = 0; l < 8; l++) {
        float zb = __shfl_sync(0xFFFFFFFFu, zg, lq + l);
        lg = fmaf(zb, lrws[(lq + l) * NC + (lane & 7)], lg);
    }
    lg = __fadd_rn(lg, __shfl_xor_sync(0xFFFFFFFFu, lg, 8));
    lg = __fadd_rn(lg, __shfl_xor_sync(0xFFFFFFFFu, lg, 16));
    lg = __fadd_rn(lg, lrbs[lane & 7]);
    float dec[NC];
    {
        float lgv[NC];
        #pragma unroll
        for (int c = 0; c < NC; c++) lgv[c] = __shfl_sync(0xFFFFFFFFu, lg, c);
        float m = lgv[0];
        #pragma unroll
        for (int c = 1; c < NC; c++) m = fmaxf(m, lgv[c]);
        float s = 0.f;
        #pragma unroll
        for (int c = 0; c < NC; c++) { dec[c] = expf(__fsub_rn(lgv[c], m)); s = __fadd_rn(s, dec[c]); }
        #pragma unroll
        for (int c = 0; c < NC; c++) dec[c] = __fdiv_rn(dec[c], s);
    }
    if (full && lane < NC) out[O_DEC + r * NC + lane] = dec[lane];

    zg_s[warp * 33 + lane] = zg;
    if (lane == 0) {
        #pragma unroll
        for (int c = 0; c < NC; c++) dec_s[warp * NC + c] = dec[c];
    }
    if (lane == 0) redv[warp] = vqa;
    __syncthreads();

    {
        int g  = warp >> 2;
        int hb = (warp & 3) * 32;
        int h  = hb + lane;
        int row0 = g * 4;
        float a[4][NC];
        #pragma unroll
        for (int q = 0; q < 4; q++)
            #pragma unroll
            for (int c = 0; c < NC; c++) a[q][c] = 0.f;

        #pragma unroll 4
        for (int l = 0; l < 32; l++) {
            float z0 = zg_s[(row0+0) * 33 + l];
            float z1 = zg_s[(row0+1) * 33 + l];
            float z2 = zg_s[(row0+2) * 33 + l];
            float z3 = zg_s[(row0+3) * 33 + l];
            #pragma unroll
            for (int c = 0; c < NC; c++) {
                float wl = decwt[(c * 32 + l) * 128 + h];
                a[0][c] = fmaf(z0, wl, a[0][c]);
                a[1][c] = fmaf(z1, wl, a[1][c]);
                a[2][c] = fmaf(z2, wl, a[2][c]);
                a[3][c] = fmaf(z3, wl, a[3][c]);
            }
        }
        size_t rb = (size_t)blockIdx.x * KWROWS + row0;
        #pragma unroll
        for (int q = 0; q < 4; q++) {
            float acc = 0.f;
            #pragma unroll
            for (int c = 0; c < NC; c++) {
                float db = decbs[c * HID + h];
                float dc = dec_s[(row0+q) * NC + c];
                acc = __fadd_rn(acc, __fmul_rn(dc, __fadd_rn(a[q][c], db)));
            }
            g_hg[(rb + q) * HID + h] = acc;
        }
    }

    if (tid == 0) {
        float ssum = 0.f;
        #pragma unroll
        for (int w = 0; w < KWROWS; w++) ssum += redv[w];
        atomicAdd(&g_vq, (double)ssum);
    }
}

// ---------------- kernel C: h_global -> x_hat (unchanged) ----------------
__global__ void __launch_bounds__(256) kC(
    const float* __restrict__ rw1, const float* __restrict__ rb1,
    const float* __restrict__ rw2, const float* __restrict__ rb2,
    const float* __restrict__ skw, const float* __restrict__ skb,
    const float* __restrict__ txw, const float* __restrict__ txb,
    const float* __restrict__ tscale, float* __restrict__ out)
{
    extern __shared__ float sm[];
    float* rw1n = sm;
    float* rw2s = rw1n + HID * HID;
    float* skws = rw2s + HID * DIN;
    float* txws = skws + HID * DIN;
    float* rb1s = txws + LAT * DIN;
    float* rb2s = rb1s + HID;
    float* skbs = rb2s + DIN;
    float* txbs = skbs + DIN;

    int tid = threadIdx.x;
    for (int i = tid; i < HID * HID; i += 256) rw1n[i] = rw1[i];
    for (int i = tid; i < HID * DIN; i += 256) { rw2s[i] = rw2[i]; skws[i] = skw[i]; }
    for (int i = tid; i < LAT * DIN; i += 256) txws[i] = txw[i];
    if (tid < HID) rb1s[tid] = rb1[tid];
    if (tid < DIN) { rb2s[tid] = rb2[tid]; skbs[tid] = skb[tid]; txbs[tid] = txb[tid]; }
    __syncthreads();

    size_t r = (size_t)blockIdx.x * 256 + tid;
    float ts = tscale[0];

    const float* hgp = g_hg + r * HID;

    float hg[HID], g[HID];
    {
        const float4* h4 = (const float4*)hgp;
        #pragma unroll
        for (int i = 0; i < 32; i++) {
            float4 t = h4[i];
            hg[4*i] = t.x; hg[4*i+1] = t.y; hg[4*i+2] = t.z; hg[4*i+3] = t.w;
            g[4*i]   = gelu_ref(t.x); g[4*i+1] = gelu_ref(t.y);
            g[4*i+2] = gelu_ref(t.z); g[4*i+3] = gelu_ref(t.w);
        }
    }

    float o[DIN], sk[DIN];
    #pragma unroll
    for (int l = 0; l < DIN; l++) { o[l] = 0.f; sk[l] = 0.f; }

    for (int j = 0; j < HID; j += 4) {
        float a0 = 0.f, a1 = 0.f, a2 = 0.f, a3 = 0.f;
        #pragma unroll
        for (int i = 0; i < HID; i++) {
            float gi = g[i];
            float4 w = *(const float4*)(rw1n + i * HID + j);
            a0 = fmaf(gi, w.x, a0); a1 = fmaf(gi, w.y, a1);
            a2 = fmaf(gi, w.z, a2); a3 = fmaf(gi, w.w, a3);
        }
        float u0 = gelu_ref(__fadd_rn(a0, rb1s[j+0]));
        float u1 = gelu_ref(__fadd_rn(a1, rb1s[j+1]));
        float u2 = gelu_ref(__fadd_rn(a2, rb1s[j+2]));
        float u3 = gelu_ref(__fadd_rn(a3, rb1s[j+3]));
        const float4* r0 = (const float4*)(rw2s + (j+0) * DIN);
        const float4* r1 = (const float4*)(rw2s + (j+1) * DIN);
        const float4* r2 = (const float4*)(rw2s + (j+2) * DIN);
        const float4* r3 = (const float4*)(rw2s + (j+3) * DIN);
        #pragma unroll
        for (int l4 = 0; l4 < 8; l4++) {
            float4 w = r0[l4];
            o[4*l4]   = fmaf(u0, w.x, o[4*l4]);   o[4*l4+1] = fmaf(u0, w.y, o[4*l4+1]);
            o[4*l4+2] = fmaf(u0, w.z, o[4*l4+2]); o[4*l4+3] = fmaf(u0, w.w, o[4*l4+3]);
        }
        #pragma unroll
        for (int l4 = 0; l4 < 8; l4++) {
            float4 w = r1[l4];
            o[4*l4]   = fmaf(u1, w.x, o[4*l4]);   o[4*l4+1] = fmaf(u1, w.y, o[4*l4+1]);
            o[4*l4+2] = fmaf(u1, w.z, o[4*l4+2]); o[4*l4+3] = fmaf(u1, w.w, o[4*l4+3]);
        }
        #pragma unroll
        for (int l4 = 0; l4 < 8; l4++) {
            float4 w = r2[l4];
            o[4*l4]   = fmaf(u2, w.x, o[4*l4]);   o[4*l4+1] = fmaf(u2, w.y, o[4*l4+1]);
            o[4*l4+2] = fmaf(u2, w.z, o[4*l4+2]); o[4*l4+3] = fmaf(u2, w.w, o[4*l4+3]);
        }
        #pragma unroll
        for (int l4 = 0; l4 < 8; l4++) {
            float4 w = r3[l4];
            o[4*l4]   = fmaf(u3, w.x, o[4*l4]);   o[4*l4+1] = fmaf(u3, w.y, o[4*l4+1]);
            o[4*l4+2] = fmaf(u3, w.z, o[4*l4+2]); o[4*l4+3] = fmaf(u3, w.w, o[4*l4+3]);
        }
        const float4* s0 = (const float4*)(skws + (j+0) * DIN);
        const float4* s1 = (const float4*)(skws + (j+1) * DIN);
        const float4* s2 = (const float4*)(skws + (j+2) * DIN);
        const float4* s3 = (const float4*)(skws + (j+3) * DIN);
        float h0 = hg[j+0], h1v = hg[j+1], h2v = hg[j+2], h3v = hg[j+3];
        #pragma unroll
        for (int l4 = 0; l4 < 8; l4++) {
            float4 w = s0[l4];
            sk[4*l4]   = fmaf(h0, w.x, sk[4*l4]);   sk[4*l4+1] = fmaf(h0, w.y, sk[4*l4+1]);
            sk[4*l4+2] = fmaf(h0, w.z, sk[4*l4+2]); sk[4*l4+3] = fmaf(h0, w.w, sk[4*l4+3]);
        }
        #pragma unroll
        for (int l4 = 0; l4 < 8; l4++) {
            float4 w = s1[l4];
            sk[4*l4]   = fmaf(h1v, w.x, sk[4*l4]);   sk[4*l4+1] = fmaf(h1v, w.y, sk[4*l4+1]);
            sk[4*l4+2] = fmaf(h1v, w.z, sk[4*l4+2]); sk[4*l4+3] = fmaf(h1v, w.w, sk[4*l4+3]);
        }
        #pragma unroll
        for (int l4 = 0; l4 < 8; l4++) {
            float4 w = s2[l4];
            sk[4*l4]   = fmaf(h2v, w.x, sk[4*l4]);   sk[4*l4+1] = fmaf(h2v, w.y, sk[4*l4+1]);
            sk[4*l4+2] = fmaf(h2v, w.z, sk[4*l4+2]); sk[4*l4+3] = fmaf(h2v, w.w, sk[4*l4+3]);
        }
        #pragma unroll
        for (int l4 = 0; l4 < 8; l4++) {
            float4 w = s3[l4];
            sk[4*l4]   = fmaf(h3v, w.x, sk[4*l4]);   sk[4*l4+1] = fmaf(h3v, w.y, sk[4*l4+1]);
            sk[4*l4+2] = fmaf(h3v, w.z, sk[4*l4+2]); sk[4*l4+3] = fmaf(h3v, w.w, sk[4*l4+3]);
        }
    }

    float zt[LAT];
    {
        const float4* z4 = (const float4*)(g_zt + r * LAT);
        #pragma unroll
        for (int i = 0; i < 8; i++) {
            float4 t = z4[i];
            zt[4*i] = t.x; zt[4*i+1] = t.y; zt[4*i+2] = t.z; zt[4*i+3] = t.w;
        }
    }
    float tx[DIN];
    #pragma unroll
    for (int l = 0; l < DIN; l++) tx[l] = 0.f;
    #pragma unroll
    for (int lp = 0; lp < LAT; lp++) {
        float ztl = zt[lp];
        const float4* t4 = (const float4*)(txws + lp * DIN);
        #pragma unroll
        for (int l4 = 0; l4 < 8; l4++) {
            float4 w = t4[l4];
            tx[4*l4]   = fmaf(ztl, w.x, tx[4*l4]);   tx[4*l4+1] = fmaf(ztl, w.y, tx[4*l4+1]);
            tx[4*l4+2] = fmaf(ztl, w.z, tx[4*l4+2]); tx[4*l4+3] = fmaf(ztl, w.w, tx[4*l4+3]);
        }
    }

    float4* xo = (float4*)(out + O_XHAT + r * DIN);
    #pragma unroll
    for (int l4 = 0; l4 < 8; l4++) {
        float4 t;
        #pragma unroll
        for (int q = 0; q < 4; q++) {
            int l = 4*l4 + q;
            float mlp  = __fadd_rn(o[l], rb2s[l]);
            float skp  = __fadd_rn(sk[l], skbs[l]);
            float base = __fadd_rn(mlp, skp);
            float texv = __fmul_rn(ts, __fadd_rn(tx[l], txbs[l]));
            ((float*)&t)[q] = __fadd_rn(base, texv);
        }
        xo[l4] = t;
    }
}

// ---------------- kernel D ----------------
__global__ void kD(float* __restrict__ out, int full) {
    if (full) out[O_VQ] = (float)(1.25 * g_vq / ((double)Bsz * (double)LAT));
}

// ---------------- launch ----------------
extern "C" void kernel_launch(void* const* d_in, const int* in_sizes, int n_in,
                              void* d_out, int out_size) {
    const float* x    = (const float*)d_in[0];
    const float* fw1  = (const float*)d_in[1];
    const float* fb1  = (const float*)d_in[2];
    const float* fw2  = (const float*)d_in[3];
    const float* fb2  = (const float*)d_in[4];
    const float* vpw  = (const float*)d_in[5];
    const float* vpb  = (const float*)d_in[6];
    const float* cc   = (const float*)d_in[7];
    const float* cbk  = (const float*)d_in[8];
    const float* sfw1 = (const float*)d_in[9];
    const float* sfb1 = (const float*)d_in[10];
    const float* sfw2 = (const float*)d_in[11];
    const float* sfb2 = (const float*)d_in[12];
    const float* decw = (const float*)d_in[13];
    const float* decb = (const float*)d_in[14];
    const float* lrw  = (const float*)d_in[15];
    const float* lrb  = (const float*)d_in[16];
    const float* txw  = (const float*)d_in[17];
    const float* txb  = (const float*)d_in[18];
    const float* tsc  = (const float*)d_in[19];
    const float* rw1  = (const float*)d_in[20];
    const float* rb1  = (const float*)d_in[21];
    const float* rw2  = (const float*)d_in[22];
    const float* rb2  = (const float*)d_in[23];
    const float* skw  = (const float*)d_in[24];
    const float* skb  = (const float*)d_in[25];

    float* out = (float*)d_out;
    int full = (out_size >= O_TOTAL) ? 1 : 0;

    const int SMEM_A  = (DIN*HID + HID*HID + HID*LAT + HID + HID + LAT + HID*256) * 4;
    const int SMEM_VB = (KC*LAT + KC) * 4;
    const int SMEM_W  = (NC*HID*LAT + NC*HID + LAT*MID + MID*LAT + LAT*NC + MID + LAT + NC
                         + 32 + KWROWS*33 + KWROWS*NC) * 4;
    const int SMEM_C  = (HID*HID + HID*DIN + HID*DIN + LAT*DIN + HID + DIN + DIN + DIN) * 4;

    cudaFuncSetAttribute(kA,  cudaFuncAttributeMaxDynamicSharedMemorySize, SMEM_A);
    cudaFuncSetAttribute(kVb, cudaFuncAttributeMaxDynamicSharedMemorySize, SMEM_VB);
    cudaFuncSetAttribute(kW,  cudaFuncAttributeMaxDynamicSharedMemorySize, SMEM_W);
    cudaFuncSetAttribute(kC,  cudaFuncAttributeMaxDynamicSharedMemorySize, SMEM_C);

    kPrep<<<16, 256>>>(cbk);
    kA<<<Bsz / 256, 256, SMEM_A>>>(x, fw1, fb1, fw2, fb2, vpw, vpb);
    kVa<<<Bsz / 256, 256>>>(cc, out, full);
    kVb<<<(Bsz / 512) * NC, 256, SMEM_VB>>>(cbk);
    kW<<<Bsz / KWROWS, KWTH, SMEM_W>>>(cbk, sfw1, sfb1, sfw2, sfb2, decw, decb, lrw, lrb, out, full);
    kC<<<Bsz / 256, 256, SMEM_C>>>(rw1, rb1, rw2, rb2, skw, skb, txw, txb, tsc, out);
    kD<<<1, 1>>>(out, full);
}